// round 1
// baseline (speedup 1.0000x reference)
#include <cuda_runtime.h>
#include <cstddef>

// Problem constants (B=16, H=W=56, C=1024, K=150, WS=7)
#define M_ROWS 50176      // 16 * 56 * 56
#define CDIM   1024
#define KSEM   150
#define NWIN   1024       // 16 * 8 * 8 windows
#define BATCH_STRIDE 3136 // 56*56

// -------- scratch (device globals; no runtime allocation) --------
__device__ float g_xn[(size_t)M_ROWS * CDIM];   // LayerNorm output (the residual "win")
__device__ float g_kf[(size_t)M_ROWS * KSEM];   // seg_ft (K projection)
__device__ float g_v [(size_t)M_ROWS * CDIM];   // V projection
__device__ float g_ao[(size_t)M_ROWS * CDIM];   // attention output (score @ V)

// ============================================================
// LayerNorm: one block per row of 1024
// ============================================================
__global__ __launch_bounds__(256)
void ln_kernel(const float* __restrict__ x, const float* __restrict__ w,
               const float* __restrict__ b, float* __restrict__ out)
{
    int row = blockIdx.x;
    int t = threadIdx.x;
    const float4* xr = (const float4*)(x + (size_t)row * CDIM);
    float4 v = xr[t];
    float s  = v.x + v.y + v.z + v.w;
    float sq = v.x*v.x + v.y*v.y + v.z*v.z + v.w*v.w;
    #pragma unroll
    for (int o = 16; o > 0; o >>= 1) {
        s  += __shfl_xor_sync(0xFFFFFFFFu, s,  o);
        sq += __shfl_xor_sync(0xFFFFFFFFu, sq, o);
    }
    __shared__ float red[2][8];
    int wid = t >> 5, lid = t & 31;
    if (lid == 0) { red[0][wid] = s; red[1][wid] = sq; }
    __syncthreads();
    float st = 0.f, sqt = 0.f;
    #pragma unroll
    for (int i = 0; i < 8; i++) { st += red[0][i]; sqt += red[1][i]; }
    float mu   = st * (1.0f / CDIM);
    float var  = sqt * (1.0f / CDIM) - mu * mu;
    float rstd = rsqrtf(var + 1e-5f);
    float4 wv = ((const float4*)w)[t];
    float4 bv = ((const float4*)b)[t];
    float4 o;
    o.x = (v.x - mu) * rstd * wv.x + bv.x;
    o.y = (v.y - mu) * rstd * wv.y + bv.y;
    o.z = (v.z - mu) * rstd * wv.z + bv.z;
    o.w = (v.w - mu) * rstd * wv.w + bv.w;
    ((float4*)(out + (size_t)row * CDIM))[t] = o;
}

// ============================================================
// Tiled fp32 GEMM: C[M,N] = A[M,1024] @ W[N,1024]^T + bias
// MODE 0: plain.  MODE 1: C = gamma*(acc+bias) + resid[m*1024+n]
// BM=BN=128, BK=16, 256 threads, 8x8 microtile per thread.
// ============================================================
#define BM 128
#define BN 128
#define BK 16

template<int MODE>
__global__ __launch_bounds__(256)
void gemm_kernel(const float* __restrict__ A, const float* __restrict__ W,
                 const float* __restrict__ bias, float* __restrict__ C,
                 int N, int ldc,
                 const float* __restrict__ resid, const float* __restrict__ gammap)
{
    __shared__ float As[BK][BM + 1];
    __shared__ float Bs[BK][BN + 1];
    int t  = threadIdx.x;
    int tx = t & 15;
    int ty = t >> 4;
    int m0 = blockIdx.y * BM;
    int n0 = blockIdx.x * BN;

    float acc[8][8];
    #pragma unroll
    for (int i = 0; i < 8; i++)
        #pragma unroll
        for (int j = 0; j < 8; j++) acc[i][j] = 0.f;

    int lrow = t >> 2;   // 0..63
    int lk4  = t & 3;    // 0..3  (float4 index within 16-wide k slab)

    for (int k0 = 0; k0 < CDIM; k0 += BK) {
        #pragma unroll
        for (int h = 0; h < 2; h++) {
            int r = lrow + h * 64;
            float4 av = *(const float4*)(A + (size_t)(m0 + r) * CDIM + k0 + lk4 * 4);
            As[lk4*4+0][r] = av.x; As[lk4*4+1][r] = av.y;
            As[lk4*4+2][r] = av.z; As[lk4*4+3][r] = av.w;
            int rn = n0 + r;
            float4 bvv;
            if (rn < N) bvv = *(const float4*)(W + (size_t)rn * CDIM + k0 + lk4 * 4);
            else        bvv = make_float4(0.f, 0.f, 0.f, 0.f);
            Bs[lk4*4+0][r] = bvv.x; Bs[lk4*4+1][r] = bvv.y;
            Bs[lk4*4+2][r] = bvv.z; Bs[lk4*4+3][r] = bvv.w;
        }
        __syncthreads();
        #pragma unroll
        for (int kk = 0; kk < BK; kk++) {
            float a[8], b[8];
            #pragma unroll
            for (int i = 0; i < 8; i++) a[i] = As[kk][ty + i * 16];
            #pragma unroll
            for (int j = 0; j < 8; j++) b[j] = Bs[kk][tx + j * 16];
            #pragma unroll
            for (int i = 0; i < 8; i++)
                #pragma unroll
                for (int j = 0; j < 8; j++)
                    acc[i][j] += a[i] * b[j];
        }
        __syncthreads();
    }

    float gm = (MODE == 1) ? gammap[0] : 0.f;
    #pragma unroll
    for (int j = 0; j < 8; j++) {
        int n = n0 + tx + j * 16;
        if (n >= N) continue;
        float bj = bias[n];
        #pragma unroll
        for (int i = 0; i < 8; i++) {
            int m = m0 + ty + i * 16;
            float val = acc[i][j] + bj;
            if (MODE == 1) val = gm * val + resid[(size_t)m * CDIM + n];
            C[(size_t)m * ldc + n] = val;
        }
    }
}

// ============================================================
// Per-window attention: 1 block per window (49 tokens).
//   S = softmax(Q @ K^T), O = S @ V   (Q from sem region of d_out)
// Rows are gathered from the natural [B, H*W, *] layout.
// ============================================================
__global__ __launch_bounds__(256)
void attn_kernel(const float* __restrict__ q, const float* __restrict__ kf,
                 const float* __restrict__ v, float* __restrict__ ao)
{
    __shared__ float Ss[49][50];
    __shared__ __align__(16) float buf[2 * 49 * 76]; // phase A: Q,K chunks; phase B: V chunk (49*128)

    int wi = blockIdx.x;
    int b  = wi >> 6;
    int wh = (wi >> 3) & 7;
    int ww = wi & 7;
    int base = b * BATCH_STRIDE + wh * 7 * 56 + ww * 7;
    int t = threadIdx.x;

    // ---- Phase A: S[n][m] = sum_k Q[n,k] * K[m,k], k split in 2 chunks of 75
    float* Qs = buf;            // [49][76]
    float* Ks = buf + 49 * 76;  // [49][76]
    for (int kc = 0; kc < 2; kc++) {
        int kb = kc * 75;
        __syncthreads();
        for (int idx = t; idx < 49 * 75; idx += 256) {
            int n = idx / 75, k = idx - n * 75;
            int r = base + (n / 7) * 56 + (n % 7);
            Qs[n * 76 + k] = q [(size_t)r * KSEM + kb + k];
            Ks[n * 76 + k] = kf[(size_t)r * KSEM + kb + k];
        }
        __syncthreads();
        for (int p = t; p < 2401; p += 256) {
            int n = p / 49, m = p - n * 49;
            float d = 0.f;
            #pragma unroll 5
            for (int k = 0; k < 75; k++) d += Qs[n * 76 + k] * Ks[m * 76 + k];
            if (kc == 0) Ss[n][m] = d; else Ss[n][m] += d;
        }
    }
    __syncthreads();

    // ---- softmax over m, one thread per row
    if (t < 49) {
        float mx = -1e30f;
        #pragma unroll
        for (int m = 0; m < 49; m++) mx = fmaxf(mx, Ss[t][m]);
        float sum = 0.f;
        #pragma unroll
        for (int m = 0; m < 49; m++) { float e = __expf(Ss[t][m] - mx); Ss[t][m] = e; sum += e; }
        float inv = 1.f / sum;
        #pragma unroll
        for (int m = 0; m < 49; m++) Ss[t][m] *= inv;
    }

    // ---- Phase B: O = S @ V, 8 column chunks of 128
    float* Vs = buf;              // [49][128]
    int g  = t >> 5;              // warp id 0..7 -> n-group (overlapping by design; dup writes identical)
    int cq = t & 31;              // float4 column index
    int nstart = g * 6;           // groups cover rows 0..48 (some rows duplicated -> same value)
    for (int cc = 0; cc < 8; cc++) {
        __syncthreads();
        int cbase = cc * 128;
        for (int idx = t; idx < 49 * 32; idx += 256) {
            int m = idx >> 5, qd = idx & 31;
            int r = base + (m / 7) * 56 + (m % 7);
            ((float4*)Vs)[m * 32 + qd] = *(const float4*)(v + (size_t)r * CDIM + cbase + qd * 4);
        }
        __syncthreads();
        float4 acc[7];
        #pragma unroll
        for (int i = 0; i < 7; i++) acc[i] = make_float4(0.f, 0.f, 0.f, 0.f);
        for (int m = 0; m < 49; m++) {
            float4 vv = ((float4*)Vs)[m * 32 + cq];
            #pragma unroll
            for (int i = 0; i < 7; i++) {
                float s = Ss[nstart + i][m];
                acc[i].x += s * vv.x; acc[i].y += s * vv.y;
                acc[i].z += s * vv.z; acc[i].w += s * vv.w;
            }
        }
        #pragma unroll
        for (int i = 0; i < 7; i++) {
            int n = nstart + i;
            int r = base + (n / 7) * 56 + (n % 7);
            *(float4*)(ao + (size_t)r * CDIM + cbase + cq * 4) = acc[i];
        }
    }
}

// ============================================================
// Host launcher
// ============================================================
extern "C" void kernel_launch(void* const* d_in, const int* in_sizes, int n_in,
                              void* d_out, int out_size)
{
    const float* x      = (const float*)d_in[0];
    const float* norm_w = (const float*)d_in[1];
    const float* norm_b = (const float*)d_in[2];
    const float* wq     = (const float*)d_in[3];
    const float* bq     = (const float*)d_in[4];
    const float* wk     = (const float*)d_in[5];
    const float* bk     = (const float*)d_in[6];
    const float* wv     = (const float*)d_in[7];
    const float* bv     = (const float*)d_in[8];
    const float* wr     = (const float*)d_in[9];
    const float* br     = (const float*)d_in[10];
    const float* gamma  = (const float*)d_in[11];
    (void)in_sizes; (void)n_in; (void)out_size;

    float* out  = (float*)d_out;
    float* sem  = out;                              // [50176, 150]
    float* xout = out + (size_t)M_ROWS * KSEM;      // [50176, 1024]

    float *xn, *kf, *vv, *ao;
    cudaGetSymbolAddress((void**)&xn, g_xn);
    cudaGetSymbolAddress((void**)&kf, g_kf);
    cudaGetSymbolAddress((void**)&vv, g_v);
    cudaGetSymbolAddress((void**)&ao, g_ao);

    // 1) LayerNorm
    ln_kernel<<<M_ROWS, 256>>>(x, norm_w, norm_b, xn);

    // 2) Q projection -> sem output directly; K projection -> scratch
    dim3 gqk((KSEM + BN - 1) / BN, M_ROWS / BM);
    gemm_kernel<0><<<gqk, 256>>>(xn, wq, bq, sem, KSEM, KSEM, nullptr, nullptr);
    gemm_kernel<0><<<gqk, 256>>>(xn, wk, bk, kf,  KSEM, KSEM, nullptr, nullptr);

    // 3) V projection
    dim3 gv(CDIM / BN, M_ROWS / BM);
    gemm_kernel<0><<<gv, 256>>>(xn, wv, bv, vv, CDIM, CDIM, nullptr, nullptr);

    // 4) per-window attention
    attn_kernel<<<NWIN, 256>>>(sem, kf, vv, ao);

    // 5) output projection + gamma residual (residual = xn)
    gemm_kernel<1><<<gv, 256>>>(ao, wr, br, xout, CDIM, CDIM, xn, gamma);
}

// round 3
// speedup vs baseline: 3.2213x; 3.2213x over previous
#include <cuda_runtime.h>
#include <cstdint>
#include <cstddef>

// Problem constants (B=16, H=W=56, C=1024, K=150, WS=7)
#define M_ROWS 50176      // 16 * 56 * 56
#define CDIM   1024
#define KSEM   150
#define NWIN   1024       // 16 * 8 * 8 windows
#define BATCH_STRIDE 3136 // 56*56

// -------- scratch (device globals; no runtime allocation) --------
__device__ float g_xn [(size_t)M_ROWS * CDIM];   // LN output, fp32 (residual)
__device__ float g_xnt[(size_t)M_ROWS * CDIM];   // LN output, tf32-rounded (GEMM A)
__device__ float g_kf [(size_t)M_ROWS * KSEM];   // seg_ft
__device__ float g_v  [(size_t)M_ROWS * CDIM];   // V projection
__device__ float g_ao [(size_t)M_ROWS * CDIM];   // attention output (tf32-rounded)
__device__ float g_wqt[(size_t)KSEM * CDIM];
__device__ float g_wkt[(size_t)KSEM * CDIM];
__device__ float g_wvt[(size_t)CDIM * CDIM];
__device__ float g_wrt[(size_t)CDIM * CDIM];

__device__ __forceinline__ uint32_t smem_to_u32(const void* p) {
    uint32_t a;
    asm("{ .reg .u64 t; cvta.to.shared.u64 t, %1; cvt.u32.u64 %0, t; }" : "=r"(a) : "l"(p));
    return a;
}
__device__ __forceinline__ float round_tf32(float x) {
    uint32_t r;
    asm("cvt.rna.tf32.f32 %0, %1;" : "=r"(r) : "f"(x));
    return __uint_as_float(r);
}
#define CP_ASYNC16(dst, src) \
    asm volatile("cp.async.cg.shared.global [%0], [%1], 16;" :: "r"(dst), "l"(src) : "memory")
#define CP_COMMIT() asm volatile("cp.async.commit_group;" ::: "memory")
#define LDMATRIX_X4(r0, r1, r2, r3, addr) \
    asm volatile("ldmatrix.sync.aligned.m8n8.x4.shared.b16 {%0,%1,%2,%3}, [%4];" \
        : "=r"(r0), "=r"(r1), "=r"(r2), "=r"(r3) : "r"(addr))

// ============================================================
// tf32 rounding pre-pass for weights
// ============================================================
__global__ __launch_bounds__(256)
void round_kernel(const float* __restrict__ in, float* __restrict__ out, int n)
{
    int i = blockIdx.x * 1024 + threadIdx.x * 4;
    if (i + 3 < n) {
        float4 v = *(const float4*)(in + i);
        float4 o;
        o.x = round_tf32(v.x); o.y = round_tf32(v.y);
        o.z = round_tf32(v.z); o.w = round_tf32(v.w);
        *(float4*)(out + i) = o;
    } else {
        for (int k = 0; k < 4 && i + k < n; k++) out[i + k] = round_tf32(in[i + k]);
    }
}

// ============================================================
// LayerNorm: one block per row; dual output (fp32 + tf32-rounded)
// ============================================================
__global__ __launch_bounds__(256)
void ln_kernel(const float* __restrict__ x, const float* __restrict__ w,
               const float* __restrict__ b, float* __restrict__ out,
               float* __restrict__ out_t)
{
    int row = blockIdx.x;
    int t = threadIdx.x;
    const float4* xr = (const float4*)(x + (size_t)row * CDIM);
    float4 v = xr[t];
    float s  = v.x + v.y + v.z + v.w;
    float sq = v.x*v.x + v.y*v.y + v.z*v.z + v.w*v.w;
    #pragma unroll
    for (int o = 16; o > 0; o >>= 1) {
        s  += __shfl_xor_sync(0xFFFFFFFFu, s,  o);
        sq += __shfl_xor_sync(0xFFFFFFFFu, sq, o);
    }
    __shared__ float red[2][8];
    int wid = t >> 5, lid = t & 31;
    if (lid == 0) { red[0][wid] = s; red[1][wid] = sq; }
    __syncthreads();
    float st = 0.f, sqt = 0.f;
    #pragma unroll
    for (int i = 0; i < 8; i++) { st += red[0][i]; sqt += red[1][i]; }
    float mu   = st * (1.0f / CDIM);
    float var  = sqt * (1.0f / CDIM) - mu * mu;
    float rstd = rsqrtf(var + 1e-5f);
    float4 wv = ((const float4*)w)[t];
    float4 bv = ((const float4*)b)[t];
    float4 o;
    o.x = (v.x - mu) * rstd * wv.x + bv.x;
    o.y = (v.y - mu) * rstd * wv.y + bv.y;
    o.z = (v.z - mu) * rstd * wv.z + bv.z;
    o.w = (v.w - mu) * rstd * wv.w + bv.w;
    ((float4*)(out + (size_t)row * CDIM))[t] = o;
    float4 ot;
    ot.x = round_tf32(o.x); ot.y = round_tf32(o.y);
    ot.z = round_tf32(o.z); ot.w = round_tf32(o.w);
    ((float4*)(out_t + (size_t)row * CDIM))[t] = ot;
}

// ============================================================
// tf32 mma.sync GEMM: C[M,N] = A[M,1024] @ W[N,1024]^T + bias
// BM=128, BN=128, BK=32, 3 stages, 256 thr, warp tile 64x32.
// MODE 0: plain. MODE 1: C = gamma*(acc+bias) + resid.
// ============================================================
template<int MODE>
__global__ __launch_bounds__(256, 1)
void gemm_mma(const float* __restrict__ A, const float* __restrict__ W,
              const float* __restrict__ bias, float* __restrict__ C,
              int Nvalid, int ldc,
              const float* __restrict__ resid, const float* __restrict__ gammap)
{
    constexpr int S = 3;
    constexpr int STAGE = 32768;  // 16KB A + 16KB B
    constexpr int NITER = CDIM / 32;

    extern __shared__ char smem_raw[];
    char* tiles = (char*)(((uintptr_t)smem_raw + 1023) & ~(uintptr_t)1023);
    const uint32_t base = smem_to_u32(tiles);

    const int tid = threadIdx.x;
    const int m0  = blockIdx.y * 128;
    const int n0  = blockIdx.x * 128;
    const int vrows = (Nvalid - n0 < 128) ? (Nvalid - n0) : 128;

    if (vrows < 128) {
        #pragma unroll
        for (int s = 0; s < S; s++) {
            float4* z = (float4*)(tiles + s * STAGE + 16384 + vrows * 128);
            int cnt = (128 - vrows) * 8;
            for (int i = tid; i < cnt; i += 256) z[i] = make_float4(0.f,0.f,0.f,0.f);
        }
        __syncthreads();
    }

    auto load_stage = [&](int c) {
        int st = c % S;
        uint32_t as = base + st * STAGE;
        uint32_t bs = as + 16384;
        const char* Ag = (const char*)(A + (size_t)m0 * CDIM + c * 32);
        const char* Wg = (const char*)(W + (size_t)n0 * CDIM + c * 32);
        #pragma unroll
        for (int i = 0; i < 4; i++) {
            int idx = tid + i * 256;
            int r = idx >> 3, u = idx & 7;
            CP_ASYNC16(as + r * 128 + ((u ^ (r & 7)) << 4),
                       Ag + (size_t)r * (CDIM * 4) + u * 16);
        }
        #pragma unroll
        for (int i = 0; i < 4; i++) {
            int idx = tid + i * 256;
            int r = idx >> 3, u = idx & 7;
            if (r < vrows)
                CP_ASYNC16(bs + r * 128 + ((u ^ (r & 7)) << 4),
                           Wg + (size_t)r * (CDIM * 4) + u * 16);
        }
        CP_COMMIT();
    };

    load_stage(0);
    load_stage(1);

    float acc[4][4][4];
    #pragma unroll
    for (int i = 0; i < 4; i++)
        #pragma unroll
        for (int j = 0; j < 4; j++)
            #pragma unroll
            for (int q = 0; q < 4; q++) acc[i][j][q] = 0.f;

    const int lane = tid & 31;
    const int wid  = tid >> 5;
    const int wm = (wid & 1) << 6;   // 0 or 64
    const int wn = (wid >> 1) << 5;  // 0,32,64,96
    const int sub = lane >> 3, rin = lane & 7;
    const int arow = wm + ((sub & 1) << 3) + rin;  // + mt*16
    const int au   = sub >> 1;                     // + 2*kk
    const int brow = wn + ((sub & 2) << 2) + rin;  // + nt2*16
    const int bu   = sub & 1;                      // + 2*kk

    for (int it = 0; it < NITER; it++) {
        asm volatile("cp.async.wait_group 1;" ::: "memory");
        __syncthreads();
        if (it + 2 < NITER) load_stage(it + 2);

        uint32_t as = base + (it % S) * STAGE;
        uint32_t bs = as + 16384;
        #pragma unroll
        for (int kk = 0; kk < 4; kk++) {
            uint32_t a[4][4], b[2][4];
            #pragma unroll
            for (int mt = 0; mt < 4; mt++) {
                int row = arow + mt * 16;
                int u = kk * 2 + au;
                uint32_t ad = as + row * 128 + ((u ^ (row & 7)) << 4);
                LDMATRIX_X4(a[mt][0], a[mt][1], a[mt][2], a[mt][3], ad);
            }
            #pragma unroll
            for (int nt2 = 0; nt2 < 2; nt2++) {
                int row = brow + nt2 * 16;
                int u = kk * 2 + bu;
                uint32_t ad = bs + row * 128 + ((u ^ (row & 7)) << 4);
                LDMATRIX_X4(b[nt2][0], b[nt2][1], b[nt2][2], b[nt2][3], ad);
            }
            #pragma unroll
            for (int mt = 0; mt < 4; mt++)
                #pragma unroll
                for (int nt = 0; nt < 4; nt++) {
                    uint32_t b0 = b[nt >> 1][(nt & 1) * 2];
                    uint32_t b1 = b[nt >> 1][(nt & 1) * 2 + 1];
                    asm volatile(
                        "mma.sync.aligned.m16n8k8.row.col.f32.tf32.tf32.f32 "
                        "{%0,%1,%2,%3}, {%4,%5,%6,%7}, {%8,%9}, {%0,%1,%2,%3};"
                        : "+f"(acc[mt][nt][0]), "+f"(acc[mt][nt][1]),
                          "+f"(acc[mt][nt][2]), "+f"(acc[mt][nt][3])
                        : "r"(a[mt][0]), "r"(a[mt][1]), "r"(a[mt][2]), "r"(a[mt][3]),
                          "r"(b0), "r"(b1));
                }
        }
    }

    // ---- epilogue ----
    const int g = lane >> 2, tig = lane & 3;
    const float gm = (MODE == 1) ? gammap[0] : 0.f;
    const bool fast = (n0 + 128 <= Nvalid);
    #pragma unroll
    for (int mt = 0; mt < 4; mt++) {
        #pragma unroll
        for (int nt = 0; nt < 4; nt++) {
            int m = m0 + wm + mt * 16 + g;
            int n = n0 + wn + nt * 8 + tig * 2;
            if (fast) {
                float b0 = bias[n], b1 = bias[n + 1];
                #pragma unroll
                for (int h = 0; h < 2; h++) {
                    int mr = m + h * 8;
                    float v0 = acc[mt][nt][h * 2 + 0] + b0;
                    float v1 = acc[mt][nt][h * 2 + 1] + b1;
                    if (MODE == 1) {
                        const float* rp = resid + (size_t)mr * CDIM + n;
                        v0 = gm * v0 + rp[0];
                        v1 = gm * v1 + rp[1];
                    }
                    *(float2*)(C + (size_t)mr * ldc + n) = make_float2(v0, v1);
                }
            } else {
                #pragma unroll
                for (int h = 0; h < 2; h++) {
                    int mr = m + h * 8;
                    #pragma unroll
                    for (int e = 0; e < 2; e++) {
                        int nc = n + e;
                        if (nc < Nvalid)
                            C[(size_t)mr * ldc + nc] = acc[mt][nt][h * 2 + e] + bias[nc];
                    }
                }
            }
        }
    }
}

// ============================================================
// Per-window attention; output rounded to tf32 (feeds R GEMM)
// ============================================================
__global__ __launch_bounds__(256)
void attn_kernel(const float* __restrict__ q, const float* __restrict__ kf,
                 const float* __restrict__ v, float* __restrict__ ao)
{
    __shared__ float Ss[49][50];
    __shared__ __align__(16) float buf[2 * 49 * 76];

    int wi = blockIdx.x;
    int b  = wi >> 6;
    int wh = (wi >> 3) & 7;
    int ww = wi & 7;
    int base = b * BATCH_STRIDE + wh * 7 * 56 + ww * 7;
    int t = threadIdx.x;

    float* Qs = buf;
    float* Ks = buf + 49 * 76;
    for (int kc = 0; kc < 2; kc++) {
        int kb = kc * 75;
        __syncthreads();
        for (int idx = t; idx < 49 * 75; idx += 256) {
            int n = idx / 75, k = idx - n * 75;
            int r = base + (n / 7) * 56 + (n % 7);
            Qs[n * 76 + k] = q [(size_t)r * KSEM + kb + k];
            Ks[n * 76 + k] = kf[(size_t)r * KSEM + kb + k];
        }
        __syncthreads();
        for (int p = t; p < 2401; p += 256) {
            int n = p / 49, m = p - n * 49;
            float d = 0.f;
            #pragma unroll 5
            for (int k = 0; k < 75; k++) d += Qs[n * 76 + k] * Ks[m * 76 + k];
            if (kc == 0) Ss[n][m] = d; else Ss[n][m] += d;
        }
    }
    __syncthreads();

    if (t < 49) {
        float mx = -1e30f;
        #pragma unroll
        for (int m = 0; m < 49; m++) mx = fmaxf(mx, Ss[t][m]);
        float sum = 0.f;
        #pragma unroll
        for (int m = 0; m < 49; m++) { float e = __expf(Ss[t][m] - mx); Ss[t][m] = e; sum += e; }
        float inv = 1.f / sum;
        #pragma unroll
        for (int m = 0; m < 49; m++) Ss[t][m] *= inv;
    }

    float* Vs = buf;
    int g  = t >> 5;
    int cq = t & 31;
    int nstart = g * 6;
    for (int cc = 0; cc < 8; cc++) {
        __syncthreads();
        int cbase = cc * 128;
        for (int idx = t; idx < 49 * 32; idx += 256) {
            int m = idx >> 5, qd = idx & 31;
            int r = base + (m / 7) * 56 + (m % 7);
            ((float4*)Vs)[m * 32 + qd] = *(const float4*)(v + (size_t)r * CDIM + cbase + qd * 4);
        }
        __syncthreads();
        float4 acc[7];
        #pragma unroll
        for (int i = 0; i < 7; i++) acc[i] = make_float4(0.f, 0.f, 0.f, 0.f);
        for (int m = 0; m < 49; m++) {
            float4 vv = ((float4*)Vs)[m * 32 + cq];
            #pragma unroll
            for (int i = 0; i < 7; i++) {
                float s = Ss[nstart + i][m];
                acc[i].x += s * vv.x; acc[i].y += s * vv.y;
                acc[i].z += s * vv.z; acc[i].w += s * vv.w;
            }
        }
        #pragma unroll
        for (int i = 0; i < 7; i++) {
            int n = nstart + i;
            int r = base + (n / 7) * 56 + (n % 7);
            float4 o;
            o.x = round_tf32(acc[i].x); o.y = round_tf32(acc[i].y);
            o.z = round_tf32(acc[i].z); o.w = round_tf32(acc[i].w);
            *(float4*)(ao + (size_t)r * CDIM + cbase + cq * 4) = o;
        }
    }
}

// ============================================================
// Host launcher
// ============================================================
extern "C" void kernel_launch(void* const* d_in, const int* in_sizes, int n_in,
                              void* d_out, int out_size)
{
    const float* x      = (const float*)d_in[0];
    const float* norm_w = (const float*)d_in[1];
    const float* norm_b = (const float*)d_in[2];
    const float* wq     = (const float*)d_in[3];
    const float* bq     = (const float*)d_in[4];
    const float* wk     = (const float*)d_in[5];
    const float* bk     = (const float*)d_in[6];
    const float* wv     = (const float*)d_in[7];
    const float* bv     = (const float*)d_in[8];
    const float* wr     = (const float*)d_in[9];
    const float* br     = (const float*)d_in[10];
    const float* gamma  = (const float*)d_in[11];
    (void)in_sizes; (void)n_in; (void)out_size;

    float* out  = (float*)d_out;
    float* sem  = out;                              // [50176, 150]
    float* xout = out + (size_t)M_ROWS * KSEM;      // [50176, 1024]

    float *xn, *xnt, *kf, *vv, *ao, *wqt, *wkt, *wvt, *wrt;
    cudaGetSymbolAddress((void**)&xn,  g_xn);
    cudaGetSymbolAddress((void**)&xnt, g_xnt);
    cudaGetSymbolAddress((void**)&kf,  g_kf);
    cudaGetSymbolAddress((void**)&vv,  g_v);
    cudaGetSymbolAddress((void**)&ao,  g_ao);
    cudaGetSymbolAddress((void**)&wqt, g_wqt);
    cudaGetSymbolAddress((void**)&wkt, g_wkt);
    cudaGetSymbolAddress((void**)&wvt, g_wvt);
    cudaGetSymbolAddress((void**)&wrt, g_wrt);

    const int SMEM = 3 * 32768 + 1024;
    cudaFuncSetAttribute(gemm_mma<0>, cudaFuncAttributeMaxDynamicSharedMemorySize, SMEM);
    cudaFuncSetAttribute(gemm_mma<1>, cudaFuncAttributeMaxDynamicSharedMemorySize, SMEM);

    // 0) round weights to tf32 (RN, unbiased)
    round_kernel<<<(KSEM * CDIM + 1023) / 1024, 256>>>(wq, wqt, KSEM * CDIM);
    round_kernel<<<(KSEM * CDIM + 1023) / 1024, 256>>>(wk, wkt, KSEM * CDIM);
    round_kernel<<<(CDIM * CDIM + 1023) / 1024, 256>>>(wv, wvt, CDIM * CDIM);
    round_kernel<<<(CDIM * CDIM + 1023) / 1024, 256>>>(wr, wrt, CDIM * CDIM);

    // 1) LayerNorm (fp32 + tf32 outputs)
    ln_kernel<<<M_ROWS, 256>>>(x, norm_w, norm_b, xn, xnt);

    // 2) Q -> sem (d_out), K -> scratch
    gemm_mma<0><<<dim3(2, M_ROWS / 128), 256, SMEM>>>(xnt, wqt, bq, sem, KSEM, KSEM, nullptr, nullptr);
    gemm_mma<0><<<dim3(2, M_ROWS / 128), 256, SMEM>>>(xnt, wkt, bk, kf,  KSEM, KSEM, nullptr, nullptr);

    // 3) V projection
    gemm_mma<0><<<dim3(8, M_ROWS / 128), 256, SMEM>>>(xnt, wvt, bv, vv, CDIM, CDIM, nullptr, nullptr);

    // 4) per-window attention
    attn_kernel<<<NWIN, 256>>>(sem, kf, vv, ao);

    // 5) output projection + gamma residual (residual = fp32 xn)
    gemm_mma<1><<<dim3(8, M_ROWS / 128), 256, SMEM>>>(ao, wrt, br, xout, CDIM, CDIM, xn, gamma);
}

// round 4
// speedup vs baseline: 5.4318x; 1.6862x over previous
#include <cuda_runtime.h>
#include <cuda_fp16.h>
#include <cstdint>
#include <cstddef>

// Problem constants (B=16, H=W=56, C=1024, K=150, WS=7)
#define M_ROWS 50176
#define CDIM   1024
#define KSEM   150
#define NWIN   1024
#define BATCH_STRIDE 3136

// -------- scratch (device globals) --------
__device__ float  g_xn  [(size_t)M_ROWS * CDIM];   // LN out fp32 (residual)
__device__ __half g_xnh [(size_t)M_ROWS * CDIM];   // LN out half (GEMM A)
__device__ float  g_kf  [(size_t)M_ROWS * KSEM];   // seg_ft
__device__ float  g_v   [(size_t)M_ROWS * CDIM];   // V projection
__device__ __half g_aoh [(size_t)M_ROWS * CDIM];   // attention out half
__device__ __half g_wqkh[(size_t)300 * CDIM];      // wq(150) + wk(150) stacked
__device__ __half g_wvh [(size_t)CDIM * CDIM];
__device__ __half g_wrh [(size_t)CDIM * CDIM];

__device__ __forceinline__ uint32_t smem_to_u32(const void* p) {
    uint32_t a;
    asm("{ .reg .u64 t; cvta.to.shared.u64 t, %1; cvt.u32.u64 %0, t; }" : "=r"(a) : "l"(p));
    return a;
}
#define CP_ASYNC16(dst, src) \
    asm volatile("cp.async.cg.shared.global [%0], [%1], 16;" :: "r"(dst), "l"(src) : "memory")
#define CP_COMMIT() asm volatile("cp.async.commit_group;" ::: "memory")
#define LDMATRIX_X4(r0, r1, r2, r3, addr) \
    asm volatile("ldmatrix.sync.aligned.m8n8.x4.shared.b16 {%0,%1,%2,%3}, [%4];" \
        : "=r"(r0), "=r"(r1), "=r"(r2), "=r"(r3) : "r"(addr))

// ============================================================
// fp32 -> fp16 conversion (RN)
// ============================================================
__global__ __launch_bounds__(256)
void f2h_kernel(const float* __restrict__ in, __half* __restrict__ out, int n)
{
    int i = blockIdx.x * 1024 + threadIdx.x * 4;
    if (i + 3 < n) {
        float4 v = *(const float4*)(in + i);
        __half2 h0 = __floats2half2_rn(v.x, v.y);
        __half2 h1 = __floats2half2_rn(v.z, v.w);
        *(__half2*)(out + i)     = h0;
        *(__half2*)(out + i + 2) = h1;
    } else {
        for (int k = 0; k < 4 && i + k < n; k++) out[i + k] = __float2half_rn(in[i + k]);
    }
}

// ============================================================
// LayerNorm: fp32 out (residual) + half out (GEMM A)
// ============================================================
__global__ __launch_bounds__(256)
void ln_kernel(const float* __restrict__ x, const float* __restrict__ w,
               const float* __restrict__ b, float* __restrict__ out,
               __half* __restrict__ outh)
{
    int row = blockIdx.x;
    int t = threadIdx.x;
    const float4* xr = (const float4*)(x + (size_t)row * CDIM);
    float4 v = xr[t];
    float s  = v.x + v.y + v.z + v.w;
    float sq = v.x*v.x + v.y*v.y + v.z*v.z + v.w*v.w;
    #pragma unroll
    for (int o = 16; o > 0; o >>= 1) {
        s  += __shfl_xor_sync(0xFFFFFFFFu, s,  o);
        sq += __shfl_xor_sync(0xFFFFFFFFu, sq, o);
    }
    __shared__ float red[2][8];
    int wid = t >> 5, lid = t & 31;
    if (lid == 0) { red[0][wid] = s; red[1][wid] = sq; }
    __syncthreads();
    float st = 0.f, sqt = 0.f;
    #pragma unroll
    for (int i = 0; i < 8; i++) { st += red[0][i]; sqt += red[1][i]; }
    float mu   = st * (1.0f / CDIM);
    float var  = sqt * (1.0f / CDIM) - mu * mu;
    float rstd = rsqrtf(var + 1e-5f);
    float4 wv = ((const float4*)w)[t];
    float4 bv = ((const float4*)b)[t];
    float4 o;
    o.x = (v.x - mu) * rstd * wv.x + bv.x;
    o.y = (v.y - mu) * rstd * wv.y + bv.y;
    o.z = (v.z - mu) * rstd * wv.z + bv.z;
    o.w = (v.w - mu) * rstd * wv.w + bv.w;
    ((float4*)(out + (size_t)row * CDIM))[t] = o;
    __half2 h0 = __floats2half2_rn(o.x, o.y);
    __half2 h1 = __floats2half2_rn(o.z, o.w);
    __half2* hp = (__half2*)(outh + (size_t)row * CDIM + t * 4);
    hp[0] = h0; hp[1] = h1;
}

// ============================================================
// fp16 mma.sync GEMM: C[M,N] = A[M,1024] @ W[N,1024]^T + bias
// BM=128, BN=256, BK=64, 3 stages, 256 thr, warp tile 64x64.
// MODE 0: C0 = acc + bias0.
// MODE 1: C0 = gamma*(acc+bias0) + resid.
// MODE 2: route by n: n<150 -> C0(sem)+bias0, else C1(kf)+bias1.  (Nvalid=300)
// ============================================================
template<int MODE>
__global__ __launch_bounds__(256, 1)
void gemm_h(const __half* __restrict__ A, const __half* __restrict__ W,
            const float* __restrict__ bias0, const float* __restrict__ bias1,
            float* __restrict__ C0, float* __restrict__ C1,
            int Nvalid, int ldc,
            const float* __restrict__ resid, const float* __restrict__ gammap)
{
    constexpr int S = 3;
    constexpr int A_BYTES = 128 * 128;      // 16 KB (128 rows x 64 half)
    constexpr int B_BYTES = 256 * 128;      // 32 KB
    constexpr int STAGE = A_BYTES + B_BYTES;
    constexpr int NITER = CDIM / 64;        // 16

    extern __shared__ char smem_raw[];
    char* tiles = (char*)(((uintptr_t)smem_raw + 1023) & ~(uintptr_t)1023);
    const uint32_t base = smem_to_u32(tiles);

    const int tid = threadIdx.x;
    const int m0  = blockIdx.y * 128;
    const int n0  = blockIdx.x * 256;
    const int vrows = (Nvalid - n0 < 256) ? (Nvalid - n0) : 256;

    if (vrows < 256) {
        #pragma unroll
        for (int s = 0; s < S; s++) {
            float4* z = (float4*)(tiles + s * STAGE + A_BYTES + vrows * 128);
            int cnt = (256 - vrows) * 8;
            for (int i = tid; i < cnt; i += 256) z[i] = make_float4(0.f, 0.f, 0.f, 0.f);
        }
        __syncthreads();
    }

    auto load_stage = [&](int c) {
        int st = c % S;
        uint32_t as = base + st * STAGE;
        uint32_t bs = as + A_BYTES;
        const char* Ag = (const char*)A + (size_t)m0 * (CDIM * 2) + c * 128;
        const char* Wg = (const char*)W + (size_t)n0 * (CDIM * 2) + c * 128;
        #pragma unroll
        for (int i = 0; i < 4; i++) {
            int idx = tid + i * 256;
            int r = idx >> 3, u = idx & 7;
            CP_ASYNC16(as + r * 128 + ((u ^ (r & 7)) << 4),
                       Ag + (size_t)r * (CDIM * 2) + u * 16);
        }
        #pragma unroll
        for (int i = 0; i < 8; i++) {
            int idx = tid + i * 256;
            int r = idx >> 3, u = idx & 7;
            if (r < vrows)
                CP_ASYNC16(bs + r * 128 + ((u ^ (r & 7)) << 4),
                           Wg + (size_t)r * (CDIM * 2) + u * 16);
        }
        CP_COMMIT();
    };

    load_stage(0);
    load_stage(1);

    float acc[4][8][4];
    #pragma unroll
    for (int i = 0; i < 4; i++)
        #pragma unroll
        for (int j = 0; j < 8; j++)
            #pragma unroll
            for (int q = 0; q < 4; q++) acc[i][j][q] = 0.f;

    const int lane = tid & 31;
    const int wid  = tid >> 5;
    const int wm = (wid & 1) << 6;   // 0 or 64
    const int wn = (wid >> 1) << 6;  // 0,64,128,192

    // ldmatrix lane-address components
    const int arow_l = wm + (lane & 15);               // + mt*16
    const int au_l   = lane >> 4;                      // + 2*kk
    const int brow_l = wn + (lane & 7) + ((lane >> 4) << 3);  // + np*16
    const int bu_l   = (lane >> 3) & 1;                // + 2*kk

    for (int it = 0; it < NITER; it++) {
        asm volatile("cp.async.wait_group 1;" ::: "memory");
        __syncthreads();
        if (it + 2 < NITER) load_stage(it + 2);

        uint32_t as = base + (it % S) * STAGE;
        uint32_t bs = as + A_BYTES;
        #pragma unroll
        for (int kk = 0; kk < 4; kk++) {
            uint32_t a[4][4], b[4][4];
            #pragma unroll
            for (int mt = 0; mt < 4; mt++) {
                int row = arow_l + mt * 16;
                int u = kk * 2 + au_l;
                uint32_t ad = as + row * 128 + ((u ^ (row & 7)) << 4);
                LDMATRIX_X4(a[mt][0], a[mt][1], a[mt][2], a[mt][3], ad);
            }
            #pragma unroll
            for (int np = 0; np < 4; np++) {
                int row = brow_l + np * 16;
                int u = kk * 2 + bu_l;
                uint32_t ad = bs + row * 128 + ((u ^ (row & 7)) << 4);
                LDMATRIX_X4(b[np][0], b[np][1], b[np][2], b[np][3], ad);
            }
            #pragma unroll
            for (int mt = 0; mt < 4; mt++)
                #pragma unroll
                for (int nt = 0; nt < 8; nt++) {
                    uint32_t b0 = b[nt >> 1][(nt & 1) * 2];
                    uint32_t b1 = b[nt >> 1][(nt & 1) * 2 + 1];
                    asm volatile(
                        "mma.sync.aligned.m16n8k16.row.col.f32.f16.f16.f32 "
                        "{%0,%1,%2,%3}, {%4,%5,%6,%7}, {%8,%9}, {%0,%1,%2,%3};"
                        : "+f"(acc[mt][nt][0]), "+f"(acc[mt][nt][1]),
                          "+f"(acc[mt][nt][2]), "+f"(acc[mt][nt][3])
                        : "r"(a[mt][0]), "r"(a[mt][1]), "r"(a[mt][2]), "r"(a[mt][3]),
                          "r"(b0), "r"(b1));
                }
        }
    }

    // ---- epilogue ----
    const int g = lane >> 2, tig = lane & 3;
    const float gm = (MODE == 1) ? gammap[0] : 0.f;
    #pragma unroll
    for (int mt = 0; mt < 4; mt++) {
        #pragma unroll
        for (int nt = 0; nt < 8; nt++) {
            int m = m0 + wm + mt * 16 + g;
            int n = n0 + wn + nt * 8 + tig * 2;
            if (MODE == 2) {
                if (n >= Nvalid) continue;
                float* dst; const float* bp; int nn;
                if (n < 150) { dst = C0; bp = bias0; nn = n; }
                else         { dst = C1; bp = bias1; nn = n - 150; }
                #pragma unroll
                for (int h = 0; h < 2; h++) {
                    int mr = m + h * 8;
                    dst[(size_t)mr * ldc + nn]     = acc[mt][nt][h*2+0] + bp[nn];
                    dst[(size_t)mr * ldc + nn + 1] = acc[mt][nt][h*2+1] + bp[nn + 1];
                }
            } else {
                float b0 = bias0[n], b1 = bias0[n + 1];
                #pragma unroll
                for (int h = 0; h < 2; h++) {
                    int mr = m + h * 8;
                    float v0 = acc[mt][nt][h*2+0] + b0;
                    float v1 = acc[mt][nt][h*2+1] + b1;
                    if (MODE == 1) {
                        const float* rp = resid + (size_t)mr * CDIM + n;
                        v0 = gm * v0 + rp[0];
                        v1 = gm * v1 + rp[1];
                    }
                    *(float2*)(C0 + (size_t)mr * ldc + n) = make_float2(v0, v1);
                }
            }
        }
    }
}

// ============================================================
// Per-window attention; half output (feeds R GEMM)
// ============================================================
__global__ __launch_bounds__(256)
void attn_kernel(const float* __restrict__ q, const float* __restrict__ kf,
                 const float* __restrict__ v, __half* __restrict__ ao)
{
    __shared__ float Ss[49][50];
    __shared__ __align__(16) float buf[2 * 49 * 76];

    int wi = blockIdx.x;
    int b  = wi >> 6;
    int wh = (wi >> 3) & 7;
    int ww = wi & 7;
    int base = b * BATCH_STRIDE + wh * 7 * 56 + ww * 7;
    int t = threadIdx.x;

    float* Qs = buf;
    float* Ks = buf + 49 * 76;
    for (int kc = 0; kc < 2; kc++) {
        int kb = kc * 75;
        __syncthreads();
        for (int idx = t; idx < 49 * 75; idx += 256) {
            int n = idx / 75, k = idx - n * 75;
            int r = base + (n / 7) * 56 + (n % 7);
            Qs[n * 76 + k] = q [(size_t)r * KSEM + kb + k];
            Ks[n * 76 + k] = kf[(size_t)r * KSEM + kb + k];
        }
        __syncthreads();
        for (int p = t; p < 2401; p += 256) {
            int n = p / 49, m = p - n * 49;
            float d = 0.f;
            #pragma unroll 5
            for (int k = 0; k < 75; k++) d += Qs[n * 76 + k] * Ks[m * 76 + k];
            if (kc == 0) Ss[n][m] = d; else Ss[n][m] += d;
        }
    }
    __syncthreads();

    if (t < 49) {
        float mx = -1e30f;
        #pragma unroll
        for (int m = 0; m < 49; m++) mx = fmaxf(mx, Ss[t][m]);
        float sum = 0.f;
        #pragma unroll
        for (int m = 0; m < 49; m++) { float e = __expf(Ss[t][m] - mx); Ss[t][m] = e; sum += e; }
        float inv = 1.f / sum;
        #pragma unroll
        for (int m = 0; m < 49; m++) Ss[t][m] *= inv;
    }

    float* Vs = buf;
    int g  = t >> 5;
    int cq = t & 31;
    int nstart = g * 6;
    for (int cc = 0; cc < 8; cc++) {
        __syncthreads();
        int cbase = cc * 128;
        for (int idx = t; idx < 49 * 32; idx += 256) {
            int m = idx >> 5, qd = idx & 31;
            int r = base + (m / 7) * 56 + (m % 7);
            ((float4*)Vs)[m * 32 + qd] = *(const float4*)(v + (size_t)r * CDIM + cbase + qd * 4);
        }
        __syncthreads();
        float4 acc[7];
        #pragma unroll
        for (int i = 0; i < 7; i++) acc[i] = make_float4(0.f, 0.f, 0.f, 0.f);
        for (int m = 0; m < 49; m++) {
            float4 vv = ((float4*)Vs)[m * 32 + cq];
            #pragma unroll
            for (int i = 0; i < 7; i++) {
                float s = Ss[nstart + i][m];
                acc[i].x += s * vv.x; acc[i].y += s * vv.y;
                acc[i].z += s * vv.z; acc[i].w += s * vv.w;
            }
        }
        #pragma unroll
        for (int i = 0; i < 7; i++) {
            int n = nstart + i;
            int r = base + (n / 7) * 56 + (n % 7);
            __half2 h0 = __floats2half2_rn(acc[i].x, acc[i].y);
            __half2 h1 = __floats2half2_rn(acc[i].z, acc[i].w);
            __half2* hp = (__half2*)(ao + (size_t)r * CDIM + cbase + cq * 4);
            hp[0] = h0; hp[1] = h1;
        }
    }
}

// ============================================================
// Host launcher
// ============================================================
extern "C" void kernel_launch(void* const* d_in, const int* in_sizes, int n_in,
                              void* d_out, int out_size)
{
    const float* x      = (const float*)d_in[0];
    const float* norm_w = (const float*)d_in[1];
    const float* norm_b = (const float*)d_in[2];
    const float* wq     = (const float*)d_in[3];
    const float* bq     = (const float*)d_in[4];
    const float* wk     = (const float*)d_in[5];
    const float* bk     = (const float*)d_in[6];
    const float* wv     = (const float*)d_in[7];
    const float* bv     = (const float*)d_in[8];
    const float* wr     = (const float*)d_in[9];
    const float* br     = (const float*)d_in[10];
    const float* gamma  = (const float*)d_in[11];
    (void)in_sizes; (void)n_in; (void)out_size;

    float* out  = (float*)d_out;
    float* sem  = out;                              // [50176, 150]
    float* xout = out + (size_t)M_ROWS * KSEM;      // [50176, 1024]

    float *xn, *kf, *vv;
    __half *xnh, *aoh, *wqkh, *wvh, *wrh;
    cudaGetSymbolAddress((void**)&xn,   g_xn);
    cudaGetSymbolAddress((void**)&xnh,  g_xnh);
    cudaGetSymbolAddress((void**)&kf,   g_kf);
    cudaGetSymbolAddress((void**)&vv,   g_v);
    cudaGetSymbolAddress((void**)&aoh,  g_aoh);
    cudaGetSymbolAddress((void**)&wqkh, g_wqkh);
    cudaGetSymbolAddress((void**)&wvh,  g_wvh);
    cudaGetSymbolAddress((void**)&wrh,  g_wrh);

    const int SMEM = 3 * 49152 + 1024;  // 148480
    cudaFuncSetAttribute(gemm_h<0>, cudaFuncAttributeMaxDynamicSharedMemorySize, SMEM);
    cudaFuncSetAttribute(gemm_h<1>, cudaFuncAttributeMaxDynamicSharedMemorySize, SMEM);
    cudaFuncSetAttribute(gemm_h<2>, cudaFuncAttributeMaxDynamicSharedMemorySize, SMEM);

    // 0) weights -> half (wq+wk stacked)
    f2h_kernel<<<(KSEM * CDIM + 1023) / 1024, 256>>>(wq, wqkh, KSEM * CDIM);
    f2h_kernel<<<(KSEM * CDIM + 1023) / 1024, 256>>>(wk, wqkh + (size_t)KSEM * CDIM, KSEM * CDIM);
    f2h_kernel<<<(CDIM * CDIM + 1023) / 1024, 256>>>(wv, wvh, CDIM * CDIM);
    f2h_kernel<<<(CDIM * CDIM + 1023) / 1024, 256>>>(wr, wrh, CDIM * CDIM);

    // 1) LayerNorm (fp32 + half)
    ln_kernel<<<M_ROWS, 256>>>(x, norm_w, norm_b, xn, xnh);

    // 2) merged Q/K projection: N=300, routed to sem / kf
    gemm_h<2><<<dim3(2, M_ROWS / 128), 256, SMEM>>>(xnh, wqkh, bq, bk, sem, kf, 300, KSEM, nullptr, nullptr);

    // 3) V projection
    gemm_h<0><<<dim3(4, M_ROWS / 128), 256, SMEM>>>(xnh, wvh, bv, nullptr, vv, nullptr, CDIM, CDIM, nullptr, nullptr);

    // 4) per-window attention (half output)
    attn_kernel<<<NWIN, 256>>>(sem, kf, vv, aoh);

    // 5) output projection + gamma residual
    gemm_h<1><<<dim3(4, M_ROWS / 128), 256, SMEM>>>(aoh, wrh, br, nullptr, xout, nullptr, CDIM, CDIM, xn, gamma);
}

// round 5
// speedup vs baseline: 6.6796x; 1.2297x over previous
#include <cuda_runtime.h>
#include <cuda_fp16.h>
#include <cstdint>
#include <cstddef>

// Problem constants (B=16, H=W=56, C=1024, K=150, WS=7)
#define M_ROWS 50176
#define CDIM   1024
#define KSEM   150
#define NWIN   1024
#define BATCH_STRIDE 3136

// -------- scratch (device globals) --------
__device__ float  g_xn  [(size_t)M_ROWS * CDIM];   // LN out fp32 (residual)
__device__ __half g_xnh [(size_t)M_ROWS * CDIM];   // LN out half (GEMM A)
__device__ __half g_semh[(size_t)M_ROWS * 160];    // seg_map half, padded stride
__device__ __half g_kfh [(size_t)M_ROWS * 160];    // seg_ft half, padded stride
__device__ __half g_vh  [(size_t)M_ROWS * CDIM];   // V projection half
__device__ __half g_aoh [(size_t)M_ROWS * CDIM];   // attention out half
__device__ __half g_wqkh[(size_t)300 * CDIM];      // wq(150) + wk(150) stacked
__device__ __half g_wvh [(size_t)CDIM * CDIM];
__device__ __half g_wrh [(size_t)CDIM * CDIM];

__device__ __forceinline__ uint32_t smem_to_u32(const void* p) {
    uint32_t a;
    asm("{ .reg .u64 t; cvta.to.shared.u64 t, %1; cvt.u32.u64 %0, t; }" : "=r"(a) : "l"(p));
    return a;
}
#define CP_ASYNC16(dst, src) \
    asm volatile("cp.async.cg.shared.global [%0], [%1], 16;" :: "r"(dst), "l"(src) : "memory")
#define CP_COMMIT() asm volatile("cp.async.commit_group;" ::: "memory")
#define LDMATRIX_X4(r0, r1, r2, r3, addr) \
    asm volatile("ldmatrix.sync.aligned.m8n8.x4.shared.b16 {%0,%1,%2,%3}, [%4];" \
        : "=r"(r0), "=r"(r1), "=r"(r2), "=r"(r3) : "r"(addr))
#define LDMATRIX_X4_T(r0, r1, r2, r3, addr) \
    asm volatile("ldmatrix.sync.aligned.m8n8.x4.trans.shared.b16 {%0,%1,%2,%3}, [%4];" \
        : "=r"(r0), "=r"(r1), "=r"(r2), "=r"(r3) : "r"(addr))
#define MMA16816(acc, a, b0, b1) \
    asm volatile("mma.sync.aligned.m16n8k16.row.col.f32.f16.f16.f32 " \
        "{%0,%1,%2,%3}, {%4,%5,%6,%7}, {%8,%9}, {%0,%1,%2,%3};" \
        : "+f"((acc)[0]), "+f"((acc)[1]), "+f"((acc)[2]), "+f"((acc)[3]) \
        : "r"((a)[0]), "r"((a)[1]), "r"((a)[2]), "r"((a)[3]), "r"(b0), "r"(b1))

// ============================================================
// fp32 -> fp16 conversion (RN)
// ============================================================
__global__ __launch_bounds__(256)
void f2h_kernel(const float* __restrict__ in, __half* __restrict__ out, int n)
{
    int i = blockIdx.x * 1024 + threadIdx.x * 4;
    if (i + 3 < n) {
        float4 v = *(const float4*)(in + i);
        *(__half2*)(out + i)     = __floats2half2_rn(v.x, v.y);
        *(__half2*)(out + i + 2) = __floats2half2_rn(v.z, v.w);
    } else {
        for (int k = 0; k < 4 && i + k < n; k++) out[i + k] = __float2half_rn(in[i + k]);
    }
}

// zero-fill a half buffer (counted in float4 units)
__global__ __launch_bounds__(256)
void zero_kernel(__half* __restrict__ p, int n4)
{
    int i = blockIdx.x * blockDim.x + threadIdx.x;
    float4 z = make_float4(0.f, 0.f, 0.f, 0.f);
    for (; i < n4; i += gridDim.x * blockDim.x) ((float4*)p)[i] = z;
}

// ============================================================
// LayerNorm: fp32 out (residual) + half out (GEMM A)
// ============================================================
__global__ __launch_bounds__(256)
void ln_kernel(const float* __restrict__ x, const float* __restrict__ w,
               const float* __restrict__ b, float* __restrict__ out,
               __half* __restrict__ outh)
{
    int row = blockIdx.x;
    int t = threadIdx.x;
    const float4* xr = (const float4*)(x + (size_t)row * CDIM);
    float4 v = xr[t];
    float s  = v.x + v.y + v.z + v.w;
    float sq = v.x*v.x + v.y*v.y + v.z*v.z + v.w*v.w;
    #pragma unroll
    for (int o = 16; o > 0; o >>= 1) {
        s  += __shfl_xor_sync(0xFFFFFFFFu, s,  o);
        sq += __shfl_xor_sync(0xFFFFFFFFu, sq, o);
    }
    __shared__ float red[2][8];
    int wid = t >> 5, lid = t & 31;
    if (lid == 0) { red[0][wid] = s; red[1][wid] = sq; }
    __syncthreads();
    float st = 0.f, sqt = 0.f;
    #pragma unroll
    for (int i = 0; i < 8; i++) { st += red[0][i]; sqt += red[1][i]; }
    float mu   = st * (1.0f / CDIM);
    float var  = sqt * (1.0f / CDIM) - mu * mu;
    float rstd = rsqrtf(var + 1e-5f);
    float4 wv = ((const float4*)w)[t];
    float4 bv = ((const float4*)b)[t];
    float4 o;
    o.x = (v.x - mu) * rstd * wv.x + bv.x;
    o.y = (v.y - mu) * rstd * wv.y + bv.y;
    o.z = (v.z - mu) * rstd * wv.z + bv.z;
    o.w = (v.w - mu) * rstd * wv.w + bv.w;
    ((float4*)(out + (size_t)row * CDIM))[t] = o;
    __half2* hp = (__half2*)(outh + (size_t)row * CDIM + t * 4);
    hp[0] = __floats2half2_rn(o.x, o.y);
    hp[1] = __floats2half2_rn(o.z, o.w);
}

// ============================================================
// fp16 mma.sync GEMM: BM=128, BN=256, BK=64, 3 stages, 256 thr.
// MODE 1: C0 fp32 = gamma*(acc+bias0) + resid
// MODE 2: n<150 -> C0 fp32 sem (ldc 150) + H0 half (stride 160);
//         n>=150 -> H1 half kf (stride 160). Nvalid=300.
// MODE 3: H0 half = acc + bias0 (stride 1024)
// ============================================================
template<int MODE>
__global__ __launch_bounds__(256, 1)
void gemm_h(const __half* __restrict__ A, const __half* __restrict__ W,
            const float* __restrict__ bias0, const float* __restrict__ bias1,
            float* __restrict__ C0, __half* __restrict__ H0, __half* __restrict__ H1,
            int Nvalid, int ldc,
            const float* __restrict__ resid, const float* __restrict__ gammap)
{
    constexpr int S = 3;
    constexpr int A_BYTES = 128 * 128;
    constexpr int B_BYTES = 256 * 128;
    constexpr int STAGE = A_BYTES + B_BYTES;
    constexpr int NITER = CDIM / 64;

    extern __shared__ char smem_raw[];
    char* tiles = (char*)(((uintptr_t)smem_raw + 1023) & ~(uintptr_t)1023);
    const uint32_t base = smem_to_u32(tiles);

    const int tid = threadIdx.x;
    const int m0  = blockIdx.y * 128;
    const int n0  = blockIdx.x * 256;
    const int vrows = (Nvalid - n0 < 256) ? (Nvalid - n0) : 256;

    if (vrows < 256) {
        #pragma unroll
        for (int s = 0; s < S; s++) {
            float4* z = (float4*)(tiles + s * STAGE + A_BYTES + vrows * 128);
            int cnt = (256 - vrows) * 8;
            for (int i = tid; i < cnt; i += 256) z[i] = make_float4(0.f, 0.f, 0.f, 0.f);
        }
        __syncthreads();
    }

    auto load_stage = [&](int c) {
        int st = c % S;
        uint32_t as = base + st * STAGE;
        uint32_t bs = as + A_BYTES;
        const char* Ag = (const char*)A + (size_t)m0 * (CDIM * 2) + c * 128;
        const char* Wg = (const char*)W + (size_t)n0 * (CDIM * 2) + c * 128;
        #pragma unroll
        for (int i = 0; i < 4; i++) {
            int idx = tid + i * 256;
            int r = idx >> 3, u = idx & 7;
            CP_ASYNC16(as + r * 128 + ((u ^ (r & 7)) << 4),
                       Ag + (size_t)r * (CDIM * 2) + u * 16);
        }
        #pragma unroll
        for (int i = 0; i < 8; i++) {
            int idx = tid + i * 256;
            int r = idx >> 3, u = idx & 7;
            if (r < vrows)
                CP_ASYNC16(bs + r * 128 + ((u ^ (r & 7)) << 4),
                           Wg + (size_t)r * (CDIM * 2) + u * 16);
        }
        CP_COMMIT();
    };

    load_stage(0);
    load_stage(1);

    float acc[4][8][4];
    #pragma unroll
    for (int i = 0; i < 4; i++)
        #pragma unroll
        for (int j = 0; j < 8; j++)
            #pragma unroll
            for (int q = 0; q < 4; q++) acc[i][j][q] = 0.f;

    const int lane = tid & 31;
    const int wid  = tid >> 5;
    const int wm = (wid & 1) << 6;
    const int wn = (wid >> 1) << 6;

    const int arow_l = wm + (lane & 15);
    const int au_l   = lane >> 4;
    const int brow_l = wn + (lane & 7) + ((lane >> 4) << 3);
    const int bu_l   = (lane >> 3) & 1;

    for (int it = 0; it < NITER; it++) {
        asm volatile("cp.async.wait_group 1;" ::: "memory");
        __syncthreads();
        if (it + 2 < NITER) load_stage(it + 2);

        uint32_t as = base + (it % S) * STAGE;
        uint32_t bs = as + A_BYTES;
        #pragma unroll
        for (int kk = 0; kk < 4; kk++) {
            uint32_t a[4][4], b[4][4];
            #pragma unroll
            for (int mt = 0; mt < 4; mt++) {
                int row = arow_l + mt * 16;
                int u = kk * 2 + au_l;
                LDMATRIX_X4(a[mt][0], a[mt][1], a[mt][2], a[mt][3],
                            as + row * 128 + ((u ^ (row & 7)) << 4));
            }
            #pragma unroll
            for (int np = 0; np < 4; np++) {
                int row = brow_l + np * 16;
                int u = kk * 2 + bu_l;
                LDMATRIX_X4(b[np][0], b[np][1], b[np][2], b[np][3],
                            bs + row * 128 + ((u ^ (row & 7)) << 4));
            }
            #pragma unroll
            for (int mt = 0; mt < 4; mt++)
                #pragma unroll
                for (int nt = 0; nt < 8; nt++)
                    MMA16816(acc[mt][nt], a[mt],
                             b[nt >> 1][(nt & 1) * 2], b[nt >> 1][(nt & 1) * 2 + 1]);
        }
    }

    // ---- epilogue ----
    const int g = lane >> 2, tig = lane & 3;
    const float gm = (MODE == 1) ? gammap[0] : 0.f;
    #pragma unroll
    for (int mt = 0; mt < 4; mt++) {
        #pragma unroll
        for (int nt = 0; nt < 8; nt++) {
            int m = m0 + wm + mt * 16 + g;
            int n = n0 + wn + nt * 8 + tig * 2;
            if (MODE == 2) {
                if (n >= Nvalid) continue;
                #pragma unroll
                for (int h = 0; h < 2; h++) {
                    int mr = m + h * 8;
                    float v0, v1;
                    if (n < 150) {
                        v0 = acc[mt][nt][h*2+0] + bias0[n];
                        v1 = acc[mt][nt][h*2+1] + bias0[n + 1];
                        C0[(size_t)mr * 150 + n]     = v0;
                        C0[(size_t)mr * 150 + n + 1] = v1;
                        *(__half2*)(H0 + (size_t)mr * 160 + n) = __floats2half2_rn(v0, v1);
                    } else {
                        int nn = n - 150;
                        v0 = acc[mt][nt][h*2+0] + bias1[nn];
                        v1 = acc[mt][nt][h*2+1] + bias1[nn + 1];
                        *(__half2*)(H1 + (size_t)mr * 160 + nn) = __floats2half2_rn(v0, v1);
                    }
                }
            } else if (MODE == 3) {
                float b0 = bias0[n], b1 = bias0[n + 1];
                #pragma unroll
                for (int h = 0; h < 2; h++) {
                    int mr = m + h * 8;
                    *(__half2*)(H0 + (size_t)mr * CDIM + n) =
                        __floats2half2_rn(acc[mt][nt][h*2+0] + b0, acc[mt][nt][h*2+1] + b1);
                }
            } else {
                float b0 = bias0[n], b1 = bias0[n + 1];
                #pragma unroll
                for (int h = 0; h < 2; h++) {
                    int mr = m + h * 8;
                    float v0 = acc[mt][nt][h*2+0] + b0;
                    float v1 = acc[mt][nt][h*2+1] + b1;
                    const float* rp = resid + (size_t)mr * CDIM + n;
                    v0 = gm * v0 + rp[0];
                    v1 = gm * v1 + rp[1];
                    *(float2*)(C0 + (size_t)mr * ldc + n) = make_float2(v0, v1);
                }
            }
        }
    }
}

// ============================================================
// HMMA per-window attention: 1 block (128 thr) per window.
// S = softmax(Q K^T) fp32; O = S V via fp16 mma; O -> half.
// smem: Qs/Ks 64x168h (stride 336B), Sf 64x66 f32, Sh 64x72h,
//       Vc (reuse of Qs) 64 rows x 272B.
// ============================================================
#define QK_STRB 336
#define SF_STR  66
#define SH_STRB 144
#define VC_STRB 272
#define ATTN_SMEM (43008 + 16896 + 9216)  // 69120

__global__ __launch_bounds__(128)
void attn_mma(const __half* __restrict__ semh, const __half* __restrict__ kfh,
              const __half* __restrict__ vh, __half* __restrict__ ao)
{
    extern __shared__ char sm[];
    char* Qc = sm;                    // 64 * 336B
    char* Kc = sm + 21504;            // 64 * 336B
    float* Sf = (float*)(sm + 43008); // 64 x 66 f32
    char* Shc = sm + 59904;           // 64 x 144B half
    char* Vc  = sm;                   // reuse: 64 x 272B

    const uint32_t qb  = smem_to_u32(Qc);
    const uint32_t kb  = smem_to_u32(Kc);
    const uint32_t shb = smem_to_u32(Shc);
    const uint32_t vb  = smem_to_u32(Vc);

    int wi = blockIdx.x;
    int b  = wi >> 6;
    int wh = (wi >> 3) & 7;
    int ww = wi & 7;
    int base = b * BATCH_STRIDE + wh * 7 * 56 + ww * 7;
    int t = threadIdx.x;
    const int lane = t & 31, w = t >> 5;

    // zero Q/K region (covers pad rows & cols)
    for (int i = t; i < 43008 / 16; i += 128)
        ((float4*)sm)[i] = make_float4(0.f, 0.f, 0.f, 0.f);
    __syncthreads();

    // gather Q, K rows (49 x 20 float4 each)
    for (int idx = t; idx < 49 * 20; idx += 128) {
        int n = idx / 20, u = idx % 20;
        int r = base + (n / 7) * 56 + (n % 7);
        ((float4*)(Qc + n * QK_STRB))[u] = ((const float4*)(semh + (size_t)r * 160))[u];
        ((float4*)(Kc + n * QK_STRB))[u] = ((const float4*)(kfh  + (size_t)r * 160))[u];
    }
    __syncthreads();

    // ---- Phase A: S = Q K^T  (per warp: rows 16w..16w+15 x all 64 keys)
    {
        float accS[8][4];
        #pragma unroll
        for (int j = 0; j < 8; j++)
            #pragma unroll
            for (int q = 0; q < 4; q++) accS[j][q] = 0.f;

        const int arow = 16 * w + (lane & 15);
        const int ak   = (lane >> 4) * 8;
        const int brow = (lane & 7) + ((lane >> 4) << 3);
        const int bk   = ((lane >> 3) & 1) * 8;

        #pragma unroll
        for (int ks = 0; ks < 10; ks++) {
            uint32_t a[4], bfr[4][4];
            LDMATRIX_X4(a[0], a[1], a[2], a[3],
                        qb + arow * QK_STRB + (ks * 16 + ak) * 2);
            #pragma unroll
            for (int np = 0; np < 4; np++)
                LDMATRIX_X4(bfr[np][0], bfr[np][1], bfr[np][2], bfr[np][3],
                            kb + (brow + np * 16) * QK_STRB + (ks * 16 + bk) * 2);
            #pragma unroll
            for (int nt = 0; nt < 8; nt++)
                MMA16816(accS[nt], a, bfr[nt >> 1][(nt & 1) * 2], bfr[nt >> 1][(nt & 1) * 2 + 1]);
        }
        const int g = lane >> 2, tig = lane & 3;
        #pragma unroll
        for (int nt = 0; nt < 8; nt++) {
            #pragma unroll
            for (int h = 0; h < 2; h++) {
                int row = 16 * w + g + h * 8;
                Sf[row * SF_STR + nt * 8 + tig * 2]     = accS[nt][h * 2 + 0];
                Sf[row * SF_STR + nt * 8 + tig * 2 + 1] = accS[nt][h * 2 + 1];
            }
        }
    }
    __syncthreads();

    // ---- softmax (rows 0..48, cols 0..48)
    if (t < 49) {
        float* row = Sf + t * SF_STR;
        float mx = -1e30f;
        #pragma unroll
        for (int m = 0; m < 49; m++) mx = fmaxf(mx, row[m]);
        float sum = 0.f;
        #pragma unroll
        for (int m = 0; m < 49; m++) { float e = __expf(row[m] - mx); row[m] = e; sum += e; }
        float inv = 1.f / sum;
        #pragma unroll
        for (int m = 0; m < 49; m++) row[m] *= inv;
    }
    __syncthreads();

    // ---- convert S -> half (zeros outside 49x49)
    for (int idx = t; idx < 4096; idx += 128) {
        int i = idx >> 6, j = idx & 63;
        float v = (i < 49 && j < 49) ? Sf[i * SF_STR + j] : 0.f;
        *((__half*)(Shc + i * SH_STRB) + j) = __float2half_rn(v);
    }

    // ---- Phase B: O = S V over 8 column chunks of 128
    const int arow = lane & 15;
    const int ak   = (lane >> 4) * 8;
    const int kk_l = (lane & 7) + ((lane >> 3) & 1) * 8;
    const int nc_l = 32 * w + ((lane >> 4) << 3);
    const int g = lane >> 2, tig = lane & 3;

    for (int cc = 0; cc < 8; cc++) {
        __syncthreads();
        for (int idx = t; idx < 49 * 16; idx += 128) {
            int m = idx >> 4, u = idx & 15;
            int r = base + (m / 7) * 56 + (m % 7);
            ((float4*)(Vc + m * VC_STRB))[u] =
                ((const float4*)(vh + (size_t)r * CDIM + cc * 128))[u];
        }
        __syncthreads();

        float acc[4][4][4];
        #pragma unroll
        for (int i = 0; i < 4; i++)
            #pragma unroll
            for (int j = 0; j < 4; j++)
                #pragma unroll
                for (int q = 0; q < 4; q++) acc[i][j][q] = 0.f;

        #pragma unroll
        for (int ks = 0; ks < 4; ks++) {
            uint32_t a[4][4], bq[2][4];
            #pragma unroll
            for (int mt = 0; mt < 4; mt++)
                LDMATRIX_X4(a[mt][0], a[mt][1], a[mt][2], a[mt][3],
                            shb + (16 * mt + arow) * SH_STRB + (ks * 16 + ak) * 2);
            #pragma unroll
            for (int nb = 0; nb < 2; nb++)
                LDMATRIX_X4_T(bq[nb][0], bq[nb][1], bq[nb][2], bq[nb][3],
                              vb + (ks * 16 + kk_l) * VC_STRB + (nc_l + nb * 16) * 2);
            #pragma unroll
            for (int mt = 0; mt < 4; mt++)
                #pragma unroll
                for (int nt = 0; nt < 4; nt++)
                    MMA16816(acc[mt][nt], a[mt],
                             bq[nt >> 1][(nt & 1) * 2], bq[nt >> 1][(nt & 1) * 2 + 1]);
        }

        #pragma unroll
        for (int mt = 0; mt < 4; mt++) {
            #pragma unroll
            for (int h = 0; h < 2; h++) {
                int m = 16 * mt + g + h * 8;
                if (m < 49) {
                    int r = base + (m / 7) * 56 + (m % 7);
                    __half* dst = ao + (size_t)r * CDIM + cc * 128;
                    #pragma unroll
                    for (int nt = 0; nt < 4; nt++) {
                        int n = 32 * w + nt * 8 + tig * 2;
                        *(__half2*)(dst + n) =
                            __floats2half2_rn(acc[mt][nt][h*2+0], acc[mt][nt][h*2+1]);
                    }
                }
            }
        }
    }
}

// ============================================================
// Host launcher
// ============================================================
extern "C" void kernel_launch(void* const* d_in, const int* in_sizes, int n_in,
                              void* d_out, int out_size)
{
    const float* x      = (const float*)d_in[0];
    const float* norm_w = (const float*)d_in[1];
    const float* norm_b = (const float*)d_in[2];
    const float* wq     = (const float*)d_in[3];
    const float* bq     = (const float*)d_in[4];
    const float* wk     = (const float*)d_in[5];
    const float* bk     = (const float*)d_in[6];
    const float* wv     = (const float*)d_in[7];
    const float* bv     = (const float*)d_in[8];
    const float* wr     = (const float*)d_in[9];
    const float* br     = (const float*)d_in[10];
    const float* gamma  = (const float*)d_in[11];
    (void)in_sizes; (void)n_in; (void)out_size;

    float* out  = (float*)d_out;
    float* sem  = out;                              // [50176, 150]
    float* xout = out + (size_t)M_ROWS * KSEM;      // [50176, 1024]

    float *xn;
    __half *xnh, *semh, *kfh, *vh, *aoh, *wqkh, *wvh, *wrh;
    cudaGetSymbolAddress((void**)&xn,   g_xn);
    cudaGetSymbolAddress((void**)&xnh,  g_xnh);
    cudaGetSymbolAddress((void**)&semh, g_semh);
    cudaGetSymbolAddress((void**)&kfh,  g_kfh);
    cudaGetSymbolAddress((void**)&vh,   g_vh);
    cudaGetSymbolAddress((void**)&aoh,  g_aoh);
    cudaGetSymbolAddress((void**)&wqkh, g_wqkh);
    cudaGetSymbolAddress((void**)&wvh,  g_wvh);
    cudaGetSymbolAddress((void**)&wrh,  g_wrh);

    const int SMEM = 3 * 49152 + 1024;
    cudaFuncSetAttribute(gemm_h<1>, cudaFuncAttributeMaxDynamicSharedMemorySize, SMEM);
    cudaFuncSetAttribute(gemm_h<2>, cudaFuncAttributeMaxDynamicSharedMemorySize, SMEM);
    cudaFuncSetAttribute(gemm_h<3>, cudaFuncAttributeMaxDynamicSharedMemorySize, SMEM);
    cudaFuncSetAttribute(attn_mma,  cudaFuncAttributeMaxDynamicSharedMemorySize, ATTN_SMEM);

    // 0) weights -> half
    f2h_kernel<<<(KSEM * CDIM + 1023) / 1024, 256>>>(wq, wqkh, KSEM * CDIM);
    f2h_kernel<<<(KSEM * CDIM + 1023) / 1024, 256>>>(wk, wqkh + (size_t)KSEM * CDIM, KSEM * CDIM);
    f2h_kernel<<<(CDIM * CDIM + 1023) / 1024, 256>>>(wv, wvh, CDIM * CDIM);
    f2h_kernel<<<(CDIM * CDIM + 1023) / 1024, 256>>>(wr, wrh, CDIM * CDIM);

    // zero padded halves of semh/kfh (pad cols 150..159 must be 0)
    zero_kernel<<<512, 256>>>(semh, M_ROWS * 160 / 8);
    zero_kernel<<<512, 256>>>(kfh,  M_ROWS * 160 / 8);

    // 1) LayerNorm
    ln_kernel<<<M_ROWS, 256>>>(x, norm_w, norm_b, xn, xnh);

    // 2) merged Q/K projection: N=300 -> sem fp32 + semh/kfh half
    gemm_h<2><<<dim3(2, M_ROWS / 128), 256, SMEM>>>(xnh, wqkh, bq, bk, sem, semh, kfh, 300, KSEM, nullptr, nullptr);

    // 3) V projection -> half
    gemm_h<3><<<dim3(4, M_ROWS / 128), 256, SMEM>>>(xnh, wvh, bv, nullptr, nullptr, vh, nullptr, CDIM, CDIM, nullptr, nullptr);

    // 4) HMMA attention
    attn_mma<<<NWIN, 128, ATTN_SMEM>>>(semh, kfh, vh, aoh);

    // 5) output projection + gamma residual
    gemm_h<1><<<dim3(4, M_ROWS / 128), 256, SMEM>>>(aoh, wrh, br, nullptr, xout, nullptr, nullptr, CDIM, CDIM, xn, gamma);
}

// round 6
// speedup vs baseline: 9.0765x; 1.3588x over previous
#include <cuda_runtime.h>
#include <cuda_fp16.h>
#include <cstdint>
#include <cstddef>

// Problem constants (B=16, H=W=56, C=1024, K=150, WS=7)
#define M_ROWS 50176
#define CDIM   1024
#define KSEM   150
#define NWIN   1024
#define BATCH_STRIDE 3136

// -------- scratch (device globals) --------
__device__ __half g_xnh [(size_t)M_ROWS * CDIM];   // LN out half (GEMM A, attn V, residual)
__device__ __half g_semh[(size_t)M_ROWS * 160];    // seg_map half, padded stride
__device__ __half g_kfh [(size_t)M_ROWS * 160];    // seg_ft half, padded stride
__device__ __half g_aoh [(size_t)M_ROWS * CDIM];   // attention out (S @ xn) half
__device__ __half g_wqkh[(size_t)300 * CDIM];      // wq(150) + wk(150) stacked
__device__ __half g_wrh [(size_t)CDIM * CDIM];     // wr half
__device__ __half g_wvth[(size_t)CDIM * CDIM];     // wv^T half
__device__ __half g_wch [(size_t)CDIM * CDIM];     // Wc = Wr @ Wv, half
__device__ float  g_bvr [CDIM];                    // Wr @ bv + br

__device__ __forceinline__ uint32_t smem_to_u32(const void* p) {
    uint32_t a;
    asm("{ .reg .u64 t; cvta.to.shared.u64 t, %1; cvt.u32.u64 %0, t; }" : "=r"(a) : "l"(p));
    return a;
}
#define CP_ASYNC16(dst, src) \
    asm volatile("cp.async.cg.shared.global [%0], [%1], 16;" :: "r"(dst), "l"(src) : "memory")
#define CP_COMMIT() asm volatile("cp.async.commit_group;" ::: "memory")
#define LDMATRIX_X4(r0, r1, r2, r3, addr) \
    asm volatile("ldmatrix.sync.aligned.m8n8.x4.shared.b16 {%0,%1,%2,%3}, [%4];" \
        : "=r"(r0), "=r"(r1), "=r"(r2), "=r"(r3) : "r"(addr))
#define LDMATRIX_X4_T(r0, r1, r2, r3, addr) \
    asm volatile("ldmatrix.sync.aligned.m8n8.x4.trans.shared.b16 {%0,%1,%2,%3}, [%4];" \
        : "=r"(r0), "=r"(r1), "=r"(r2), "=r"(r3) : "r"(addr))
#define MMA16816(acc, a, b0, b1) \
    asm volatile("mma.sync.aligned.m16n8k16.row.col.f32.f16.f16.f32 " \
        "{%0,%1,%2,%3}, {%4,%5,%6,%7}, {%8,%9}, {%0,%1,%2,%3};" \
        : "+f"((acc)[0]), "+f"((acc)[1]), "+f"((acc)[2]), "+f"((acc)[3]) \
        : "r"((a)[0]), "r"((a)[1]), "r"((a)[2]), "r"((a)[3]), "r"(b0), "r"(b1))

// ============================================================
// fp32 -> fp16 (RN)
// ============================================================
__global__ __launch_bounds__(256)
void f2h_kernel(const float* __restrict__ in, __half* __restrict__ out, int n)
{
    int i = blockIdx.x * 1024 + threadIdx.x * 4;
    if (i + 3 < n) {
        float4 v = *(const float4*)(in + i);
        *(__half2*)(out + i)     = __floats2half2_rn(v.x, v.y);
        *(__half2*)(out + i + 2) = __floats2half2_rn(v.z, v.w);
    } else {
        for (int k = 0; k < 4 && i + k < n; k++) out[i + k] = __float2half_rn(in[i + k]);
    }
}

// transpose 1024x1024 fp32 -> fp16
__global__ __launch_bounds__(256)
void t_f2h_kernel(const float* __restrict__ in, __half* __restrict__ out)
{
    __shared__ float tile[32][33];
    int x = blockIdx.x * 32 + threadIdx.x;
    int y0 = blockIdx.y * 32 + threadIdx.y;
    #pragma unroll
    for (int i = 0; i < 32; i += 8)
        tile[threadIdx.y + i][threadIdx.x] = in[(size_t)(y0 + i) * CDIM + x];
    __syncthreads();
    int x2 = blockIdx.y * 32 + threadIdx.x;
    int y2 = blockIdx.x * 32 + threadIdx.y;
    #pragma unroll
    for (int i = 0; i < 32; i += 8)
        out[(size_t)(y2 + i) * CDIM + x2] = __float2half_rn(tile[threadIdx.x][threadIdx.y + i]);
}

// bvr = Wr @ bv + br
__global__ __launch_bounds__(256)
void bvr_kernel(const float* __restrict__ wr, const float* __restrict__ bv,
                const float* __restrict__ br, float* __restrict__ bvr)
{
    int i = blockIdx.x * 256 + threadIdx.x;
    const float4* w4 = (const float4*)(wr + (size_t)i * CDIM);
    const float4* b4 = (const float4*)bv;
    float s = 0.f;
    #pragma unroll 8
    for (int k = 0; k < 256; k++) {
        float4 a = w4[k], b = b4[k];
        s += a.x * b.x + a.y * b.y + a.z * b.z + a.w * b.w;
    }
    bvr[i] = s + br[i];
}

// zero-fill half buffer (float4 units)
__global__ __launch_bounds__(256)
void zero_kernel(__half* __restrict__ p, int n4)
{
    int i = blockIdx.x * blockDim.x + threadIdx.x;
    float4 z = make_float4(0.f, 0.f, 0.f, 0.f);
    for (; i < n4; i += gridDim.x * blockDim.x) ((float4*)p)[i] = z;
}

// ============================================================
// LayerNorm: half output only
// ============================================================
__global__ __launch_bounds__(256)
void ln_kernel(const float* __restrict__ x, const float* __restrict__ w,
               const float* __restrict__ b, __half* __restrict__ outh)
{
    int row = blockIdx.x;
    int t = threadIdx.x;
    const float4* xr = (const float4*)(x + (size_t)row * CDIM);
    float4 v = xr[t];
    float s  = v.x + v.y + v.z + v.w;
    float sq = v.x*v.x + v.y*v.y + v.z*v.z + v.w*v.w;
    #pragma unroll
    for (int o = 16; o > 0; o >>= 1) {
        s  += __shfl_xor_sync(0xFFFFFFFFu, s,  o);
        sq += __shfl_xor_sync(0xFFFFFFFFu, sq, o);
    }
    __shared__ float red[2][8];
    int wid = t >> 5, lid = t & 31;
    if (lid == 0) { red[0][wid] = s; red[1][wid] = sq; }
    __syncthreads();
    float st = 0.f, sqt = 0.f;
    #pragma unroll
    for (int i = 0; i < 8; i++) { st += red[0][i]; sqt += red[1][i]; }
    float mu   = st * (1.0f / CDIM);
    float var  = sqt * (1.0f / CDIM) - mu * mu;
    float rstd = rsqrtf(var + 1e-5f);
    float4 wv = ((const float4*)w)[t];
    float4 bv = ((const float4*)b)[t];
    float4 o;
    o.x = (v.x - mu) * rstd * wv.x + bv.x;
    o.y = (v.y - mu) * rstd * wv.y + bv.y;
    o.z = (v.z - mu) * rstd * wv.z + bv.z;
    o.w = (v.w - mu) * rstd * wv.w + bv.w;
    __half2* hp = (__half2*)(outh + (size_t)row * CDIM + t * 4);
    hp[0] = __floats2half2_rn(o.x, o.y);
    hp[1] = __floats2half2_rn(o.z, o.w);
}

// ============================================================
// fp16 mma.sync GEMM: C[M,N] = A[M,1024] @ W[N,1024]^T (+bias)
// BM=128, BK=64, 3 stages, 256 thr. BN=256 (warps 2x4, tile 64x64)
// or BN=128 (warps 4x2, tile 32x64).
// MODE 1: C0 fp32 = gamma*(acc+bias0) + (float)residh   [BN=256]
// MODE 2: n<150 -> C0 fp32 sem(ldc 150) + H0 half(160); else H1 half kf(160)
// MODE 4: H0 half = acc (no bias), stride ldc            [Wc gemm]
// ============================================================
template<int MODE, int BN>
__global__ __launch_bounds__(256, 1)
void gemm_h(const __half* __restrict__ A, const __half* __restrict__ W,
            const float* __restrict__ bias0, const float* __restrict__ bias1,
            float* __restrict__ C0, __half* __restrict__ H0, __half* __restrict__ H1,
            int Nvalid, int ldc,
            const __half* __restrict__ residh, const float* __restrict__ gammap)
{
    constexpr int S = 3;
    constexpr int A_BYTES = 128 * 128;
    constexpr int B_BYTES = BN * 128;
    constexpr int STAGE = A_BYTES + B_BYTES;
    constexpr int NITER = CDIM / 64;
    constexpr int BLD = BN / 32;          // B load iters
    constexpr int MT  = (BN == 256) ? 4 : 2;

    extern __shared__ char smem_raw[];
    char* tiles = (char*)(((uintptr_t)smem_raw + 1023) & ~(uintptr_t)1023);
    const uint32_t base = smem_to_u32(tiles);

    const int tid = threadIdx.x;
    const int m0  = blockIdx.y * 128;
    const int n0  = blockIdx.x * BN;
    const int vrows = (Nvalid - n0 < BN) ? (Nvalid - n0) : BN;

    if (vrows < BN) {
        #pragma unroll
        for (int s = 0; s < S; s++) {
            float4* z = (float4*)(tiles + s * STAGE + A_BYTES + vrows * 128);
            int cnt = (BN - vrows) * 8;
            for (int i = tid; i < cnt; i += 256) z[i] = make_float4(0.f, 0.f, 0.f, 0.f);
        }
        __syncthreads();
    }

    auto load_stage = [&](int c) {
        int st = c % S;
        uint32_t as = base + st * STAGE;
        uint32_t bs = as + A_BYTES;
        const char* Ag = (const char*)A + (size_t)m0 * (CDIM * 2) + c * 128;
        const char* Wg = (const char*)W + (size_t)n0 * (CDIM * 2) + c * 128;
        #pragma unroll
        for (int i = 0; i < 4; i++) {
            int idx = tid + i * 256;
            int r = idx >> 3, u = idx & 7;
            CP_ASYNC16(as + r * 128 + ((u ^ (r & 7)) << 4),
                       Ag + (size_t)r * (CDIM * 2) + u * 16);
        }
        #pragma unroll
        for (int i = 0; i < BLD; i++) {
            int idx = tid + i * 256;
            int r = idx >> 3, u = idx & 7;
            if (r < vrows)
                CP_ASYNC16(bs + r * 128 + ((u ^ (r & 7)) << 4),
                           Wg + (size_t)r * (CDIM * 2) + u * 16);
        }
        CP_COMMIT();
    };

    load_stage(0);
    load_stage(1);

    float acc[MT][8][4];
    #pragma unroll
    for (int i = 0; i < MT; i++)
        #pragma unroll
        for (int j = 0; j < 8; j++)
            #pragma unroll
            for (int q = 0; q < 4; q++) acc[i][j][q] = 0.f;

    const int lane = tid & 31;
    const int wid  = tid >> 5;
    const int wm = (BN == 256) ? ((wid & 1) << 6) : ((wid & 3) << 5);
    const int wn = (BN == 256) ? ((wid >> 1) << 6) : ((wid >> 2) << 6);

    const int arow_l = wm + (lane & 15);
    const int au_l   = lane >> 4;
    const int brow_l = wn + (lane & 7) + ((lane >> 4) << 3);
    const int bu_l   = (lane >> 3) & 1;

    for (int it = 0; it < NITER; it++) {
        asm volatile("cp.async.wait_group 1;" ::: "memory");
        __syncthreads();
        if (it + 2 < NITER) load_stage(it + 2);

        uint32_t as = base + (it % S) * STAGE;
        uint32_t bs = as + A_BYTES;
        #pragma unroll
        for (int kk = 0; kk < 4; kk++) {
            uint32_t a[MT][4], b[4][4];
            #pragma unroll
            for (int mt = 0; mt < MT; mt++) {
                int row = arow_l + mt * 16;
                int u = kk * 2 + au_l;
                LDMATRIX_X4(a[mt][0], a[mt][1], a[mt][2], a[mt][3],
                            as + row * 128 + ((u ^ (row & 7)) << 4));
            }
            #pragma unroll
            for (int np = 0; np < 4; np++) {
                int row = brow_l + np * 16;
                int u = kk * 2 + bu_l;
                LDMATRIX_X4(b[np][0], b[np][1], b[np][2], b[np][3],
                            bs + row * 128 + ((u ^ (row & 7)) << 4));
            }
            #pragma unroll
            for (int mt = 0; mt < MT; mt++)
                #pragma unroll
                for (int nt = 0; nt < 8; nt++)
                    MMA16816(acc[mt][nt], a[mt],
                             b[nt >> 1][(nt & 1) * 2], b[nt >> 1][(nt & 1) * 2 + 1]);
        }
    }

    // ---- epilogue ----
    const int g = lane >> 2, tig = lane & 3;
    const float gm = (MODE == 1) ? gammap[0] : 0.f;
    #pragma unroll
    for (int mt = 0; mt < MT; mt++) {
        #pragma unroll
        for (int nt = 0; nt < 8; nt++) {
            int m = m0 + wm + mt * 16 + g;
            int n = n0 + wn + nt * 8 + tig * 2;
            if (MODE == 2) {
                if (n >= Nvalid) continue;
                #pragma unroll
                for (int h = 0; h < 2; h++) {
                    int mr = m + h * 8;
                    float v0, v1;
                    if (n < 150) {
                        v0 = acc[mt][nt][h*2+0] + bias0[n];
                        v1 = acc[mt][nt][h*2+1] + bias0[n + 1];
                        C0[(size_t)mr * 150 + n]     = v0;
                        C0[(size_t)mr * 150 + n + 1] = v1;
                        *(__half2*)(H0 + (size_t)mr * 160 + n) = __floats2half2_rn(v0, v1);
                    } else {
                        int nn = n - 150;
                        v0 = acc[mt][nt][h*2+0] + bias1[nn];
                        v1 = acc[mt][nt][h*2+1] + bias1[nn + 1];
                        *(__half2*)(H1 + (size_t)mr * 160 + nn) = __floats2half2_rn(v0, v1);
                    }
                }
            } else if (MODE == 4) {
                #pragma unroll
                for (int h = 0; h < 2; h++) {
                    int mr = m + h * 8;
                    *(__half2*)(H0 + (size_t)mr * ldc + n) =
                        __floats2half2_rn(acc[mt][nt][h*2+0], acc[mt][nt][h*2+1]);
                }
            } else { // MODE 1
                float b0 = bias0[n], b1 = bias0[n + 1];
                #pragma unroll
                for (int h = 0; h < 2; h++) {
                    int mr = m + h * 8;
                    float v0 = acc[mt][nt][h*2+0] + b0;
                    float v1 = acc[mt][nt][h*2+1] + b1;
                    __half2 rv = *(const __half2*)(residh + (size_t)mr * CDIM + n);
                    v0 = gm * v0 + __low2float(rv);
                    v1 = gm * v1 + __high2float(rv);
                    *(float2*)(C0 + (size_t)mr * ldc + n) = make_float2(v0, v1);
                }
            }
        }
    }
}

// ============================================================
// HMMA per-window attention: O = softmax(Q K^T) @ V, V = xnh.
// ============================================================
#define QK_STRB 336
#define SF_STR  66
#define SH_STRB 144
#define VC_STRB 272
#define ATTN_SMEM (43008 + 16896 + 9216)  // 69120

__global__ __launch_bounds__(128)
void attn_mma(const __half* __restrict__ semh, const __half* __restrict__ kfh,
              const __half* __restrict__ vh, __half* __restrict__ ao)
{
    extern __shared__ char sm[];
    char* Qc = sm;
    char* Kc = sm + 21504;
    float* Sf = (float*)(sm + 43008);
    char* Shc = sm + 59904;
    char* Vc  = sm;

    const uint32_t qb  = smem_to_u32(Qc);
    const uint32_t kb  = smem_to_u32(Kc);
    const uint32_t shb = smem_to_u32(Shc);
    const uint32_t vb  = smem_to_u32(Vc);

    int wi = blockIdx.x;
    int b  = wi >> 6;
    int wh = (wi >> 3) & 7;
    int ww = wi & 7;
    int base = b * BATCH_STRIDE + wh * 7 * 56 + ww * 7;
    int t = threadIdx.x;
    const int lane = t & 31, w = t >> 5;

    for (int i = t; i < 43008 / 16; i += 128)
        ((float4*)sm)[i] = make_float4(0.f, 0.f, 0.f, 0.f);
    __syncthreads();

    for (int idx = t; idx < 49 * 20; idx += 128) {
        int n = idx / 20, u = idx % 20;
        int r = base + (n / 7) * 56 + (n % 7);
        ((float4*)(Qc + n * QK_STRB))[u] = ((const float4*)(semh + (size_t)r * 160))[u];
        ((float4*)(Kc + n * QK_STRB))[u] = ((const float4*)(kfh  + (size_t)r * 160))[u];
    }
    __syncthreads();

    {
        float accS[8][4];
        #pragma unroll
        for (int j = 0; j < 8; j++)
            #pragma unroll
            for (int q = 0; q < 4; q++) accS[j][q] = 0.f;

        const int arow = 16 * w + (lane & 15);
        const int ak   = (lane >> 4) * 8;
        const int brow = (lane & 7) + ((lane >> 4) << 3);
        const int bk   = ((lane >> 3) & 1) * 8;

        #pragma unroll
        for (int ks = 0; ks < 10; ks++) {
            uint32_t a[4], bfr[4][4];
            LDMATRIX_X4(a[0], a[1], a[2], a[3],
                        qb + arow * QK_STRB + (ks * 16 + ak) * 2);
            #pragma unroll
            for (int np = 0; np < 4; np++)
                LDMATRIX_X4(bfr[np][0], bfr[np][1], bfr[np][2], bfr[np][3],
                            kb + (brow + np * 16) * QK_STRB + (ks * 16 + bk) * 2);
            #pragma unroll
            for (int nt = 0; nt < 8; nt++)
                MMA16816(accS[nt], a, bfr[nt >> 1][(nt & 1) * 2], bfr[nt >> 1][(nt & 1) * 2 + 1]);
        }
        const int g = lane >> 2, tig = lane & 3;
        #pragma unroll
        for (int nt = 0; nt < 8; nt++) {
            #pragma unroll
            for (int h = 0; h < 2; h++) {
                int row = 16 * w + g + h * 8;
                Sf[row * SF_STR + nt * 8 + tig * 2]     = accS[nt][h * 2 + 0];
                Sf[row * SF_STR + nt * 8 + tig * 2 + 1] = accS[nt][h * 2 + 1];
            }
        }
    }
    __syncthreads();

    if (t < 49) {
        float* row = Sf + t * SF_STR;
        float mx = -1e30f;
        #pragma unroll
        for (int m = 0; m < 49; m++) mx = fmaxf(mx, row[m]);
        float sum = 0.f;
        #pragma unroll
        for (int m = 0; m < 49; m++) { float e = __expf(row[m] - mx); row[m] = e; sum += e; }
        float inv = 1.f / sum;
        #pragma unroll
        for (int m = 0; m < 49; m++) row[m] *= inv;
    }
    __syncthreads();

    for (int idx = t; idx < 4096; idx += 128) {
        int i = idx >> 6, j = idx & 63;
        float v = (i < 49 && j < 49) ? Sf[i * SF_STR + j] : 0.f;
        *((__half*)(Shc + i * SH_STRB) + j) = __float2half_rn(v);
    }

    const int arow = lane & 15;
    const int ak   = (lane >> 4) * 8;
    const int kk_l = (lane & 7) + ((lane >> 3) & 1) * 8;
    const int nc_l = 32 * w + ((lane >> 4) << 3);
    const int g = lane >> 2, tig = lane & 3;

    for (int cc = 0; cc < 8; cc++) {
        __syncthreads();
        for (int idx = t; idx < 49 * 16; idx += 128) {
            int m = idx >> 4, u = idx & 15;
            int r = base + (m / 7) * 56 + (m % 7);
            ((float4*)(Vc + m * VC_STRB))[u] =
                ((const float4*)(vh + (size_t)r * CDIM + cc * 128))[u];
        }
        __syncthreads();

        float acc[4][4][4];
        #pragma unroll
        for (int i = 0; i < 4; i++)
            #pragma unroll
            for (int j = 0; j < 4; j++)
                #pragma unroll
                for (int q = 0; q < 4; q++) acc[i][j][q] = 0.f;

        #pragma unroll
        for (int ks = 0; ks < 4; ks++) {
            uint32_t a[4][4], bq[2][4];
            #pragma unroll
            for (int mt = 0; mt < 4; mt++)
                LDMATRIX_X4(a[mt][0], a[mt][1], a[mt][2], a[mt][3],
                            shb + (16 * mt + arow) * SH_STRB + (ks * 16 + ak) * 2);
            #pragma unroll
            for (int nb = 0; nb < 2; nb++)
                LDMATRIX_X4_T(bq[nb][0], bq[nb][1], bq[nb][2], bq[nb][3],
                              vb + (ks * 16 + kk_l) * VC_STRB + (nc_l + nb * 16) * 2);
            #pragma unroll
            for (int mt = 0; mt < 4; mt++)
                #pragma unroll
                for (int nt = 0; nt < 4; nt++)
                    MMA16816(acc[mt][nt], a[mt],
                             bq[nt >> 1][(nt & 1) * 2], bq[nt >> 1][(nt & 1) * 2 + 1]);
        }

        #pragma unroll
        for (int mt = 0; mt < 4; mt++) {
            #pragma unroll
            for (int h = 0; h < 2; h++) {
                int m = 16 * mt + g + h * 8;
                if (m < 49) {
                    int r = base + (m / 7) * 56 + (m % 7);
                    __half* dst = ao + (size_t)r * CDIM + cc * 128;
                    #pragma unroll
                    for (int nt = 0; nt < 4; nt++) {
                        int n = 32 * w + nt * 8 + tig * 2;
                        *(__half2*)(dst + n) =
                            __floats2half2_rn(acc[mt][nt][h*2+0], acc[mt][nt][h*2+1]);
                    }
                }
            }
        }
    }
}

// ============================================================
// Host launcher
// ============================================================
extern "C" void kernel_launch(void* const* d_in, const int* in_sizes, int n_in,
                              void* d_out, int out_size)
{
    const float* x      = (const float*)d_in[0];
    const float* norm_w = (const float*)d_in[1];
    const float* norm_b = (const float*)d_in[2];
    const float* wq     = (const float*)d_in[3];
    const float* bq     = (const float*)d_in[4];
    const float* wk     = (const float*)d_in[5];
    const float* bk     = (const float*)d_in[6];
    const float* wv     = (const float*)d_in[7];
    const float* bv     = (const float*)d_in[8];
    const float* wr     = (const float*)d_in[9];
    const float* br     = (const float*)d_in[10];
    const float* gamma  = (const float*)d_in[11];
    (void)in_sizes; (void)n_in; (void)out_size;

    float* out  = (float*)d_out;
    float* sem  = out;                              // [50176, 150]
    float* xout = out + (size_t)M_ROWS * KSEM;      // [50176, 1024]

    __half *xnh, *semh, *kfh, *aoh, *wqkh, *wrh, *wvth, *wch;
    float* bvr;
    cudaGetSymbolAddress((void**)&xnh,  g_xnh);
    cudaGetSymbolAddress((void**)&semh, g_semh);
    cudaGetSymbolAddress((void**)&kfh,  g_kfh);
    cudaGetSymbolAddress((void**)&aoh,  g_aoh);
    cudaGetSymbolAddress((void**)&wqkh, g_wqkh);
    cudaGetSymbolAddress((void**)&wrh,  g_wrh);
    cudaGetSymbolAddress((void**)&wvth, g_wvth);
    cudaGetSymbolAddress((void**)&wch,  g_wch);
    cudaGetSymbolAddress((void**)&bvr,  g_bvr);

    const int SMEM256 = 3 * 49152 + 1024;  // 148480
    const int SMEM128 = 3 * 32768 + 1024;  // 99328
    cudaFuncSetAttribute(gemm_h<1, 256>, cudaFuncAttributeMaxDynamicSharedMemorySize, SMEM256);
    cudaFuncSetAttribute(gemm_h<2, 128>, cudaFuncAttributeMaxDynamicSharedMemorySize, SMEM128);
    cudaFuncSetAttribute(gemm_h<4, 128>, cudaFuncAttributeMaxDynamicSharedMemorySize, SMEM128);
    cudaFuncSetAttribute(attn_mma, cudaFuncAttributeMaxDynamicSharedMemorySize, ATTN_SMEM);

    // 0) weight prep
    f2h_kernel<<<(KSEM * CDIM + 1023) / 1024, 256>>>(wq, wqkh, KSEM * CDIM);
    f2h_kernel<<<(KSEM * CDIM + 1023) / 1024, 256>>>(wk, wqkh + (size_t)KSEM * CDIM, KSEM * CDIM);
    f2h_kernel<<<(CDIM * CDIM + 1023) / 1024, 256>>>(wr, wrh, CDIM * CDIM);
    t_f2h_kernel<<<dim3(32, 32), dim3(32, 8)>>>(wv, wvth);
    bvr_kernel<<<4, 256>>>(wr, bv, br, bvr);
    zero_kernel<<<512, 256>>>(semh, M_ROWS * 160 / 8);
    zero_kernel<<<512, 256>>>(kfh,  M_ROWS * 160 / 8);

    // Wc = Wr @ Wv (half), via C = Wr @ (Wv^T)^T
    gemm_h<4, 128><<<dim3(8, 8), 256, SMEM128>>>(wrh, wvth, nullptr, nullptr,
                                                 nullptr, wch, nullptr, CDIM, CDIM, nullptr, nullptr);

    // 1) LayerNorm -> half
    ln_kernel<<<M_ROWS, 256>>>(x, norm_w, norm_b, xnh);

    // 2) merged Q/K projection (N=300): sem fp32 + semh/kfh half
    gemm_h<2, 128><<<dim3(3, M_ROWS / 128), 256, SMEM128>>>(xnh, wqkh, bq, bk, sem, semh, kfh,
                                                            300, KSEM, nullptr, nullptr);

    // 3) attention directly on xn: aoh = softmax(QK^T) @ xnh
    attn_mma<<<NWIN, 128, ATTN_SMEM>>>(semh, kfh, xnh, aoh);

    // 4) xout = gamma*(aoh @ Wc^T + bvr) + xnh
    gemm_h<1, 256><<<dim3(4, M_ROWS / 128), 256, SMEM256>>>(aoh, wch, bvr, nullptr, xout,
                                                            nullptr, nullptr, CDIM, CDIM, xnh, gamma);
}

// round 8
// speedup vs baseline: 10.1632x; 1.1197x over previous
#include <cuda_runtime.h>
#include <cuda_fp16.h>
#include <cstdint>
#include <cstddef>

// Problem constants (B=16, H=W=56, C=1024, K=150, WS=7)
#define M_ROWS 50176
#define CDIM   1024
#define KSEM   150
#define NWIN   1024
#define BATCH_STRIDE 3136

// -------- scratch (device globals) --------
__device__ __half g_xnh [(size_t)M_ROWS * CDIM];   // LN out half
__device__ __half g_semh[(size_t)M_ROWS * 160];    // seg_map half, padded stride
__device__ __half g_kfh [(size_t)M_ROWS * 160];    // seg_ft half, padded stride
__device__ __half g_aoh [(size_t)M_ROWS * CDIM];   // attention out half
__device__ __half g_wqkh[(size_t)300 * CDIM];      // wq(150) + wk(150) stacked
__device__ __half g_wrh [(size_t)CDIM * CDIM];     // wr half
__device__ __half g_wvth[(size_t)CDIM * CDIM];     // wv^T half
__device__ __half g_wch [(size_t)CDIM * CDIM];     // Wc = gamma * Wr @ Wv, half
__device__ float  g_bvr [CDIM];                    // gamma * (Wr @ bv + br)

__device__ __forceinline__ uint32_t smem_to_u32(const void* p) {
    uint32_t a;
    asm("{ .reg .u64 t; cvta.to.shared.u64 t, %1; cvt.u32.u64 %0, t; }" : "=r"(a) : "l"(p));
    return a;
}
#define CP_ASYNC16(dst, src) \
    asm volatile("cp.async.cg.shared.global [%0], [%1], 16;" :: "r"(dst), "l"(src) : "memory")
#define CP_COMMIT() asm volatile("cp.async.commit_group;" ::: "memory")
#define LDMATRIX_X4(r0, r1, r2, r3, addr) \
    asm volatile("ldmatrix.sync.aligned.m8n8.x4.shared.b16 {%0,%1,%2,%3}, [%4];" \
        : "=r"(r0), "=r"(r1), "=r"(r2), "=r"(r3) : "r"(addr))
#define LDMATRIX_X4_T(r0, r1, r2, r3, addr) \
    asm volatile("ldmatrix.sync.aligned.m8n8.x4.trans.shared.b16 {%0,%1,%2,%3}, [%4];" \
        : "=r"(r0), "=r"(r1), "=r"(r2), "=r"(r3) : "r"(addr))
#define MMA16816(acc, a, b0, b1) \
    asm volatile("mma.sync.aligned.m16n8k16.row.col.f32.f16.f16.f32 " \
        "{%0,%1,%2,%3}, {%4,%5,%6,%7}, {%8,%9}, {%0,%1,%2,%3};" \
        : "+f"((acc)[0]), "+f"((acc)[1]), "+f"((acc)[2]), "+f"((acc)[3]) \
        : "r"((a)[0]), "r"((a)[1]), "r"((a)[2]), "r"((a)[3]), "r"(b0), "r"(b1))

// ============================================================
// fp32 -> fp16 (RN)
// ============================================================
__global__ __launch_bounds__(256)
void f2h_kernel(const float* __restrict__ in, __half* __restrict__ out, int n)
{
    int i = blockIdx.x * 1024 + threadIdx.x * 4;
    if (i + 3 < n) {
        float4 v = *(const float4*)(in + i);
        *(__half2*)(out + i)     = __floats2half2_rn(v.x, v.y);
        *(__half2*)(out + i + 2) = __floats2half2_rn(v.z, v.w);
    } else {
        for (int k = 0; k < 4 && i + k < n; k++) out[i + k] = __float2half_rn(in[i + k]);
    }
}

// transpose 1024x1024 fp32 -> fp16
__global__ __launch_bounds__(256)
void t_f2h_kernel(const float* __restrict__ in, __half* __restrict__ out)
{
    __shared__ float tile[32][33];
    int x = blockIdx.x * 32 + threadIdx.x;
    int y0 = blockIdx.y * 32 + threadIdx.y;
    #pragma unroll
    for (int i = 0; i < 32; i += 8)
        tile[threadIdx.y + i][threadIdx.x] = in[(size_t)(y0 + i) * CDIM + x];
    __syncthreads();
    int x2 = blockIdx.y * 32 + threadIdx.x;
    int y2 = blockIdx.x * 32 + threadIdx.y;
    #pragma unroll
    for (int i = 0; i < 32; i += 8)
        out[(size_t)(y2 + i) * CDIM + x2] = __float2half_rn(tile[threadIdx.x][threadIdx.y + i]);
}

// bvr = gamma * (Wr @ bv + br)
__global__ __launch_bounds__(256)
void bvr_kernel(const float* __restrict__ wr, const float* __restrict__ bv,
                const float* __restrict__ br, const float* __restrict__ gammap,
                float* __restrict__ bvr)
{
    int i = blockIdx.x * 256 + threadIdx.x;
    const float4* w4 = (const float4*)(wr + (size_t)i * CDIM);
    const float4* b4 = (const float4*)bv;
    float s = 0.f;
    #pragma unroll 8
    for (int k = 0; k < 256; k++) {
        float4 a = w4[k], b = b4[k];
        s += a.x * b.x + a.y * b.y + a.z * b.z + a.w * b.w;
    }
    bvr[i] = gammap[0] * (s + br[i]);
}

// zero pad columns 150..159 of semh/kfh
__global__ __launch_bounds__(256)
void zero_pad_kernel(__half* __restrict__ a, __half* __restrict__ b)
{
    int r = blockIdx.x * 256 + threadIdx.x;
    if (r >= M_ROWS) return;
    __half2 z = __floats2half2_rn(0.f, 0.f);
    __half2* pa = (__half2*)(a + (size_t)r * 160 + 150);
    __half2* pb = (__half2*)(b + (size_t)r * 160 + 150);
    #pragma unroll
    for (int i = 0; i < 5; i++) { pa[i] = z; pb[i] = z; }
}

// ============================================================
// LayerNorm: half output
// ============================================================
__global__ __launch_bounds__(256)
void ln_kernel(const float* __restrict__ x, const float* __restrict__ w,
               const float* __restrict__ b, __half* __restrict__ outh)
{
    int row = blockIdx.x;
    int t = threadIdx.x;
    const float4* xr = (const float4*)(x + (size_t)row * CDIM);
    float4 v = xr[t];
    float s  = v.x + v.y + v.z + v.w;
    float sq = v.x*v.x + v.y*v.y + v.z*v.z + v.w*v.w;
    #pragma unroll
    for (int o = 16; o > 0; o >>= 1) {
        s  += __shfl_xor_sync(0xFFFFFFFFu, s,  o);
        sq += __shfl_xor_sync(0xFFFFFFFFu, sq, o);
    }
    __shared__ float red[2][8];
    int wid = t >> 5, lid = t & 31;
    if (lid == 0) { red[0][wid] = s; red[1][wid] = sq; }
    __syncthreads();
    float st = 0.f, sqt = 0.f;
    #pragma unroll
    for (int i = 0; i < 8; i++) { st += red[0][i]; sqt += red[1][i]; }
    float mu   = st * (1.0f / CDIM);
    float var  = sqt * (1.0f / CDIM) - mu * mu;
    float rstd = rsqrtf(var + 1e-5f);
    float4 wv = ((const float4*)w)[t];
    float4 bv = ((const float4*)b)[t];
    float4 o;
    o.x = (v.x - mu) * rstd * wv.x + bv.x;
    o.y = (v.y - mu) * rstd * wv.y + bv.y;
    o.z = (v.z - mu) * rstd * wv.z + bv.z;
    o.w = (v.w - mu) * rstd * wv.w + bv.w;
    __half2* hp = (__half2*)(outh + (size_t)row * CDIM + t * 4);
    hp[0] = __floats2half2_rn(o.x, o.y);
    hp[1] = __floats2half2_rn(o.z, o.w);
}

// ============================================================
// fp16 mma.sync GEMM (BM=128, BK=64, 3 stages, 256 thr)
// MODE 1: C0 fp32 = acc + bias0 + (float)residh          [BN=256]
// MODE 2: n<150 -> C0 fp32 sem(150) + H0 half(160); else H1 half kf(160)
// MODE 4: H0 half = gamma * acc (no bias), stride ldc    [Wc gemm]
// ============================================================
template<int MODE, int BN>
__global__ __launch_bounds__(256, 1)
void gemm_h(const __half* __restrict__ A, const __half* __restrict__ W,
            const float* __restrict__ bias0, const float* __restrict__ bias1,
            float* __restrict__ C0, __half* __restrict__ H0, __half* __restrict__ H1,
            int Nvalid, int ldc,
            const __half* __restrict__ residh, const float* __restrict__ gammap)
{
    constexpr int S = 3;
    constexpr int A_BYTES = 128 * 128;
    constexpr int B_BYTES = BN * 128;
    constexpr int STAGE = A_BYTES + B_BYTES;
    constexpr int NITER = CDIM / 64;
    constexpr int BLD = BN / 32;
    constexpr int MT  = (BN == 256) ? 4 : 2;

    extern __shared__ char smem_raw[];
    char* tiles = (char*)(((uintptr_t)smem_raw + 1023) & ~(uintptr_t)1023);
    const uint32_t base = smem_to_u32(tiles);

    const int tid = threadIdx.x;
    const int m0  = blockIdx.y * 128;
    const int n0  = blockIdx.x * BN;
    const int vrows = (Nvalid - n0 < BN) ? (Nvalid - n0) : BN;

    if (vrows < BN) {
        #pragma unroll
        for (int s = 0; s < S; s++) {
            float4* z = (float4*)(tiles + s * STAGE + A_BYTES + vrows * 128);
            int cnt = (BN - vrows) * 8;
            for (int i = tid; i < cnt; i += 256) z[i] = make_float4(0.f, 0.f, 0.f, 0.f);
        }
        __syncthreads();
    }

    auto load_stage = [&](int c) {
        int st = c % S;
        uint32_t as = base + st * STAGE;
        uint32_t bs = as + A_BYTES;
        const char* Ag = (const char*)A + (size_t)m0 * (CDIM * 2) + c * 128;
        const char* Wg = (const char*)W + (size_t)n0 * (CDIM * 2) + c * 128;
        #pragma unroll
        for (int i = 0; i < 4; i++) {
            int idx = tid + i * 256;
            int r = idx >> 3, u = idx & 7;
            CP_ASYNC16(as + r * 128 + ((u ^ (r & 7)) << 4),
                       Ag + (size_t)r * (CDIM * 2) + u * 16);
        }
        #pragma unroll
        for (int i = 0; i < BLD; i++) {
            int idx = tid + i * 256;
            int r = idx >> 3, u = idx & 7;
            if (r < vrows)
                CP_ASYNC16(bs + r * 128 + ((u ^ (r & 7)) << 4),
                           Wg + (size_t)r * (CDIM * 2) + u * 16);
        }
        CP_COMMIT();
    };

    load_stage(0);
    load_stage(1);

    float acc[MT][8][4];
    #pragma unroll
    for (int i = 0; i < MT; i++)
        #pragma unroll
        for (int j = 0; j < 8; j++)
            #pragma unroll
            for (int q = 0; q < 4; q++) acc[i][j][q] = 0.f;

    const int lane = tid & 31;
    const int wid  = tid >> 5;
    const int wm = (BN == 256) ? ((wid & 1) << 6) : ((wid & 3) << 5);
    const int wn = (BN == 256) ? ((wid >> 1) << 6) : ((wid >> 2) << 6);

    const int arow_l = wm + (lane & 15);
    const int au_l   = lane >> 4;
    const int brow_l = wn + (lane & 7) + ((lane >> 4) << 3);
    const int bu_l   = (lane >> 3) & 1;

    for (int it = 0; it < NITER; it++) {
        asm volatile("cp.async.wait_group 1;" ::: "memory");
        __syncthreads();
        if (it + 2 < NITER) load_stage(it + 2);

        uint32_t as = base + (it % S) * STAGE;
        uint32_t bs = as + A_BYTES;
        #pragma unroll
        for (int kk = 0; kk < 4; kk++) {
            uint32_t a[MT][4], b[4][4];
            #pragma unroll
            for (int mt = 0; mt < MT; mt++) {
                int row = arow_l + mt * 16;
                int u = kk * 2 + au_l;
                LDMATRIX_X4(a[mt][0], a[mt][1], a[mt][2], a[mt][3],
                            as + row * 128 + ((u ^ (row & 7)) << 4));
            }
            #pragma unroll
            for (int np = 0; np < 4; np++) {
                int row = brow_l + np * 16;
                int u = kk * 2 + bu_l;
                LDMATRIX_X4(b[np][0], b[np][1], b[np][2], b[np][3],
                            bs + row * 128 + ((u ^ (row & 7)) << 4));
            }
            #pragma unroll
            for (int mt = 0; mt < MT; mt++)
                #pragma unroll
                for (int nt = 0; nt < 8; nt++)
                    MMA16816(acc[mt][nt], a[mt],
                             b[nt >> 1][(nt & 1) * 2], b[nt >> 1][(nt & 1) * 2 + 1]);
        }
    }

    // ---- epilogue ----
    const int g = lane >> 2, tig = lane & 3;
    #pragma unroll
    for (int mt = 0; mt < MT; mt++) {
        #pragma unroll
        for (int nt = 0; nt < 8; nt++) {
            int m = m0 + wm + mt * 16 + g;
            int n = n0 + wn + nt * 8 + tig * 2;
            if (MODE == 2) {
                if (n >= Nvalid) continue;
                #pragma unroll
                for (int h = 0; h < 2; h++) {
                    int mr = m + h * 8;
                    float v0, v1;
                    if (n < 150) {
                        v0 = acc[mt][nt][h*2+0] + bias0[n];
                        v1 = acc[mt][nt][h*2+1] + bias0[n + 1];
                        C0[(size_t)mr * 150 + n]     = v0;
                        C0[(size_t)mr * 150 + n + 1] = v1;
                        *(__half2*)(H0 + (size_t)mr * 160 + n) = __floats2half2_rn(v0, v1);
                    } else {
                        int nn = n - 150;
                        v0 = acc[mt][nt][h*2+0] + bias1[nn];
                        v1 = acc[mt][nt][h*2+1] + bias1[nn + 1];
                        *(__half2*)(H1 + (size_t)mr * 160 + nn) = __floats2half2_rn(v0, v1);
                    }
                }
            } else if (MODE == 4) {
                float gm = gammap[0];
                #pragma unroll
                for (int h = 0; h < 2; h++) {
                    int mr = m + h * 8;
                    *(__half2*)(H0 + (size_t)mr * ldc + n) =
                        __floats2half2_rn(gm * acc[mt][nt][h*2+0], gm * acc[mt][nt][h*2+1]);
                }
            } else { // MODE 1
                float b0 = bias0[n], b1 = bias0[n + 1];
                #pragma unroll
                for (int h = 0; h < 2; h++) {
                    int mr = m + h * 8;
                    __half2 rv = *(const __half2*)(residh + (size_t)mr * CDIM + n);
                    float v0 = acc[mt][nt][h*2+0] + b0 + __low2float(rv);
                    float v1 = acc[mt][nt][h*2+1] + b1 + __high2float(rv);
                    *(float2*)(C0 + (size_t)mr * ldc + n) = make_float2(v0, v1);
                }
            }
        }
    }
}

// ============================================================
// HMMA per-window attention, cp.async double-buffered V.
// smem: Qc 64x336, Kc 64x336, Sf 64x66 f32, Sh 64x144B,
//       V double buffer 2 x 64x272 (rows 49..63 zeroed once).
// ============================================================
#define QK_STRB 336
#define SF_STR  66
#define SH_STRB 144
#define VC_STRB 272
#define V_OFF   69120
#define V_BUFB  17408
#define ATTN_SMEM (69120 + 2 * 17408)  // 103936

__global__ __launch_bounds__(128)
void attn_mma(const __half* __restrict__ semh, const __half* __restrict__ kfh,
              const __half* __restrict__ vh, __half* __restrict__ ao)
{
    extern __shared__ char sm[];
    char* Qc = sm;
    char* Kc = sm + 21504;
    float* Sf = (float*)(sm + 43008);
    char* Shc = sm + 59904;
    char* Vb0 = sm + V_OFF;

    const uint32_t qb  = smem_to_u32(Qc);
    const uint32_t kb  = smem_to_u32(Kc);
    const uint32_t shb = smem_to_u32(Shc);
    const uint32_t vbb = smem_to_u32(Vb0);

    int wi = blockIdx.x;
    int b  = wi >> 6;
    int wh = (wi >> 3) & 7;
    int ww = wi & 7;
    int base = b * BATCH_STRIDE + wh * 7 * 56 + ww * 7;
    int t = threadIdx.x;
    const int lane = t & 31, w = t >> 5;

    // zero pad rows 49..63 of Qc/Kc (Phase A reads them)
    for (int i = t; i < 630; i += 128) {
        char* buf = (i < 315) ? Qc : Kc;
        int idx = (i < 315) ? i : i - 315;
        int row = 49 + idx / 21, u = idx % 21;
        ((float4*)(buf + row * QK_STRB))[u] = make_float4(0.f, 0.f, 0.f, 0.f);
    }
    // zero pad rows 49..63 of BOTH V buffers (Phase B trans-ldmatrix reads
    // all 64 k-rows; S cols >=49 are zero but 0 * NaN-garbage = NaN).
    for (int i = t; i < 2 * 15 * 17; i += 128) {
        int bsel = i >= 255;
        int idx = i - bsel * 255;
        int row = 49 + idx / 17, u = idx % 17;
        ((float4*)(Vb0 + bsel * V_BUFB + row * VC_STRB))[u] = make_float4(0.f, 0.f, 0.f, 0.f);
    }

    // cp.async gather Q,K rows (group 0)
    for (int idx = t; idx < 1960; idx += 128) {
        int which = idx >= 980;
        int i2 = idx - which * 980;
        int n = i2 / 20, u = i2 % 20;
        int r = base + (n / 7) * 56 + (n % 7);
        uint32_t dst = (which ? kb : qb) + n * QK_STRB + u * 16;
        const char* src = (const char*)(which ? kfh : semh) + (size_t)r * 320 + u * 16;
        CP_ASYNC16(dst, src);
    }
    CP_COMMIT();

    // prefetch V chunk 0 (group 1)
    for (int idx = t; idx < 49 * 16; idx += 128) {
        int m = idx >> 4, u = idx & 15;
        int r = base + (m / 7) * 56 + (m % 7);
        CP_ASYNC16(vbb + m * VC_STRB + u * 16,
                   (const char*)vh + (size_t)r * 2048 + u * 16);
    }
    CP_COMMIT();

    asm volatile("cp.async.wait_group 1;" ::: "memory");  // QK ready, V0 in flight
    __syncthreads();

    // ---- Phase A: S = Q K^T
    {
        float accS[8][4];
        #pragma unroll
        for (int j = 0; j < 8; j++)
            #pragma unroll
            for (int q = 0; q < 4; q++) accS[j][q] = 0.f;

        const int arow = 16 * w + (lane & 15);
        const int ak   = (lane >> 4) * 8;
        const int brow = (lane & 7) + ((lane >> 4) << 3);
        const int bk   = ((lane >> 3) & 1) * 8;

        #pragma unroll
        for (int ks = 0; ks < 10; ks++) {
            uint32_t a[4], bfr[4][4];
            LDMATRIX_X4(a[0], a[1], a[2], a[3],
                        qb + arow * QK_STRB + (ks * 16 + ak) * 2);
            #pragma unroll
            for (int np = 0; np < 4; np++)
                LDMATRIX_X4(bfr[np][0], bfr[np][1], bfr[np][2], bfr[np][3],
                            kb + (brow + np * 16) * QK_STRB + (ks * 16 + bk) * 2);
            #pragma unroll
            for (int nt = 0; nt < 8; nt++)
                MMA16816(accS[nt], a, bfr[nt >> 1][(nt & 1) * 2], bfr[nt >> 1][(nt & 1) * 2 + 1]);
        }
        const int g = lane >> 2, tig = lane & 3;
        #pragma unroll
        for (int nt = 0; nt < 8; nt++) {
            #pragma unroll
            for (int h = 0; h < 2; h++) {
                int row = 16 * w + g + h * 8;
                Sf[row * SF_STR + nt * 8 + tig * 2]     = accS[nt][h * 2 + 0];
                Sf[row * SF_STR + nt * 8 + tig * 2 + 1] = accS[nt][h * 2 + 1];
            }
        }
    }
    __syncthreads();

    // ---- softmax
    if (t < 49) {
        float* row = Sf + t * SF_STR;
        float mx = -1e30f;
        #pragma unroll
        for (int m = 0; m < 49; m++) mx = fmaxf(mx, row[m]);
        float sum = 0.f;
        #pragma unroll
        for (int m = 0; m < 49; m++) { float e = __expf(row[m] - mx); row[m] = e; sum += e; }
        float inv = 1.f / sum;
        #pragma unroll
        for (int m = 0; m < 49; m++) row[m] *= inv;
    }
    __syncthreads();

    // ---- S -> half (zeros outside 49x49), half2 writes
    for (int idx = t; idx < 2048; idx += 128) {
        int i = idx >> 5, j2 = (idx & 31) * 2;
        float v0 = (i < 49 && j2     < 49) ? Sf[i * SF_STR + j2]     : 0.f;
        float v1 = (i < 49 && j2 + 1 < 49) ? Sf[i * SF_STR + j2 + 1] : 0.f;
        *(__half2*)(Shc + i * SH_STRB + j2 * 2) = __floats2half2_rn(v0, v1);
    }

    // ---- Phase B: O = S V, double-buffered chunks
    const int arow = lane & 15;
    const int ak   = (lane >> 4) * 8;
    const int kk_l = (lane & 7) + ((lane >> 3) & 1) * 8;
    const int nc_l = 32 * w + ((lane >> 4) << 3);
    const int g = lane >> 2, tig = lane & 3;

    for (int cc = 0; cc < 8; cc++) {
        if (cc + 1 < 8) {
            uint32_t nb = vbb + ((cc + 1) & 1) * V_BUFB;
            for (int idx = t; idx < 49 * 16; idx += 128) {
                int m = idx >> 4, u = idx & 15;
                int r = base + (m / 7) * 56 + (m % 7);
                CP_ASYNC16(nb + m * VC_STRB + u * 16,
                           (const char*)vh + (size_t)r * 2048 + (cc + 1) * 256 + u * 16);
            }
            CP_COMMIT();
            asm volatile("cp.async.wait_group 1;" ::: "memory");
        } else {
            asm volatile("cp.async.wait_group 0;" ::: "memory");
        }
        __syncthreads();

        const uint32_t vb = vbb + (cc & 1) * V_BUFB;
        float acc[4][4][4];
        #pragma unroll
        for (int i = 0; i < 4; i++)
            #pragma unroll
            for (int j = 0; j < 4; j++)
                #pragma unroll
                for (int q = 0; q < 4; q++) acc[i][j][q] = 0.f;

        #pragma unroll
        for (int ks = 0; ks < 4; ks++) {
            uint32_t a[4][4], bq[2][4];
            #pragma unroll
            for (int mt = 0; mt < 4; mt++)
                LDMATRIX_X4(a[mt][0], a[mt][1], a[mt][2], a[mt][3],
                            shb + (16 * mt + arow) * SH_STRB + (ks * 16 + ak) * 2);
            #pragma unroll
            for (int nb2 = 0; nb2 < 2; nb2++)
                LDMATRIX_X4_T(bq[nb2][0], bq[nb2][1], bq[nb2][2], bq[nb2][3],
                              vb + (ks * 16 + kk_l) * VC_STRB + (nc_l + nb2 * 16) * 2);
            #pragma unroll
            for (int mt = 0; mt < 4; mt++)
                #pragma unroll
                for (int nt = 0; nt < 4; nt++)
                    MMA16816(acc[mt][nt], a[mt],
                             bq[nt >> 1][(nt & 1) * 2], bq[nt >> 1][(nt & 1) * 2 + 1]);
        }

        #pragma unroll
        for (int mt = 0; mt < 4; mt++) {
            #pragma unroll
            for (int h = 0; h < 2; h++) {
                int m = 16 * mt + g + h * 8;
                if (m < 49) {
                    int r = base + (m / 7) * 56 + (m % 7);
                    __half* dst = ao + (size_t)r * CDIM + cc * 128;
                    #pragma unroll
                    for (int nt = 0; nt < 4; nt++) {
                        int n = 32 * w + nt * 8 + tig * 2;
                        *(__half2*)(dst + n) =
                            __floats2half2_rn(acc[mt][nt][h*2+0], acc[mt][nt][h*2+1]);
                    }
                }
            }
        }
        __syncthreads();  // protect V buffer reuse
    }
}

// ============================================================
// Host launcher
// ============================================================
extern "C" void kernel_launch(void* const* d_in, const int* in_sizes, int n_in,
                              void* d_out, int out_size)
{
    const float* x      = (const float*)d_in[0];
    const float* norm_w = (const float*)d_in[1];
    const float* norm_b = (const float*)d_in[2];
    const float* wq     = (const float*)d_in[3];
    const float* bq     = (const float*)d_in[4];
    const float* wk     = (const float*)d_in[5];
    const float* bk     = (const float*)d_in[6];
    const float* wv     = (const float*)d_in[7];
    const float* bv     = (const float*)d_in[8];
    const float* wr     = (const float*)d_in[9];
    const float* br     = (const float*)d_in[10];
    const float* gamma  = (const float*)d_in[11];
    (void)in_sizes; (void)n_in; (void)out_size;

    float* out  = (float*)d_out;
    float* sem  = out;                              // [50176, 150]
    float* xout = out + (size_t)M_ROWS * KSEM;      // [50176, 1024]

    __half *xnh, *semh, *kfh, *aoh, *wqkh, *wrh, *wvth, *wch;
    float* bvr;
    cudaGetSymbolAddress((void**)&xnh,  g_xnh);
    cudaGetSymbolAddress((void**)&semh, g_semh);
    cudaGetSymbolAddress((void**)&kfh,  g_kfh);
    cudaGetSymbolAddress((void**)&aoh,  g_aoh);
    cudaGetSymbolAddress((void**)&wqkh, g_wqkh);
    cudaGetSymbolAddress((void**)&wrh,  g_wrh);
    cudaGetSymbolAddress((void**)&wvth, g_wvth);
    cudaGetSymbolAddress((void**)&wch,  g_wch);
    cudaGetSymbolAddress((void**)&bvr,  g_bvr);

    const int SMEM256 = 3 * 49152 + 1024;  // 148480
    const int SMEM128 = 3 * 32768 + 1024;  // 99328
    cudaFuncSetAttribute(gemm_h<1, 256>, cudaFuncAttributeMaxDynamicSharedMemorySize, SMEM256);
    cudaFuncSetAttribute(gemm_h<2, 128>, cudaFuncAttributeMaxDynamicSharedMemorySize, SMEM128);
    cudaFuncSetAttribute(gemm_h<4, 128>, cudaFuncAttributeMaxDynamicSharedMemorySize, SMEM128);
    cudaFuncSetAttribute(attn_mma, cudaFuncAttributeMaxDynamicSharedMemorySize, ATTN_SMEM);

    // 0) weight prep
    f2h_kernel<<<(KSEM * CDIM + 1023) / 1024, 256>>>(wq, wqkh, KSEM * CDIM);
    f2h_kernel<<<(KSEM * CDIM + 1023) / 1024, 256>>>(wk, wqkh + (size_t)KSEM * CDIM, KSEM * CDIM);
    f2h_kernel<<<(CDIM * CDIM + 1023) / 1024, 256>>>(wr, wrh, CDIM * CDIM);
    t_f2h_kernel<<<dim3(32, 32), dim3(32, 8)>>>(wv, wvth);
    bvr_kernel<<<4, 256>>>(wr, bv, br, gamma, bvr);
    zero_pad_kernel<<<(M_ROWS + 255) / 256, 256>>>(semh, kfh);

    // Wc = gamma * Wr @ Wv (half)
    gemm_h<4, 128><<<dim3(8, 8), 256, SMEM128>>>(wrh, wvth, nullptr, nullptr,
                                                 nullptr, wch, nullptr, CDIM, CDIM, nullptr, gamma);

    // 1) LayerNorm -> half
    ln_kernel<<<M_ROWS, 256>>>(x, norm_w, norm_b, xnh);

    // 2) merged Q/K projection (N=300)
    gemm_h<2, 128><<<dim3(3, M_ROWS / 128), 256, SMEM128>>>(xnh, wqkh, bq, bk, sem, semh, kfh,
                                                            300, KSEM, nullptr, nullptr);

    // 3) attention: aoh = softmax(QK^T) @ xnh
    attn_mma<<<NWIN, 128, ATTN_SMEM>>>(semh, kfh, xnh, aoh);

    // 4) xout = aoh @ Wc^T + bvr + xnh   (gamma folded into Wc, bvr)
    gemm_h<1, 256><<<dim3(4, M_ROWS / 128), 256, SMEM256>>>(aoh, wch, bvr, nullptr, xout,
                                                            nullptr, nullptr, CDIM, CDIM, xnh, nullptr);
}

// round 9
// speedup vs baseline: 10.5587x; 1.0389x over previous
#include <cuda_runtime.h>
#include <cuda_fp16.h>
#include <cstdint>
#include <cstddef>

// Problem constants (B=16, H=W=56, C=1024, K=150, WS=7)
#define M_ROWS 50176
#define CDIM   1024
#define KSEM   150
#define NWIN   1024
#define BATCH_STRIDE 3136

// -------- scratch (device globals) --------
__device__ __half g_xnh [(size_t)M_ROWS * CDIM];   // LN out half
__device__ __half g_semh[(size_t)M_ROWS * 160];    // seg_map half, padded stride
__device__ __half g_kfh [(size_t)M_ROWS * 160];    // seg_ft half, padded stride
__device__ __half g_aoh [(size_t)M_ROWS * CDIM];   // attention out half
__device__ __half g_wqkh[(size_t)300 * CDIM];      // wq(150) + wk(150) stacked
__device__ __half g_wrh [(size_t)CDIM * CDIM];     // wr half
__device__ __half g_wvth[(size_t)CDIM * CDIM];     // wv^T half
__device__ __half g_wch [(size_t)CDIM * CDIM];     // Wc = gamma * Wr @ Wv, half
__device__ float  g_bvr [CDIM];                    // gamma * (Wr @ bv + br)

__device__ __forceinline__ uint32_t smem_to_u32(const void* p) {
    uint32_t a;
    asm("{ .reg .u64 t; cvta.to.shared.u64 t, %1; cvt.u32.u64 %0, t; }" : "=r"(a) : "l"(p));
    return a;
}
#define CP_ASYNC16(dst, src) \
    asm volatile("cp.async.cg.shared.global [%0], [%1], 16;" :: "r"(dst), "l"(src) : "memory")
#define CP_COMMIT() asm volatile("cp.async.commit_group;" ::: "memory")
#define LDMATRIX_X4(r0, r1, r2, r3, addr) \
    asm volatile("ldmatrix.sync.aligned.m8n8.x4.shared.b16 {%0,%1,%2,%3}, [%4];" \
        : "=r"(r0), "=r"(r1), "=r"(r2), "=r"(r3) : "r"(addr))
#define LDMATRIX_X4_T(r0, r1, r2, r3, addr) \
    asm volatile("ldmatrix.sync.aligned.m8n8.x4.trans.shared.b16 {%0,%1,%2,%3}, [%4];" \
        : "=r"(r0), "=r"(r1), "=r"(r2), "=r"(r3) : "r"(addr))
#define MMA16816(acc, a, b0, b1) \
    asm volatile("mma.sync.aligned.m16n8k16.row.col.f32.f16.f16.f32 " \
        "{%0,%1,%2,%3}, {%4,%5,%6,%7}, {%8,%9}, {%0,%1,%2,%3};" \
        : "+f"((acc)[0]), "+f"((acc)[1]), "+f"((acc)[2]), "+f"((acc)[3]) \
        : "r"((a)[0]), "r"((a)[1]), "r"((a)[2]), "r"((a)[3]), "r"(b0), "r"(b1))

// ============================================================
// Merged prep kernel: one launch does all weight conversion,
// the Wv transpose, bvr, and semh/kfh pad-column zeroing.
// Block ranges:
//  [0,150)      f2h wq -> wqkh
//  [150,300)    f2h wk -> wqkh+150*1024
//  [300,1324)   f2h wr -> wrh
//  [1324,2348)  transpose wv -> wvth (32x32 tiles, linear->2D)
//  [2348,2352)  bvr
//  [2352,2548)  zero pad cols of semh/kfh
// ============================================================
__global__ __launch_bounds__(256)
void prep_kernel(const float* __restrict__ wq, const float* __restrict__ wk,
                 const float* __restrict__ wr, const float* __restrict__ wv,
                 const float* __restrict__ bv, const float* __restrict__ br,
                 const float* __restrict__ gammap,
                 __half* __restrict__ wqkh, __half* __restrict__ wrh,
                 __half* __restrict__ wvth, float* __restrict__ bvr,
                 __half* __restrict__ semh, __half* __restrict__ kfh)
{
    int bid = blockIdx.x;
    int t = threadIdx.x;
    if (bid < 300) {
        // f2h for wq / wk
        const float* in = (bid < 150) ? wq : wk;
        __half* out = wqkh + (bid < 150 ? 0 : (size_t)150 * CDIM);
        int i = (bid % 150) * 1024 + t * 4;
        float4 v = *(const float4*)(in + i);
        *(__half2*)(out + i)     = __floats2half2_rn(v.x, v.y);
        *(__half2*)(out + i + 2) = __floats2half2_rn(v.z, v.w);
    } else if (bid < 1324) {
        int i = (bid - 300) * 1024 + t * 4;
        float4 v = *(const float4*)(wr + i);
        *(__half2*)(wrh + i)     = __floats2half2_rn(v.x, v.y);
        *(__half2*)(wrh + i + 2) = __floats2half2_rn(v.z, v.w);
    } else if (bid < 2348) {
        // transpose wv (fp32) -> wvth (half)
        __shared__ float tile[32][33];
        int idx = bid - 1324;
        int bx = idx & 31, by = idx >> 5;
        int tx = t & 31, ty = t >> 5;  // ty 0..7
        int x = bx * 32 + tx;
        int y0 = by * 32 + ty;
        #pragma unroll
        for (int i = 0; i < 32; i += 8)
            tile[ty + i][tx] = wv[(size_t)(y0 + i) * CDIM + x];
        __syncthreads();
        int x2 = by * 32 + tx;
        int y2 = bx * 32 + ty;
        #pragma unroll
        for (int i = 0; i < 32; i += 8)
            wvth[(size_t)(y2 + i) * CDIM + x2] = __float2half_rn(tile[tx][ty + i]);
    } else if (bid < 2352) {
        // bvr = gamma * (Wr @ bv + br)
        int i = (bid - 2348) * 256 + t;
        const float4* w4 = (const float4*)(wr + (size_t)i * CDIM);
        const float4* b4 = (const float4*)bv;
        float s = 0.f;
        #pragma unroll 8
        for (int k = 0; k < 256; k++) {
            float4 a = w4[k], b = b4[k];
            s += a.x * b.x + a.y * b.y + a.z * b.z + a.w * b.w;
        }
        bvr[i] = gammap[0] * (s + br[i]);
    } else {
        // zero pad cols 150..159 of semh / kfh
        int r = (bid - 2352) * 256 + t;
        if (r < M_ROWS) {
            __half2 z = __floats2half2_rn(0.f, 0.f);
            __half2* pa = (__half2*)(semh + (size_t)r * 160 + 150);
            __half2* pb = (__half2*)(kfh  + (size_t)r * 160 + 150);
            #pragma unroll
            for (int i = 0; i < 5; i++) { pa[i] = z; pb[i] = z; }
        }
    }
}

// ============================================================
// LayerNorm: half output
// ============================================================
__global__ __launch_bounds__(256)
void ln_kernel(const float* __restrict__ x, const float* __restrict__ w,
               const float* __restrict__ b, __half* __restrict__ outh)
{
    int row = blockIdx.x;
    int t = threadIdx.x;
    const float4* xr = (const float4*)(x + (size_t)row * CDIM);
    float4 v = xr[t];
    float s  = v.x + v.y + v.z + v.w;
    float sq = v.x*v.x + v.y*v.y + v.z*v.z + v.w*v.w;
    #pragma unroll
    for (int o = 16; o > 0; o >>= 1) {
        s  += __shfl_xor_sync(0xFFFFFFFFu, s,  o);
        sq += __shfl_xor_sync(0xFFFFFFFFu, sq, o);
    }
    __shared__ float red[2][8];
    int wid = t >> 5, lid = t & 31;
    if (lid == 0) { red[0][wid] = s; red[1][wid] = sq; }
    __syncthreads();
    float st = 0.f, sqt = 0.f;
    #pragma unroll
    for (int i = 0; i < 8; i++) { st += red[0][i]; sqt += red[1][i]; }
    float mu   = st * (1.0f / CDIM);
    float var  = sqt * (1.0f / CDIM) - mu * mu;
    float rstd = rsqrtf(var + 1e-5f);
    float4 wv = ((const float4*)w)[t];
    float4 bv = ((const float4*)b)[t];
    float4 o;
    o.x = (v.x - mu) * rstd * wv.x + bv.x;
    o.y = (v.y - mu) * rstd * wv.y + bv.y;
    o.z = (v.z - mu) * rstd * wv.z + bv.z;
    o.w = (v.w - mu) * rstd * wv.w + bv.w;
    __half2* hp = (__half2*)(outh + (size_t)row * CDIM + t * 4);
    hp[0] = __floats2half2_rn(o.x, o.y);
    hp[1] = __floats2half2_rn(o.z, o.w);
}

// ============================================================
// fp16 mma.sync GEMM (BM=128, BK=64, 3 stages, 256 thr, 8 warps)
// WN = warps along n; WM = 8/WN. Warp tile (128/WM) x (BN/WN).
// MODE 1: C0 fp32 = acc + bias0 + (float)residh          [BN=256,WN=4]
// MODE 2: n<150 -> C0 fp32 sem(150) + H0 half(160); else H1 half kf(160)
//                                                        [BN=160,WN=2]
// MODE 4: H0 half = gamma * acc (no bias), stride ldc    [BN=128,WN=2]
// ============================================================
template<int MODE, int BN, int WN>
__global__ __launch_bounds__(256, 1)
void gemm_h(const __half* __restrict__ A, const __half* __restrict__ W,
            const float* __restrict__ bias0, const float* __restrict__ bias1,
            float* __restrict__ C0, __half* __restrict__ H0, __half* __restrict__ H1,
            int Nvalid, int ldc,
            const __half* __restrict__ residh, const float* __restrict__ gammap)
{
    constexpr int S = 3;
    constexpr int A_BYTES = 128 * 128;
    constexpr int B_BYTES = BN * 128;
    constexpr int STAGE = A_BYTES + B_BYTES;
    constexpr int NITER = CDIM / 64;
    constexpr int BLD = BN / 32;          // B cp.async iterations
    constexpr int WM  = 8 / WN;
    constexpr int MT  = 128 / (WM * 16);  // m tiles / warp
    constexpr int NT  = BN / (WN * 8);    // n tiles / warp
    constexpr int NB2 = (NT + 1) / 2;     // 16-row B ldmatrix tiles

    extern __shared__ char smem_raw[];
    char* tiles = (char*)(((uintptr_t)smem_raw + 1023) & ~(uintptr_t)1023);
    const uint32_t base = smem_to_u32(tiles);

    const int tid = threadIdx.x;
    const int m0  = blockIdx.y * 128;
    const int n0  = blockIdx.x * BN;
    const int vrows = (Nvalid - n0 < BN) ? (Nvalid - n0) : BN;

    if (vrows < BN) {
        #pragma unroll
        for (int s = 0; s < S; s++) {
            float4* z = (float4*)(tiles + s * STAGE + A_BYTES + vrows * 128);
            int cnt = (BN - vrows) * 8;
            for (int i = tid; i < cnt; i += 256) z[i] = make_float4(0.f, 0.f, 0.f, 0.f);
        }
        __syncthreads();
    }

    auto load_stage = [&](int c) {
        int st = c % S;
        uint32_t as = base + st * STAGE;
        uint32_t bs = as + A_BYTES;
        const char* Ag = (const char*)A + (size_t)m0 * (CDIM * 2) + c * 128;
        const char* Wg = (const char*)W + (size_t)n0 * (CDIM * 2) + c * 128;
        #pragma unroll
        for (int i = 0; i < 4; i++) {
            int idx = tid + i * 256;
            int r = idx >> 3, u = idx & 7;
            CP_ASYNC16(as + r * 128 + ((u ^ (r & 7)) << 4),
                       Ag + (size_t)r * (CDIM * 2) + u * 16);
        }
        #pragma unroll
        for (int i = 0; i < BLD; i++) {
            int idx = tid + i * 256;
            int r = idx >> 3, u = idx & 7;
            if (r < vrows)
                CP_ASYNC16(bs + r * 128 + ((u ^ (r & 7)) << 4),
                           Wg + (size_t)r * (CDIM * 2) + u * 16);
        }
        CP_COMMIT();
    };

    load_stage(0);
    load_stage(1);

    float acc[MT][NT][4];
    #pragma unroll
    for (int i = 0; i < MT; i++)
        #pragma unroll
        for (int j = 0; j < NT; j++)
            #pragma unroll
            for (int q = 0; q < 4; q++) acc[i][j][q] = 0.f;

    const int lane = tid & 31;
    const int wid  = tid >> 5;
    const int wm = (wid & (WM - 1)) * (128 / WM);
    const int wn = (wid / WM) * (NT * 8);

    const int arow_l = wm + (lane & 15);
    const int au_l   = lane >> 4;
    const int brow_l = wn + (lane & 7) + ((lane >> 4) << 3);
    const int bu_l   = (lane >> 3) & 1;

    for (int it = 0; it < NITER; it++) {
        asm volatile("cp.async.wait_group 1;" ::: "memory");
        __syncthreads();
        if (it + 2 < NITER) load_stage(it + 2);

        uint32_t as = base + (it % S) * STAGE;
        uint32_t bs = as + A_BYTES;
        #pragma unroll
        for (int kk = 0; kk < 4; kk++) {
            uint32_t a[MT][4], b[NB2][4];
            #pragma unroll
            for (int mt = 0; mt < MT; mt++) {
                int row = arow_l + mt * 16;
                int u = kk * 2 + au_l;
                LDMATRIX_X4(a[mt][0], a[mt][1], a[mt][2], a[mt][3],
                            as + row * 128 + ((u ^ (row & 7)) << 4));
            }
            #pragma unroll
            for (int np = 0; np < NB2; np++) {
                int row = brow_l + np * 16;
                int u = kk * 2 + bu_l;
                LDMATRIX_X4(b[np][0], b[np][1], b[np][2], b[np][3],
                            bs + row * 128 + ((u ^ (row & 7)) << 4));
            }
            #pragma unroll
            for (int mt = 0; mt < MT; mt++)
                #pragma unroll
                for (int nt = 0; nt < NT; nt++)
                    MMA16816(acc[mt][nt], a[mt],
                             b[nt >> 1][(nt & 1) * 2], b[nt >> 1][(nt & 1) * 2 + 1]);
        }
    }

    // ---- epilogue ----
    const int g = lane >> 2, tig = lane & 3;
    #pragma unroll
    for (int mt = 0; mt < MT; mt++) {
        #pragma unroll
        for (int nt = 0; nt < NT; nt++) {
            int m = m0 + wm + mt * 16 + g;
            int n = n0 + wn + nt * 8 + tig * 2;
            if (MODE == 2) {
                if (n >= Nvalid) continue;
                #pragma unroll
                for (int h = 0; h < 2; h++) {
                    int mr = m + h * 8;
                    float v0, v1;
                    if (n < 150) {
                        v0 = acc[mt][nt][h*2+0] + bias0[n];
                        v1 = acc[mt][nt][h*2+1] + bias0[n + 1];
                        C0[(size_t)mr * 150 + n]     = v0;
                        C0[(size_t)mr * 150 + n + 1] = v1;
                        *(__half2*)(H0 + (size_t)mr * 160 + n) = __floats2half2_rn(v0, v1);
                    } else {
                        int nn = n - 150;
                        v0 = acc[mt][nt][h*2+0] + bias1[nn];
                        v1 = acc[mt][nt][h*2+1] + bias1[nn + 1];
                        *(__half2*)(H1 + (size_t)mr * 160 + nn) = __floats2half2_rn(v0, v1);
                    }
                }
            } else if (MODE == 4) {
                float gm = gammap[0];
                #pragma unroll
                for (int h = 0; h < 2; h++) {
                    int mr = m + h * 8;
                    *(__half2*)(H0 + (size_t)mr * ldc + n) =
                        __floats2half2_rn(gm * acc[mt][nt][h*2+0], gm * acc[mt][nt][h*2+1]);
                }
            } else { // MODE 1
                float b0 = bias0[n], b1 = bias0[n + 1];
                #pragma unroll
                for (int h = 0; h < 2; h++) {
                    int mr = m + h * 8;
                    __half2 rv = *(const __half2*)(residh + (size_t)mr * CDIM + n);
                    float v0 = acc[mt][nt][h*2+0] + b0 + __low2float(rv);
                    float v1 = acc[mt][nt][h*2+1] + b1 + __high2float(rv);
                    *(float2*)(C0 + (size_t)mr * ldc + n) = make_float2(v0, v1);
                }
            }
        }
    }
}

// ============================================================
// HMMA per-window attention, cp.async double-buffered V.
// ============================================================
#define QK_STRB 336
#define SF_STR  66
#define SH_STRB 144
#define VC_STRB 272
#define V_OFF   69120
#define V_BUFB  17408
#define ATTN_SMEM (69120 + 2 * 17408)  // 103936

__global__ __launch_bounds__(128)
void attn_mma(const __half* __restrict__ semh, const __half* __restrict__ kfh,
              const __half* __restrict__ vh, __half* __restrict__ ao)
{
    extern __shared__ char sm[];
    char* Qc = sm;
    char* Kc = sm + 21504;
    float* Sf = (float*)(sm + 43008);
    char* Shc = sm + 59904;
    char* Vb0 = sm + V_OFF;

    const uint32_t qb  = smem_to_u32(Qc);
    const uint32_t kb  = smem_to_u32(Kc);
    const uint32_t shb = smem_to_u32(Shc);
    const uint32_t vbb = smem_to_u32(Vb0);

    int wi = blockIdx.x;
    int b  = wi >> 6;
    int wh = (wi >> 3) & 7;
    int ww = wi & 7;
    int base = b * BATCH_STRIDE + wh * 7 * 56 + ww * 7;
    int t = threadIdx.x;
    const int lane = t & 31, w = t >> 5;

    // zero pad rows 49..63 of Qc/Kc
    for (int i = t; i < 630; i += 128) {
        char* buf = (i < 315) ? Qc : Kc;
        int idx = (i < 315) ? i : i - 315;
        int row = 49 + idx / 21, u = idx % 21;
        ((float4*)(buf + row * QK_STRB))[u] = make_float4(0.f, 0.f, 0.f, 0.f);
    }
    // zero pad rows 49..63 of BOTH V buffers
    for (int i = t; i < 2 * 15 * 17; i += 128) {
        int bsel = i >= 255;
        int idx = i - bsel * 255;
        int row = 49 + idx / 17, u = idx % 17;
        ((float4*)(Vb0 + bsel * V_BUFB + row * VC_STRB))[u] = make_float4(0.f, 0.f, 0.f, 0.f);
    }

    // cp.async gather Q,K rows (group 0)
    for (int idx = t; idx < 1960; idx += 128) {
        int which = idx >= 980;
        int i2 = idx - which * 980;
        int n = i2 / 20, u = i2 % 20;
        int r = base + (n / 7) * 56 + (n % 7);
        uint32_t dst = (which ? kb : qb) + n * QK_STRB + u * 16;
        const char* src = (const char*)(which ? kfh : semh) + (size_t)r * 320 + u * 16;
        CP_ASYNC16(dst, src);
    }
    CP_COMMIT();

    // prefetch V chunk 0 (group 1)
    for (int idx = t; idx < 49 * 16; idx += 128) {
        int m = idx >> 4, u = idx & 15;
        int r = base + (m / 7) * 56 + (m % 7);
        CP_ASYNC16(vbb + m * VC_STRB + u * 16,
                   (const char*)vh + (size_t)r * 2048 + u * 16);
    }
    CP_COMMIT();

    asm volatile("cp.async.wait_group 1;" ::: "memory");
    __syncthreads();

    // ---- Phase A: S = Q K^T
    {
        float accS[8][4];
        #pragma unroll
        for (int j = 0; j < 8; j++)
            #pragma unroll
            for (int q = 0; q < 4; q++) accS[j][q] = 0.f;

        const int arow = 16 * w + (lane & 15);
        const int ak   = (lane >> 4) * 8;
        const int brow = (lane & 7) + ((lane >> 4) << 3);
        const int bk   = ((lane >> 3) & 1) * 8;

        #pragma unroll
        for (int ks = 0; ks < 10; ks++) {
            uint32_t a[4], bfr[4][4];
            LDMATRIX_X4(a[0], a[1], a[2], a[3],
                        qb + arow * QK_STRB + (ks * 16 + ak) * 2);
            #pragma unroll
            for (int np = 0; np < 4; np++)
                LDMATRIX_X4(bfr[np][0], bfr[np][1], bfr[np][2], bfr[np][3],
                            kb + (brow + np * 16) * QK_STRB + (ks * 16 + bk) * 2);
            #pragma unroll
            for (int nt = 0; nt < 8; nt++)
                MMA16816(accS[nt], a, bfr[nt >> 1][(nt & 1) * 2], bfr[nt >> 1][(nt & 1) * 2 + 1]);
        }
        const int g = lane >> 2, tig = lane & 3;
        #pragma unroll
        for (int nt = 0; nt < 8; nt++) {
            #pragma unroll
            for (int h = 0; h < 2; h++) {
                int row = 16 * w + g + h * 8;
                Sf[row * SF_STR + nt * 8 + tig * 2]     = accS[nt][h * 2 + 0];
                Sf[row * SF_STR + nt * 8 + tig * 2 + 1] = accS[nt][h * 2 + 1];
            }
        }
    }
    __syncthreads();

    // ---- softmax
    if (t < 49) {
        float* row = Sf + t * SF_STR;
        float mx = -1e30f;
        #pragma unroll
        for (int m = 0; m < 49; m++) mx = fmaxf(mx, row[m]);
        float sum = 0.f;
        #pragma unroll
        for (int m = 0; m < 49; m++) { float e = __expf(row[m] - mx); row[m] = e; sum += e; }
        float inv = 1.f / sum;
        #pragma unroll
        for (int m = 0; m < 49; m++) row[m] *= inv;
    }
    __syncthreads();

    // ---- S -> half (zeros outside 49x49)
    for (int idx = t; idx < 2048; idx += 128) {
        int i = idx >> 5, j2 = (idx & 31) * 2;
        float v0 = (i < 49 && j2     < 49) ? Sf[i * SF_STR + j2]     : 0.f;
        float v1 = (i < 49 && j2 + 1 < 49) ? Sf[i * SF_STR + j2 + 1] : 0.f;
        *(__half2*)(Shc + i * SH_STRB + j2 * 2) = __floats2half2_rn(v0, v1);
    }

    // ---- Phase B: O = S V, double-buffered chunks
    const int arow = lane & 15;
    const int ak   = (lane >> 4) * 8;
    const int kk_l = (lane & 7) + ((lane >> 3) & 1) * 8;
    const int nc_l = 32 * w + ((lane >> 4) << 3);
    const int g = lane >> 2, tig = lane & 3;

    for (int cc = 0; cc < 8; cc++) {
        if (cc + 1 < 8) {
            uint32_t nb = vbb + ((cc + 1) & 1) * V_BUFB;
            for (int idx = t; idx < 49 * 16; idx += 128) {
                int m = idx >> 4, u = idx & 15;
                int r = base + (m / 7) * 56 + (m % 7);
                CP_ASYNC16(nb + m * VC_STRB + u * 16,
                           (const char*)vh + (size_t)r * 2048 + (cc + 1) * 256 + u * 16);
            }
            CP_COMMIT();
            asm volatile("cp.async.wait_group 1;" ::: "memory");
        } else {
            asm volatile("cp.async.wait_group 0;" ::: "memory");
        }
        __syncthreads();

        const uint32_t vb = vbb + (cc & 1) * V_BUFB;
        float acc[4][4][4];
        #pragma unroll
        for (int i = 0; i < 4; i++)
            #pragma unroll
            for (int j = 0; j < 4; j++)
                #pragma unroll
                for (int q = 0; q < 4; q++) acc[i][j][q] = 0.f;

        #pragma unroll
        for (int ks = 0; ks < 4; ks++) {
            uint32_t a[4][4], bq[2][4];
            #pragma unroll
            for (int mt = 0; mt < 4; mt++)
                LDMATRIX_X4(a[mt][0], a[mt][1], a[mt][2], a[mt][3],
                            shb + (16 * mt + arow) * SH_STRB + (ks * 16 + ak) * 2);
            #pragma unroll
            for (int nb2 = 0; nb2 < 2; nb2++)
                LDMATRIX_X4_T(bq[nb2][0], bq[nb2][1], bq[nb2][2], bq[nb2][3],
                              vb + (ks * 16 + kk_l) * VC_STRB + (nc_l + nb2 * 16) * 2);
            #pragma unroll
            for (int mt = 0; mt < 4; mt++)
                #pragma unroll
                for (int nt = 0; nt < 4; nt++)
                    MMA16816(acc[mt][nt], a[mt],
                             bq[nt >> 1][(nt & 1) * 2], bq[nt >> 1][(nt & 1) * 2 + 1]);
        }

        #pragma unroll
        for (int mt = 0; mt < 4; mt++) {
            #pragma unroll
            for (int h = 0; h < 2; h++) {
                int m = 16 * mt + g + h * 8;
                if (m < 49) {
                    int r = base + (m / 7) * 56 + (m % 7);
                    __half* dst = ao + (size_t)r * CDIM + cc * 128;
                    #pragma unroll
                    for (int nt = 0; nt < 4; nt++) {
                        int n = 32 * w + nt * 8 + tig * 2;
                        *(__half2*)(dst + n) =
                            __floats2half2_rn(acc[mt][nt][h*2+0], acc[mt][nt][h*2+1]);
                    }
                }
            }
        }
        __syncthreads();
    }
}

// ============================================================
// Host launcher
// ============================================================
extern "C" void kernel_launch(void* const* d_in, const int* in_sizes, int n_in,
                              void* d_out, int out_size)
{
    const float* x      = (const float*)d_in[0];
    const float* norm_w = (const float*)d_in[1];
    const float* norm_b = (const float*)d_in[2];
    const float* wq     = (const float*)d_in[3];
    const float* bq     = (const float*)d_in[4];
    const float* wk     = (const float*)d_in[5];
    const float* bk     = (const float*)d_in[6];
    const float* wv     = (const float*)d_in[7];
    const float* bv     = (const float*)d_in[8];
    const float* wr     = (const float*)d_in[9];
    const float* br     = (const float*)d_in[10];
    const float* gamma  = (const float*)d_in[11];
    (void)in_sizes; (void)n_in; (void)out_size;

    float* out  = (float*)d_out;
    float* sem  = out;                              // [50176, 150]
    float* xout = out + (size_t)M_ROWS * KSEM;      // [50176, 1024]

    __half *xnh, *semh, *kfh, *aoh, *wqkh, *wrh, *wvth, *wch;
    float* bvr;
    cudaGetSymbolAddress((void**)&xnh,  g_xnh);
    cudaGetSymbolAddress((void**)&semh, g_semh);
    cudaGetSymbolAddress((void**)&kfh,  g_kfh);
    cudaGetSymbolAddress((void**)&aoh,  g_aoh);
    cudaGetSymbolAddress((void**)&wqkh, g_wqkh);
    cudaGetSymbolAddress((void**)&wrh,  g_wrh);
    cudaGetSymbolAddress((void**)&wvth, g_wvth);
    cudaGetSymbolAddress((void**)&wch,  g_wch);
    cudaGetSymbolAddress((void**)&bvr,  g_bvr);

    const int SMEM256 = 3 * 49152 + 1024;  // 148480
    const int SMEM160 = 3 * 36864 + 1024;  // 111616
    const int SMEM128 = 3 * 32768 + 1024;  // 99328
    cudaFuncSetAttribute(gemm_h<1, 256, 4>, cudaFuncAttributeMaxDynamicSharedMemorySize, SMEM256);
    cudaFuncSetAttribute(gemm_h<2, 160, 2>, cudaFuncAttributeMaxDynamicSharedMemorySize, SMEM160);
    cudaFuncSetAttribute(gemm_h<4, 128, 2>, cudaFuncAttributeMaxDynamicSharedMemorySize, SMEM128);
    cudaFuncSetAttribute(attn_mma, cudaFuncAttributeMaxDynamicSharedMemorySize, ATTN_SMEM);

    // 0) merged weight prep (f2h x3, transpose, bvr, pad zero)
    prep_kernel<<<2548, 256>>>(wq, wk, wr, wv, bv, br, gamma,
                               wqkh, wrh, wvth, bvr, semh, kfh);

    // Wc = gamma * Wr @ Wv (half)
    gemm_h<4, 128, 2><<<dim3(8, 8), 256, SMEM128>>>(wrh, wvth, nullptr, nullptr,
                                                    nullptr, wch, nullptr, CDIM, CDIM, nullptr, gamma);

    // 1) LayerNorm -> half
    ln_kernel<<<M_ROWS, 256>>>(x, norm_w, norm_b, xnh);

    // 2) merged Q/K projection (N=300, padded 320, BN=160 x 2 tiles)
    gemm_h<2, 160, 2><<<dim3(2, M_ROWS / 128), 256, SMEM160>>>(xnh, wqkh, bq, bk, sem, semh, kfh,
                                                               300, KSEM, nullptr, nullptr);

    // 3) attention: aoh = softmax(QK^T) @ xnh
    attn_mma<<<NWIN, 128, ATTN_SMEM>>>(semh, kfh, xnh, aoh);

    // 4) xout = aoh @ Wc^T + bvr + xnh
    gemm_h<1, 256, 4><<<dim3(4, M_ROWS / 128), 256, SMEM256>>>(aoh, wch, bvr, nullptr, xout,
                                                               nullptr, nullptr, CDIM, CDIM, xnh, nullptr);
}

// round 10
// speedup vs baseline: 10.6981x; 1.0132x over previous
#include <cuda_runtime.h>
#include <cuda_fp16.h>
#include <cstdint>
#include <cstddef>

// Problem constants (B=16, H=W=56, C=1024, K=150, WS=7)
#define M_ROWS 50176
#define CDIM   1024
#define KSEM   150
#define NWIN   1024
#define BATCH_STRIDE 3136

// -------- scratch (device globals) --------
__device__ __half g_xnh [(size_t)M_ROWS * CDIM];   // LN out half
__device__ __half g_semh[(size_t)M_ROWS * 160];    // seg_map half, padded stride
__device__ __half g_kfh [(size_t)M_ROWS * 160];    // seg_ft half, padded stride
__device__ __half g_aoh [(size_t)M_ROWS * CDIM];   // attention out half
__device__ __half g_wqkh[(size_t)300 * CDIM];      // wq(150) + wk(150) stacked
__device__ __half g_wrh [(size_t)CDIM * CDIM];     // wr half
__device__ __half g_wvth[(size_t)CDIM * CDIM];     // wv^T half
__device__ __half g_wch [(size_t)CDIM * CDIM];     // Wc = gamma * Wr @ Wv, half
__device__ float  g_bvr [CDIM];                    // gamma * (Wr @ bv + br)

__device__ __forceinline__ uint32_t smem_to_u32(const void* p) {
    uint32_t a;
    asm("{ .reg .u64 t; cvta.to.shared.u64 t, %1; cvt.u32.u64 %0, t; }" : "=r"(a) : "l"(p));
    return a;
}
#define CP_ASYNC16(dst, src) \
    asm volatile("cp.async.cg.shared.global [%0], [%1], 16;" :: "r"(dst), "l"(src) : "memory")
#define CP_COMMIT() asm volatile("cp.async.commit_group;" ::: "memory")
#define LDMATRIX_X4(r0, r1, r2, r3, addr) \
    asm volatile("ldmatrix.sync.aligned.m8n8.x4.shared.b16 {%0,%1,%2,%3}, [%4];" \
        : "=r"(r0), "=r"(r1), "=r"(r2), "=r"(r3) : "r"(addr))
#define LDMATRIX_X4_T(r0, r1, r2, r3, addr) \
    asm volatile("ldmatrix.sync.aligned.m8n8.x4.trans.shared.b16 {%0,%1,%2,%3}, [%4];" \
        : "=r"(r0), "=r"(r1), "=r"(r2), "=r"(r3) : "r"(addr))
#define MMA16816(acc, a, b0, b1) \
    asm volatile("mma.sync.aligned.m16n8k16.row.col.f32.f16.f16.f32 " \
        "{%0,%1,%2,%3}, {%4,%5,%6,%7}, {%8,%9}, {%0,%1,%2,%3};" \
        : "+f"((acc)[0]), "+f"((acc)[1]), "+f"((acc)[2]), "+f"((acc)[3]) \
        : "r"((a)[0]), "r"((a)[1]), "r"((a)[2]), "r"((a)[3]), "r"(b0), "r"(b1))

// ============================================================
// Merged LN + prep kernel. Block ranges:
//  [0,300)      f2h wq/wk -> wqkh
//  [300,1324)   f2h wr -> wrh
//  [1324,2348)  transpose wv -> wvth
//  [2348,2352)  bvr = gamma*(Wr@bv+br)
//  [2352,2548)  zero pad cols 150..159 of semh/kfh
//  [2548,52724) LayerNorm row (bid-2548)
// Prep blocks come FIRST so they are scheduled earliest and
// their output is long done before the kernel retires.
// ============================================================
#define PREP_BLOCKS 2548

__global__ __launch_bounds__(256)
void ln_prep_kernel(const float* __restrict__ x, const float* __restrict__ norm_w,
                    const float* __restrict__ norm_b, __half* __restrict__ outh,
                    const float* __restrict__ wq, const float* __restrict__ wk,
                    const float* __restrict__ wr, const float* __restrict__ wv,
                    const float* __restrict__ bv, const float* __restrict__ br,
                    const float* __restrict__ gammap,
                    __half* __restrict__ wqkh, __half* __restrict__ wrh,
                    __half* __restrict__ wvth, float* __restrict__ bvr,
                    __half* __restrict__ semh, __half* __restrict__ kfh)
{
    __shared__ float tile[32][33];   // transpose branch
    __shared__ float red[2][8];      // LN branch
    int bid = blockIdx.x;
    int t = threadIdx.x;

    if (bid >= PREP_BLOCKS) {
        // ---- LayerNorm ----
        int row = bid - PREP_BLOCKS;
        const float4* xr = (const float4*)(x + (size_t)row * CDIM);
        float4 v = xr[t];
        float s  = v.x + v.y + v.z + v.w;
        float sq = v.x*v.x + v.y*v.y + v.z*v.z + v.w*v.w;
        #pragma unroll
        for (int o = 16; o > 0; o >>= 1) {
            s  += __shfl_xor_sync(0xFFFFFFFFu, s,  o);
            sq += __shfl_xor_sync(0xFFFFFFFFu, sq, o);
        }
        int wid = t >> 5, lid = t & 31;
        if (lid == 0) { red[0][wid] = s; red[1][wid] = sq; }
        __syncthreads();
        float st = 0.f, sqt = 0.f;
        #pragma unroll
        for (int i = 0; i < 8; i++) { st += red[0][i]; sqt += red[1][i]; }
        float mu   = st * (1.0f / CDIM);
        float var  = sqt * (1.0f / CDIM) - mu * mu;
        float rstd = rsqrtf(var + 1e-5f);
        float4 wv4 = ((const float4*)norm_w)[t];
        float4 bv4 = ((const float4*)norm_b)[t];
        float4 o;
        o.x = (v.x - mu) * rstd * wv4.x + bv4.x;
        o.y = (v.y - mu) * rstd * wv4.y + bv4.y;
        o.z = (v.z - mu) * rstd * wv4.z + bv4.z;
        o.w = (v.w - mu) * rstd * wv4.w + bv4.w;
        __half2* hp = (__half2*)(outh + (size_t)row * CDIM + t * 4);
        hp[0] = __floats2half2_rn(o.x, o.y);
        hp[1] = __floats2half2_rn(o.z, o.w);
    } else if (bid < 300) {
        const float* in = (bid < 150) ? wq : wk;
        __half* out = wqkh + (bid < 150 ? 0 : (size_t)150 * CDIM);
        int i = (bid % 150) * 1024 + t * 4;
        float4 v = *(const float4*)(in + i);
        *(__half2*)(out + i)     = __floats2half2_rn(v.x, v.y);
        *(__half2*)(out + i + 2) = __floats2half2_rn(v.z, v.w);
    } else if (bid < 1324) {
        int i = (bid - 300) * 1024 + t * 4;
        float4 v = *(const float4*)(wr + i);
        *(__half2*)(wrh + i)     = __floats2half2_rn(v.x, v.y);
        *(__half2*)(wrh + i + 2) = __floats2half2_rn(v.z, v.w);
    } else if (bid < 2348) {
        // transpose wv (fp32) -> wvth (half)
        int idx = bid - 1324;
        int bx = idx & 31, by = idx >> 5;
        int tx = t & 31, ty = t >> 5;  // ty 0..7
        int xx = bx * 32 + tx;
        int y0 = by * 32 + ty;
        #pragma unroll
        for (int i = 0; i < 32; i += 8)
            tile[ty + i][tx] = wv[(size_t)(y0 + i) * CDIM + xx];
        __syncthreads();
        int x2 = by * 32 + tx;
        int y2 = bx * 32 + ty;
        #pragma unroll
        for (int i = 0; i < 32; i += 8)
            wvth[(size_t)(y2 + i) * CDIM + x2] = __float2half_rn(tile[tx][ty + i]);
    } else if (bid < 2352) {
        int i = (bid - 2348) * 256 + t;
        const float4* w4 = (const float4*)(wr + (size_t)i * CDIM);
        const float4* b4 = (const float4*)bv;
        float s = 0.f;
        #pragma unroll 8
        for (int k = 0; k < 256; k++) {
            float4 a = w4[k], b = b4[k];
            s += a.x * b.x + a.y * b.y + a.z * b.z + a.w * b.w;
        }
        bvr[i] = gammap[0] * (s + br[i]);
    } else {
        int r = (bid - 2352) * 256 + t;
        if (r < M_ROWS) {
            __half2 z = __floats2half2_rn(0.f, 0.f);
            __half2* pa = (__half2*)(semh + (size_t)r * 160 + 150);
            __half2* pb = (__half2*)(kfh  + (size_t)r * 160 + 150);
            #pragma unroll
            for (int i = 0; i < 5; i++) { pa[i] = z; pb[i] = z; }
        }
    }
}

// ============================================================
// fp16 mma.sync GEMM (BM=128, BK=64, 3 stages, 256 thr, 8 warps)
// MODE 1: C0 fp32 = acc + bias0 + (float)residh          [BN=256,WN=4]
// MODE 2: n<150 -> C0 fp32 sem(150) + H0 half(160); else H1 half kf(160)
//                                                        [BN=160,WN=2]
// MODE 4: H0 half = gamma * acc (no bias), stride ldc    [BN=128,WN=2]
// ============================================================
template<int MODE, int BN, int WN>
__global__ __launch_bounds__(256, 1)
void gemm_h(const __half* __restrict__ A, const __half* __restrict__ W,
            const float* __restrict__ bias0, const float* __restrict__ bias1,
            float* __restrict__ C0, __half* __restrict__ H0, __half* __restrict__ H1,
            int Nvalid, int ldc,
            const __half* __restrict__ residh, const float* __restrict__ gammap)
{
    constexpr int S = 3;
    constexpr int A_BYTES = 128 * 128;
    constexpr int B_BYTES = BN * 128;
    constexpr int STAGE = A_BYTES + B_BYTES;
    constexpr int NITER = CDIM / 64;
    constexpr int BLD = BN / 32;
    constexpr int WM  = 8 / WN;
    constexpr int MT  = 128 / (WM * 16);
    constexpr int NT  = BN / (WN * 8);
    constexpr int NB2 = (NT + 1) / 2;

    extern __shared__ char smem_raw[];
    char* tiles = (char*)(((uintptr_t)smem_raw + 1023) & ~(uintptr_t)1023);
    const uint32_t base = smem_to_u32(tiles);

    const int tid = threadIdx.x;
    const int m0  = blockIdx.y * 128;
    const int n0  = blockIdx.x * BN;
    const int vrows = (Nvalid - n0 < BN) ? (Nvalid - n0) : BN;

    if (vrows < BN) {
        #pragma unroll
        for (int s = 0; s < S; s++) {
            float4* z = (float4*)(tiles + s * STAGE + A_BYTES + vrows * 128);
            int cnt = (BN - vrows) * 8;
            for (int i = tid; i < cnt; i += 256) z[i] = make_float4(0.f, 0.f, 0.f, 0.f);
        }
        __syncthreads();
    }

    auto load_stage = [&](int c) {
        int st = c % S;
        uint32_t as = base + st * STAGE;
        uint32_t bs = as + A_BYTES;
        const char* Ag = (const char*)A + (size_t)m0 * (CDIM * 2) + c * 128;
        const char* Wg = (const char*)W + (size_t)n0 * (CDIM * 2) + c * 128;
        #pragma unroll
        for (int i = 0; i < 4; i++) {
            int idx = tid + i * 256;
            int r = idx >> 3, u = idx & 7;
            CP_ASYNC16(as + r * 128 + ((u ^ (r & 7)) << 4),
                       Ag + (size_t)r * (CDIM * 2) + u * 16);
        }
        #pragma unroll
        for (int i = 0; i < BLD; i++) {
            int idx = tid + i * 256;
            int r = idx >> 3, u = idx & 7;
            if (r < vrows)
                CP_ASYNC16(bs + r * 128 + ((u ^ (r & 7)) << 4),
                           Wg + (size_t)r * (CDIM * 2) + u * 16);
        }
        CP_COMMIT();
    };

    load_stage(0);
    load_stage(1);

    float acc[MT][NT][4];
    #pragma unroll
    for (int i = 0; i < MT; i++)
        #pragma unroll
        for (int j = 0; j < NT; j++)
            #pragma unroll
            for (int q = 0; q < 4; q++) acc[i][j][q] = 0.f;

    const int lane = tid & 31;
    const int wid  = tid >> 5;
    const int wm = (wid & (WM - 1)) * (128 / WM);
    const int wn = (wid / WM) * (NT * 8);

    const int arow_l = wm + (lane & 15);
    const int au_l   = lane >> 4;
    const int brow_l = wn + (lane & 7) + ((lane >> 4) << 3);
    const int bu_l   = (lane >> 3) & 1;

    for (int it = 0; it < NITER; it++) {
        asm volatile("cp.async.wait_group 1;" ::: "memory");
        __syncthreads();
        if (it + 2 < NITER) load_stage(it + 2);

        uint32_t as = base + (it % S) * STAGE;
        uint32_t bs = as + A_BYTES;
        #pragma unroll
        for (int kk = 0; kk < 4; kk++) {
            uint32_t a[MT][4], b[NB2][4];
            #pragma unroll
            for (int mt = 0; mt < MT; mt++) {
                int row = arow_l + mt * 16;
                int u = kk * 2 + au_l;
                LDMATRIX_X4(a[mt][0], a[mt][1], a[mt][2], a[mt][3],
                            as + row * 128 + ((u ^ (row & 7)) << 4));
            }
            #pragma unroll
            for (int np = 0; np < NB2; np++) {
                int row = brow_l + np * 16;
                int u = kk * 2 + bu_l;
                LDMATRIX_X4(b[np][0], b[np][1], b[np][2], b[np][3],
                            bs + row * 128 + ((u ^ (row & 7)) << 4));
            }
            #pragma unroll
            for (int mt = 0; mt < MT; mt++)
                #pragma unroll
                for (int nt = 0; nt < NT; nt++)
                    MMA16816(acc[mt][nt], a[mt],
                             b[nt >> 1][(nt & 1) * 2], b[nt >> 1][(nt & 1) * 2 + 1]);
        }
    }

    // ---- epilogue ----
    const int g = lane >> 2, tig = lane & 3;
    #pragma unroll
    for (int mt = 0; mt < MT; mt++) {
        #pragma unroll
        for (int nt = 0; nt < NT; nt++) {
            int m = m0 + wm + mt * 16 + g;
            int n = n0 + wn + nt * 8 + tig * 2;
            if (MODE == 2) {
                if (n >= Nvalid) continue;
                #pragma unroll
                for (int h = 0; h < 2; h++) {
                    int mr = m + h * 8;
                    float v0, v1;
                    if (n < 150) {
                        v0 = acc[mt][nt][h*2+0] + bias0[n];
                        v1 = acc[mt][nt][h*2+1] + bias0[n + 1];
                        C0[(size_t)mr * 150 + n]     = v0;
                        C0[(size_t)mr * 150 + n + 1] = v1;
                        *(__half2*)(H0 + (size_t)mr * 160 + n) = __floats2half2_rn(v0, v1);
                    } else {
                        int nn = n - 150;
                        v0 = acc[mt][nt][h*2+0] + bias1[nn];
                        v1 = acc[mt][nt][h*2+1] + bias1[nn + 1];
                        *(__half2*)(H1 + (size_t)mr * 160 + nn) = __floats2half2_rn(v0, v1);
                    }
                }
            } else if (MODE == 4) {
                float gm = gammap[0];
                #pragma unroll
                for (int h = 0; h < 2; h++) {
                    int mr = m + h * 8;
                    *(__half2*)(H0 + (size_t)mr * ldc + n) =
                        __floats2half2_rn(gm * acc[mt][nt][h*2+0], gm * acc[mt][nt][h*2+1]);
                }
            } else { // MODE 1
                float b0 = bias0[n], b1 = bias0[n + 1];
                #pragma unroll
                for (int h = 0; h < 2; h++) {
                    int mr = m + h * 8;
                    __half2 rv = *(const __half2*)(residh + (size_t)mr * CDIM + n);
                    float v0 = acc[mt][nt][h*2+0] + b0 + __low2float(rv);
                    float v1 = acc[mt][nt][h*2+1] + b1 + __high2float(rv);
                    *(float2*)(C0 + (size_t)mr * ldc + n) = make_float2(v0, v1);
                }
            }
        }
    }
}

// ============================================================
// HMMA per-window attention, cp.async double-buffered V,
// warp-parallel softmax fused with S->half conversion.
// ============================================================
#define QK_STRB 336
#define SF_STR  66
#define SH_STRB 144
#define VC_STRB 272
#define V_OFF   69120
#define V_BUFB  17408
#define ATTN_SMEM (69120 + 2 * 17408)  // 103936

__global__ __launch_bounds__(128)
void attn_mma(const __half* __restrict__ semh, const __half* __restrict__ kfh,
              const __half* __restrict__ vh, __half* __restrict__ ao)
{
    extern __shared__ char sm[];
    char* Qc = sm;
    char* Kc = sm + 21504;
    float* Sf = (float*)(sm + 43008);
    char* Shc = sm + 59904;
    char* Vb0 = sm + V_OFF;

    const uint32_t qb  = smem_to_u32(Qc);
    const uint32_t kb  = smem_to_u32(Kc);
    const uint32_t shb = smem_to_u32(Shc);
    const uint32_t vbb = smem_to_u32(Vb0);

    int wi = blockIdx.x;
    int b  = wi >> 6;
    int wh = (wi >> 3) & 7;
    int ww = wi & 7;
    int base = b * BATCH_STRIDE + wh * 7 * 56 + ww * 7;
    int t = threadIdx.x;
    const int lane = t & 31, w = t >> 5;

    // zero pad rows 49..63 of Qc/Kc
    for (int i = t; i < 630; i += 128) {
        char* buf = (i < 315) ? Qc : Kc;
        int idx = (i < 315) ? i : i - 315;
        int row = 49 + idx / 21, u = idx % 21;
        ((float4*)(buf + row * QK_STRB))[u] = make_float4(0.f, 0.f, 0.f, 0.f);
    }
    // zero pad rows 49..63 of BOTH V buffers
    for (int i = t; i < 2 * 15 * 17; i += 128) {
        int bsel = i >= 255;
        int idx = i - bsel * 255;
        int row = 49 + idx / 17, u = idx % 17;
        ((float4*)(Vb0 + bsel * V_BUFB + row * VC_STRB))[u] = make_float4(0.f, 0.f, 0.f, 0.f);
    }

    // cp.async gather Q,K rows (group 0)
    for (int idx = t; idx < 1960; idx += 128) {
        int which = idx >= 980;
        int i2 = idx - which * 980;
        int n = i2 / 20, u = i2 % 20;
        int r = base + (n / 7) * 56 + (n % 7);
        uint32_t dst = (which ? kb : qb) + n * QK_STRB + u * 16;
        const char* src = (const char*)(which ? kfh : semh) + (size_t)r * 320 + u * 16;
        CP_ASYNC16(dst, src);
    }
    CP_COMMIT();

    // prefetch V chunk 0 (group 1)
    for (int idx = t; idx < 49 * 16; idx += 128) {
        int m = idx >> 4, u = idx & 15;
        int r = base + (m / 7) * 56 + (m % 7);
        CP_ASYNC16(vbb + m * VC_STRB + u * 16,
                   (const char*)vh + (size_t)r * 2048 + u * 16);
    }
    CP_COMMIT();

    asm volatile("cp.async.wait_group 1;" ::: "memory");
    __syncthreads();

    // ---- Phase A: S = Q K^T
    {
        float accS[8][4];
        #pragma unroll
        for (int j = 0; j < 8; j++)
            #pragma unroll
            for (int q = 0; q < 4; q++) accS[j][q] = 0.f;

        const int arow = 16 * w + (lane & 15);
        const int ak   = (lane >> 4) * 8;
        const int brow = (lane & 7) + ((lane >> 4) << 3);
        const int bk   = ((lane >> 3) & 1) * 8;

        #pragma unroll
        for (int ks = 0; ks < 10; ks++) {
            uint32_t a[4], bfr[4][4];
            LDMATRIX_X4(a[0], a[1], a[2], a[3],
                        qb + arow * QK_STRB + (ks * 16 + ak) * 2);
            #pragma unroll
            for (int np = 0; np < 4; np++)
                LDMATRIX_X4(bfr[np][0], bfr[np][1], bfr[np][2], bfr[np][3],
                            kb + (brow + np * 16) * QK_STRB + (ks * 16 + bk) * 2);
            #pragma unroll
            for (int nt = 0; nt < 8; nt++)
                MMA16816(accS[nt], a, bfr[nt >> 1][(nt & 1) * 2], bfr[nt >> 1][(nt & 1) * 2 + 1]);
        }
        const int g = lane >> 2, tig = lane & 3;
        #pragma unroll
        for (int nt = 0; nt < 8; nt++) {
            #pragma unroll
            for (int h = 0; h < 2; h++) {
                int row = 16 * w + g + h * 8;
                Sf[row * SF_STR + nt * 8 + tig * 2]     = accS[nt][h * 2 + 0];
                Sf[row * SF_STR + nt * 8 + tig * 2 + 1] = accS[nt][h * 2 + 1];
            }
        }
    }
    __syncthreads();

    // ---- softmax + half conversion, warp-per-row (rows >=49 -> zeros)
    for (int r = w; r < 64; r += 4) {
        __half* dst = (__half*)(Shc + r * SH_STRB);
        if (r < 49) {
            float* row = Sf + r * SF_STR;
            float v0 = row[lane];
            bool hi = (lane + 32) < 49;
            float v1 = hi ? row[lane + 32] : -1e30f;
            float m = fmaxf(v0, v1);
            #pragma unroll
            for (int o = 16; o > 0; o >>= 1) m = fmaxf(m, __shfl_xor_sync(0xFFFFFFFFu, m, o));
            float e0 = __expf(v0 - m);
            float e1 = hi ? __expf(v1 - m) : 0.f;
            float s = e0 + e1;
            #pragma unroll
            for (int o = 16; o > 0; o >>= 1) s += __shfl_xor_sync(0xFFFFFFFFu, s, o);
            float inv = 1.f / s;
            dst[lane]      = __float2half_rn(e0 * inv);
            dst[lane + 32] = __float2half_rn(e1 * inv);
        } else {
            dst[lane]      = __ushort_as_half((unsigned short)0);
            dst[lane + 32] = __ushort_as_half((unsigned short)0);
        }
    }

    // ---- Phase B: O = S V, double-buffered chunks
    const int arow = lane & 15;
    const int ak   = (lane >> 4) * 8;
    const int kk_l = (lane & 7) + ((lane >> 3) & 1) * 8;
    const int nc_l = 32 * w + ((lane >> 4) << 3);
    const int g = lane >> 2, tig = lane & 3;

    for (int cc = 0; cc < 8; cc++) {
        if (cc + 1 < 8) {
            uint32_t nb = vbb + ((cc + 1) & 1) * V_BUFB;
            for (int idx = t; idx < 49 * 16; idx += 128) {
                int m = idx >> 4, u = idx & 15;
                int r = base + (m / 7) * 56 + (m % 7);
                CP_ASYNC16(nb + m * VC_STRB + u * 16,
                           (const char*)vh + (size_t)r * 2048 + (cc + 1) * 256 + u * 16);
            }
            CP_COMMIT();
            asm volatile("cp.async.wait_group 1;" ::: "memory");
        } else {
            asm volatile("cp.async.wait_group 0;" ::: "memory");
        }
        __syncthreads();

        const uint32_t vb = vbb + (cc & 1) * V_BUFB;
        float acc[4][4][4];
        #pragma unroll
        for (int i = 0; i < 4; i++)
            #pragma unroll
            for (int j = 0; j < 4; j++)
                #pragma unroll
                for (int q = 0; q < 4; q++) acc[i][j][q] = 0.f;

        #pragma unroll
        for (int ks = 0; ks < 4; ks++) {
            uint32_t a[4][4], bq[2][4];
            #pragma unroll
            for (int mt = 0; mt < 4; mt++)
                LDMATRIX_X4(a[mt][0], a[mt][1], a[mt][2], a[mt][3],
                            shb + (16 * mt + arow) * SH_STRB + (ks * 16 + ak) * 2);
            #pragma unroll
            for (int nb2 = 0; nb2 < 2; nb2++)
                LDMATRIX_X4_T(bq[nb2][0], bq[nb2][1], bq[nb2][2], bq[nb2][3],
                              vb + (ks * 16 + kk_l) * VC_STRB + (nc_l + nb2 * 16) * 2);
            #pragma unroll
            for (int mt = 0; mt < 4; mt++)
                #pragma unroll
                for (int nt = 0; nt < 4; nt++)
                    MMA16816(acc[mt][nt], a[mt],
                             bq[nt >> 1][(nt & 1) * 2], bq[nt >> 1][(nt & 1) * 2 + 1]);
        }

        #pragma unroll
        for (int mt = 0; mt < 4; mt++) {
            #pragma unroll
            for (int h = 0; h < 2; h++) {
                int m = 16 * mt + g + h * 8;
                if (m < 49) {
                    int r = base + (m / 7) * 56 + (m % 7);
                    __half* dst = ao + (size_t)r * CDIM + cc * 128;
                    #pragma unroll
                    for (int nt = 0; nt < 4; nt++) {
                        int n = 32 * w + nt * 8 + tig * 2;
                        *(__half2*)(dst + n) =
                            __floats2half2_rn(acc[mt][nt][h*2+0], acc[mt][nt][h*2+1]);
                    }
                }
            }
        }
        __syncthreads();
    }
}

// ============================================================
// Host launcher
// ============================================================
extern "C" void kernel_launch(void* const* d_in, const int* in_sizes, int n_in,
                              void* d_out, int out_size)
{
    const float* x      = (const float*)d_in[0];
    const float* norm_w = (const float*)d_in[1];
    const float* norm_b = (const float*)d_in[2];
    const float* wq     = (const float*)d_in[3];
    const float* bq     = (const float*)d_in[4];
    const float* wk     = (const float*)d_in[5];
    const float* bk     = (const float*)d_in[6];
    const float* wv     = (const float*)d_in[7];
    const float* bv     = (const float*)d_in[8];
    const float* wr     = (const float*)d_in[9];
    const float* br     = (const float*)d_in[10];
    const float* gamma  = (const float*)d_in[11];
    (void)in_sizes; (void)n_in; (void)out_size;

    float* out  = (float*)d_out;
    float* sem  = out;                              // [50176, 150]
    float* xout = out + (size_t)M_ROWS * KSEM;      // [50176, 1024]

    __half *xnh, *semh, *kfh, *aoh, *wqkh, *wrh, *wvth, *wch;
    float* bvr;
    cudaGetSymbolAddress((void**)&xnh,  g_xnh);
    cudaGetSymbolAddress((void**)&semh, g_semh);
    cudaGetSymbolAddress((void**)&kfh,  g_kfh);
    cudaGetSymbolAddress((void**)&aoh,  g_aoh);
    cudaGetSymbolAddress((void**)&wqkh, g_wqkh);
    cudaGetSymbolAddress((void**)&wrh,  g_wrh);
    cudaGetSymbolAddress((void**)&wvth, g_wvth);
    cudaGetSymbolAddress((void**)&wch,  g_wch);
    cudaGetSymbolAddress((void**)&bvr,  g_bvr);

    const int SMEM256 = 3 * 49152 + 1024;  // 148480
    const int SMEM160 = 3 * 36864 + 1024;  // 111616
    const int SMEM128 = 3 * 32768 + 1024;  // 99328
    cudaFuncSetAttribute(gemm_h<1, 256, 4>, cudaFuncAttributeMaxDynamicSharedMemorySize, SMEM256);
    cudaFuncSetAttribute(gemm_h<2, 160, 2>, cudaFuncAttributeMaxDynamicSharedMemorySize, SMEM160);
    cudaFuncSetAttribute(gemm_h<4, 128, 2>, cudaFuncAttributeMaxDynamicSharedMemorySize, SMEM128);
    cudaFuncSetAttribute(attn_mma, cudaFuncAttributeMaxDynamicSharedMemorySize, ATTN_SMEM);

    // 0+1) merged prep + LayerNorm (prep blocks first, LN blocks after)
    ln_prep_kernel<<<PREP_BLOCKS + M_ROWS, 256>>>(x, norm_w, norm_b, xnh,
                                                  wq, wk, wr, wv, bv, br, gamma,
                                                  wqkh, wrh, wvth, bvr, semh, kfh);

    // Wc = gamma * Wr @ Wv (half)
    gemm_h<4, 128, 2><<<dim3(8, 8), 256, SMEM128>>>(wrh, wvth, nullptr, nullptr,
                                                    nullptr, wch, nullptr, CDIM, CDIM, nullptr, gamma);

    // 2) merged Q/K projection (N=300, padded 320, BN=160 x 2 tiles)
    gemm_h<2, 160, 2><<<dim3(2, M_ROWS / 128), 256, SMEM160>>>(xnh, wqkh, bq, bk, sem, semh, kfh,
                                                               300, KSEM, nullptr, nullptr);

    // 3) attention: aoh = softmax(QK^T) @ xnh
    attn_mma<<<NWIN, 128, ATTN_SMEM>>>(semh, kfh, xnh, aoh);

    // 4) xout = aoh @ Wc^T + bvr + xnh
    gemm_h<1, 256, 4><<<dim3(4, M_ROWS / 128), 256, SMEM256>>>(aoh, wch, bvr, nullptr, xout,
                                                               nullptr, nullptr, CDIM, CDIM, xnh, nullptr);
}

// round 11
// speedup vs baseline: 10.9260x; 1.0213x over previous
#include <cuda_runtime.h>
#include <cuda_fp16.h>
#include <cstdint>
#include <cstddef>

// Problem constants (B=16, H=W=56, C=1024, K=150, WS=7)
#define M_ROWS 50176
#define CDIM   1024
#define KSEM   150
#define NWIN   1024
#define BATCH_STRIDE 3136

// -------- scratch (device globals) --------
__device__ __half g_xnh [(size_t)M_ROWS * CDIM];   // LN out half
__device__ __half g_semh[(size_t)M_ROWS * 160];    // seg_map half, padded stride
__device__ __half g_kfh [(size_t)M_ROWS * 160];    // seg_ft half, padded stride
__device__ __half g_aoh [(size_t)M_ROWS * CDIM];   // attention out half
__device__ __half g_wqkh[(size_t)300 * CDIM];      // wq(150) + wk(150) stacked
__device__ __half g_wrh [(size_t)CDIM * CDIM];     // wr half
__device__ __half g_wvth[(size_t)CDIM * CDIM];     // wv^T half
__device__ __half g_wch [(size_t)CDIM * CDIM];     // Wc = gamma * Wr @ Wv, half
__device__ float  g_bvr [CDIM];                    // gamma * (Wr @ bv + br)

__device__ __forceinline__ uint32_t smem_to_u32(const void* p) {
    uint32_t a;
    asm("{ .reg .u64 t; cvta.to.shared.u64 t, %1; cvt.u32.u64 %0, t; }" : "=r"(a) : "l"(p));
    return a;
}
#define CP_ASYNC16(dst, src) \
    asm volatile("cp.async.cg.shared.global [%0], [%1], 16;" :: "r"(dst), "l"(src) : "memory")
#define CP_COMMIT() asm volatile("cp.async.commit_group;" ::: "memory")
#define LDMATRIX_X4(r0, r1, r2, r3, addr) \
    asm volatile("ldmatrix.sync.aligned.m8n8.x4.shared.b16 {%0,%1,%2,%3}, [%4];" \
        : "=r"(r0), "=r"(r1), "=r"(r2), "=r"(r3) : "r"(addr))
#define LDMATRIX_X4_T(r0, r1, r2, r3, addr) \
    asm volatile("ldmatrix.sync.aligned.m8n8.x4.trans.shared.b16 {%0,%1,%2,%3}, [%4];" \
        : "=r"(r0), "=r"(r1), "=r"(r2), "=r"(r3) : "r"(addr))
#define MMA16816(acc, a, b0, b1) \
    asm volatile("mma.sync.aligned.m16n8k16.row.col.f32.f16.f16.f32 " \
        "{%0,%1,%2,%3}, {%4,%5,%6,%7}, {%8,%9}, {%0,%1,%2,%3};" \
        : "+f"((acc)[0]), "+f"((acc)[1]), "+f"((acc)[2]), "+f"((acc)[3]) \
        : "r"((a)[0]), "r"((a)[1]), "r"((a)[2]), "r"((a)[3]), "r"(b0), "r"(b1))

// ============================================================
// Merged LN + prep kernel (unchanged from R10)
// ============================================================
#define PREP_BLOCKS 2548

__global__ __launch_bounds__(256)
void ln_prep_kernel(const float* __restrict__ x, const float* __restrict__ norm_w,
                    const float* __restrict__ norm_b, __half* __restrict__ outh,
                    const float* __restrict__ wq, const float* __restrict__ wk,
                    const float* __restrict__ wr, const float* __restrict__ wv,
                    const float* __restrict__ bv, const float* __restrict__ br,
                    const float* __restrict__ gammap,
                    __half* __restrict__ wqkh, __half* __restrict__ wrh,
                    __half* __restrict__ wvth, float* __restrict__ bvr,
                    __half* __restrict__ semh, __half* __restrict__ kfh)
{
    __shared__ float tile[32][33];
    __shared__ float red[2][8];
    int bid = blockIdx.x;
    int t = threadIdx.x;

    if (bid >= PREP_BLOCKS) {
        int row = bid - PREP_BLOCKS;
        const float4* xr = (const float4*)(x + (size_t)row * CDIM);
        float4 v = xr[t];
        float s  = v.x + v.y + v.z + v.w;
        float sq = v.x*v.x + v.y*v.y + v.z*v.z + v.w*v.w;
        #pragma unroll
        for (int o = 16; o > 0; o >>= 1) {
            s  += __shfl_xor_sync(0xFFFFFFFFu, s,  o);
            sq += __shfl_xor_sync(0xFFFFFFFFu, sq, o);
        }
        int wid = t >> 5, lid = t & 31;
        if (lid == 0) { red[0][wid] = s; red[1][wid] = sq; }
        __syncthreads();
        float st = 0.f, sqt = 0.f;
        #pragma unroll
        for (int i = 0; i < 8; i++) { st += red[0][i]; sqt += red[1][i]; }
        float mu   = st * (1.0f / CDIM);
        float var  = sqt * (1.0f / CDIM) - mu * mu;
        float rstd = rsqrtf(var + 1e-5f);
        float4 wv4 = ((const float4*)norm_w)[t];
        float4 bv4 = ((const float4*)norm_b)[t];
        float4 o;
        o.x = (v.x - mu) * rstd * wv4.x + bv4.x;
        o.y = (v.y - mu) * rstd * wv4.y + bv4.y;
        o.z = (v.z - mu) * rstd * wv4.z + bv4.z;
        o.w = (v.w - mu) * rstd * wv4.w + bv4.w;
        __half2* hp = (__half2*)(outh + (size_t)row * CDIM + t * 4);
        hp[0] = __floats2half2_rn(o.x, o.y);
        hp[1] = __floats2half2_rn(o.z, o.w);
    } else if (bid < 300) {
        const float* in = (bid < 150) ? wq : wk;
        __half* out = wqkh + (bid < 150 ? 0 : (size_t)150 * CDIM);
        int i = (bid % 150) * 1024 + t * 4;
        float4 v = *(const float4*)(in + i);
        *(__half2*)(out + i)     = __floats2half2_rn(v.x, v.y);
        *(__half2*)(out + i + 2) = __floats2half2_rn(v.z, v.w);
    } else if (bid < 1324) {
        int i = (bid - 300) * 1024 + t * 4;
        float4 v = *(const float4*)(wr + i);
        *(__half2*)(wrh + i)     = __floats2half2_rn(v.x, v.y);
        *(__half2*)(wrh + i + 2) = __floats2half2_rn(v.z, v.w);
    } else if (bid < 2348) {
        int idx = bid - 1324;
        int bx = idx & 31, by = idx >> 5;
        int tx = t & 31, ty = t >> 5;
        int xx = bx * 32 + tx;
        int y0 = by * 32 + ty;
        #pragma unroll
        for (int i = 0; i < 32; i += 8)
            tile[ty + i][tx] = wv[(size_t)(y0 + i) * CDIM + xx];
        __syncthreads();
        int x2 = by * 32 + tx;
        int y2 = bx * 32 + ty;
        #pragma unroll
        for (int i = 0; i < 32; i += 8)
            wvth[(size_t)(y2 + i) * CDIM + x2] = __float2half_rn(tile[tx][ty + i]);
    } else if (bid < 2352) {
        int i = (bid - 2348) * 256 + t;
        const float4* w4 = (const float4*)(wr + (size_t)i * CDIM);
        const float4* b4 = (const float4*)bv;
        float s = 0.f;
        #pragma unroll 8
        for (int k = 0; k < 256; k++) {
            float4 a = w4[k], b = b4[k];
            s += a.x * b.x + a.y * b.y + a.z * b.z + a.w * b.w;
        }
        bvr[i] = gammap[0] * (s + br[i]);
    } else {
        int r = (bid - 2352) * 256 + t;
        if (r < M_ROWS) {
            __half2 z = __floats2half2_rn(0.f, 0.f);
            __half2* pa = (__half2*)(semh + (size_t)r * 160 + 150);
            __half2* pb = (__half2*)(kfh  + (size_t)r * 160 + 150);
            #pragma unroll
            for (int i = 0; i < 5; i++) { pa[i] = z; pb[i] = z; }
        }
    }
}

// ============================================================
// fp16 mma.sync GEMM (unchanged from R10)
// ============================================================
template<int MODE, int BN, int WN>
__global__ __launch_bounds__(256, 1)
void gemm_h(const __half* __restrict__ A, const __half* __restrict__ W,
            const float* __restrict__ bias0, const float* __restrict__ bias1,
            float* __restrict__ C0, __half* __restrict__ H0, __half* __restrict__ H1,
            int Nvalid, int ldc,
            const __half* __restrict__ residh, const float* __restrict__ gammap)
{
    constexpr int S = 3;
    constexpr int A_BYTES = 128 * 128;
    constexpr int B_BYTES = BN * 128;
    constexpr int STAGE = A_BYTES + B_BYTES;
    constexpr int NITER = CDIM / 64;
    constexpr int BLD = BN / 32;
    constexpr int WM  = 8 / WN;
    constexpr int MT  = 128 / (WM * 16);
    constexpr int NT  = BN / (WN * 8);
    constexpr int NB2 = (NT + 1) / 2;

    extern __shared__ char smem_raw[];
    char* tiles = (char*)(((uintptr_t)smem_raw + 1023) & ~(uintptr_t)1023);
    const uint32_t base = smem_to_u32(tiles);

    const int tid = threadIdx.x;
    const int m0  = blockIdx.y * 128;
    const int n0  = blockIdx.x * BN;
    const int vrows = (Nvalid - n0 < BN) ? (Nvalid - n0) : BN;

    if (vrows < BN) {
        #pragma unroll
        for (int s = 0; s < S; s++) {
            float4* z = (float4*)(tiles + s * STAGE + A_BYTES + vrows * 128);
            int cnt = (BN - vrows) * 8;
            for (int i = tid; i < cnt; i += 256) z[i] = make_float4(0.f, 0.f, 0.f, 0.f);
        }
        __syncthreads();
    }

    auto load_stage = [&](int c) {
        int st = c % S;
        uint32_t as = base + st * STAGE;
        uint32_t bs = as + A_BYTES;
        const char* Ag = (const char*)A + (size_t)m0 * (CDIM * 2) + c * 128;
        const char* Wg = (const char*)W + (size_t)n0 * (CDIM * 2) + c * 128;
        #pragma unroll
        for (int i = 0; i < 4; i++) {
            int idx = tid + i * 256;
            int r = idx >> 3, u = idx & 7;
            CP_ASYNC16(as + r * 128 + ((u ^ (r & 7)) << 4),
                       Ag + (size_t)r * (CDIM * 2) + u * 16);
        }
        #pragma unroll
        for (int i = 0; i < BLD; i++) {
            int idx = tid + i * 256;
            int r = idx >> 3, u = idx & 7;
            if (r < vrows)
                CP_ASYNC16(bs + r * 128 + ((u ^ (r & 7)) << 4),
                           Wg + (size_t)r * (CDIM * 2) + u * 16);
        }
        CP_COMMIT();
    };

    load_stage(0);
    load_stage(1);

    float acc[MT][NT][4];
    #pragma unroll
    for (int i = 0; i < MT; i++)
        #pragma unroll
        for (int j = 0; j < NT; j++)
            #pragma unroll
            for (int q = 0; q < 4; q++) acc[i][j][q] = 0.f;

    const int lane = tid & 31;
    const int wid  = tid >> 5;
    const int wm = (wid & (WM - 1)) * (128 / WM);
    const int wn = (wid / WM) * (NT * 8);

    const int arow_l = wm + (lane & 15);
    const int au_l   = lane >> 4;
    const int brow_l = wn + (lane & 7) + ((lane >> 4) << 3);
    const int bu_l   = (lane >> 3) & 1;

    for (int it = 0; it < NITER; it++) {
        asm volatile("cp.async.wait_group 1;" ::: "memory");
        __syncthreads();
        if (it + 2 < NITER) load_stage(it + 2);

        uint32_t as = base + (it % S) * STAGE;
        uint32_t bs = as + A_BYTES;
        #pragma unroll
        for (int kk = 0; kk < 4; kk++) {
            uint32_t a[MT][4], b[NB2][4];
            #pragma unroll
            for (int mt = 0; mt < MT; mt++) {
                int row = arow_l + mt * 16;
                int u = kk * 2 + au_l;
                LDMATRIX_X4(a[mt][0], a[mt][1], a[mt][2], a[mt][3],
                            as + row * 128 + ((u ^ (row & 7)) << 4));
            }
            #pragma unroll
            for (int np = 0; np < NB2; np++) {
                int row = brow_l + np * 16;
                int u = kk * 2 + bu_l;
                LDMATRIX_X4(b[np][0], b[np][1], b[np][2], b[np][3],
                            bs + row * 128 + ((u ^ (row & 7)) << 4));
            }
            #pragma unroll
            for (int mt = 0; mt < MT; mt++)
                #pragma unroll
                for (int nt = 0; nt < NT; nt++)
                    MMA16816(acc[mt][nt], a[mt],
                             b[nt >> 1][(nt & 1) * 2], b[nt >> 1][(nt & 1) * 2 + 1]);
        }
    }

    const int g = lane >> 2, tig = lane & 3;
    #pragma unroll
    for (int mt = 0; mt < MT; mt++) {
        #pragma unroll
        for (int nt = 0; nt < NT; nt++) {
            int m = m0 + wm + mt * 16 + g;
            int n = n0 + wn + nt * 8 + tig * 2;
            if (MODE == 2) {
                if (n >= Nvalid) continue;
                #pragma unroll
                for (int h = 0; h < 2; h++) {
                    int mr = m + h * 8;
                    float v0, v1;
                    if (n < 150) {
                        v0 = acc[mt][nt][h*2+0] + bias0[n];
                        v1 = acc[mt][nt][h*2+1] + bias0[n + 1];
                        C0[(size_t)mr * 150 + n]     = v0;
                        C0[(size_t)mr * 150 + n + 1] = v1;
                        *(__half2*)(H0 + (size_t)mr * 160 + n) = __floats2half2_rn(v0, v1);
                    } else {
                        int nn = n - 150;
                        v0 = acc[mt][nt][h*2+0] + bias1[nn];
                        v1 = acc[mt][nt][h*2+1] + bias1[nn + 1];
                        *(__half2*)(H1 + (size_t)mr * 160 + nn) = __floats2half2_rn(v0, v1);
                    }
                }
            } else if (MODE == 4) {
                float gm = gammap[0];
                #pragma unroll
                for (int h = 0; h < 2; h++) {
                    int mr = m + h * 8;
                    *(__half2*)(H0 + (size_t)mr * ldc + n) =
                        __floats2half2_rn(gm * acc[mt][nt][h*2+0], gm * acc[mt][nt][h*2+1]);
                }
            } else { // MODE 1
                float b0 = bias0[n], b1 = bias0[n + 1];
                #pragma unroll
                for (int h = 0; h < 2; h++) {
                    int mr = m + h * 8;
                    __half2 rv = *(const __half2*)(residh + (size_t)mr * CDIM + n);
                    float v0 = acc[mt][nt][h*2+0] + b0 + __low2float(rv);
                    float v1 = acc[mt][nt][h*2+1] + b1 + __high2float(rv);
                    *(float2*)(C0 + (size_t)mr * ldc + n) = make_float2(v0, v1);
                }
            }
        }
    }
}

// ============================================================
// HMMA attention: 2 windows per block, register softmax,
// cross-window QK prefetch, double-buffered V.
// smem: Qc 64x336, Kc 64x336, Sh 64x144B, V 2 x 64x272 = 87040B
// ============================================================
#define QK_STRB 336
#define SH_STRB 144
#define VC_STRB 272
#define SH_OFF  43008
#define V_OFF   52224
#define V_BUFB  17408
#define ATTN_SMEM (52224 + 2 * 17408)  // 87040

__global__ __launch_bounds__(128)
void attn_mma(const __half* __restrict__ semh, const __half* __restrict__ kfh,
              const __half* __restrict__ vh, __half* __restrict__ ao)
{
    extern __shared__ char sm[];
    char* Qc  = sm;
    char* Kc  = sm + 21504;
    char* Shc = sm + SH_OFF;
    char* Vb0 = sm + V_OFF;

    const uint32_t qb  = smem_to_u32(Qc);
    const uint32_t kb  = smem_to_u32(Kc);
    const uint32_t shb = smem_to_u32(Shc);
    const uint32_t vbb = smem_to_u32(Vb0);

    int t = threadIdx.x;
    const int lane = t & 31, w = t >> 5;
    const int g = lane >> 2, tig = lane & 3;

    auto win_base = [](int wi) {
        int b  = wi >> 6;
        int wh = (wi >> 3) & 7;
        int ww = wi & 7;
        return b * BATCH_STRIDE + wh * 7 * 56 + ww * 7;
    };
    auto issue_qk = [&](int base) {
        for (int idx = t; idx < 1960; idx += 128) {
            int which = idx >= 980;
            int i2 = idx - which * 980;
            int n = i2 / 20, u = i2 % 20;
            int r = base + (n / 7) * 56 + (n % 7);
            uint32_t dst = (which ? kb : qb) + n * QK_STRB + u * 16;
            const char* src = (const char*)(which ? kfh : semh) + (size_t)r * 320 + u * 16;
            CP_ASYNC16(dst, src);
        }
        CP_COMMIT();
    };
    auto issue_v = [&](int base, int cc) {
        uint32_t nb = vbb + (cc & 1) * V_BUFB;
        for (int idx = t; idx < 49 * 16; idx += 128) {
            int m = idx >> 4, u = idx & 15;
            int r = base + (m / 7) * 56 + (m % 7);
            CP_ASYNC16(nb + m * VC_STRB + u * 16,
                       (const char*)vh + (size_t)r * 2048 + cc * 256 + u * 16);
        }
        CP_COMMIT();
    };

    // ---- one-time pad zeroing (rows 49..63 of Qc/Kc and both V buffers)
    for (int i = t; i < 630; i += 128) {
        char* buf = (i < 315) ? Qc : Kc;
        int idx = (i < 315) ? i : i - 315;
        int row = 49 + idx / 21, u = idx % 21;
        ((float4*)(buf + row * QK_STRB))[u] = make_float4(0.f, 0.f, 0.f, 0.f);
    }
    for (int i = t; i < 510; i += 128) {
        int bsel = i >= 255;
        int idx = i - bsel * 255;
        int row = 49 + idx / 17, u = idx % 17;
        ((float4*)(Vb0 + bsel * V_BUFB + row * VC_STRB))[u] = make_float4(0.f, 0.f, 0.f, 0.f);
    }

    const int wi0 = blockIdx.x * 2;
    issue_qk(win_base(wi0));

    for (int wl = 0; wl < 2; wl++) {
        const int base = win_base(wi0 + wl);
        // V chunk 0 of this window (QK of this window already in flight/loaded)
        issue_v(base, 0);
        if (wl == 0) {
            asm volatile("cp.async.wait_group 0;" ::: "memory");  // QK + V0 ready
        }
        // for wl==1: QK arrived during prev window's Phase B (wait_group 0 at end);
        // V0 still in flight, not needed until Phase B.
        __syncthreads();

        // ---- Phase A: S = Q K^T (rows 16w..16w+15 x 64 keys per warp)
        float accS[8][4];
        #pragma unroll
        for (int j = 0; j < 8; j++)
            #pragma unroll
            for (int q = 0; q < 4; q++) accS[j][q] = 0.f;
        {
            const int arow = 16 * w + (lane & 15);
            const int ak   = (lane >> 4) * 8;
            const int brow = (lane & 7) + ((lane >> 4) << 3);
            const int bk   = ((lane >> 3) & 1) * 8;
            #pragma unroll
            for (int ks = 0; ks < 10; ks++) {
                uint32_t a[4], bfr[4][4];
                LDMATRIX_X4(a[0], a[1], a[2], a[3],
                            qb + arow * QK_STRB + (ks * 16 + ak) * 2);
                #pragma unroll
                for (int np = 0; np < 4; np++)
                    LDMATRIX_X4(bfr[np][0], bfr[np][1], bfr[np][2], bfr[np][3],
                                kb + (brow + np * 16) * QK_STRB + (ks * 16 + bk) * 2);
                #pragma unroll
                for (int nt = 0; nt < 8; nt++)
                    MMA16816(accS[nt], a, bfr[nt >> 1][(nt & 1) * 2], bfr[nt >> 1][(nt & 1) * 2 + 1]);
            }
        }

        // ---- register softmax (quad shfl) + write half S to Shc
        {
            int r0 = 16 * w + g;      // rows r0 and r0+8
            float m0 = -1e30f, m1 = -1e30f;
            #pragma unroll
            for (int nt = 0; nt < 8; nt++)
                #pragma unroll
                for (int e = 0; e < 2; e++) {
                    int c = nt * 8 + tig * 2 + e;
                    if (c < 49) {
                        m0 = fmaxf(m0, accS[nt][e]);
                        m1 = fmaxf(m1, accS[nt][2 + e]);
                    }
                }
            m0 = fmaxf(m0, __shfl_xor_sync(0xFFFFFFFFu, m0, 1));
            m0 = fmaxf(m0, __shfl_xor_sync(0xFFFFFFFFu, m0, 2));
            m1 = fmaxf(m1, __shfl_xor_sync(0xFFFFFFFFu, m1, 1));
            m1 = fmaxf(m1, __shfl_xor_sync(0xFFFFFFFFu, m1, 2));
            float s0 = 0.f, s1 = 0.f;
            #pragma unroll
            for (int nt = 0; nt < 8; nt++)
                #pragma unroll
                for (int e = 0; e < 2; e++) {
                    int c = nt * 8 + tig * 2 + e;
                    float e0 = 0.f, e1 = 0.f;
                    if (c < 49) {
                        e0 = __expf(accS[nt][e]     - m0);
                        e1 = __expf(accS[nt][2 + e] - m1);
                    }
                    accS[nt][e] = e0;     s0 += e0;
                    accS[nt][2 + e] = e1; s1 += e1;
                }
            s0 += __shfl_xor_sync(0xFFFFFFFFu, s0, 1);
            s0 += __shfl_xor_sync(0xFFFFFFFFu, s0, 2);
            s1 += __shfl_xor_sync(0xFFFFFFFFu, s1, 1);
            s1 += __shfl_xor_sync(0xFFFFFFFFu, s1, 2);
            float inv0 = 1.f / s0, inv1 = 1.f / s1;
            __half2* d0 = (__half2*)(Shc + r0 * SH_STRB + tig * 4);
            __half2* d1 = (__half2*)(Shc + (r0 + 8) * SH_STRB + tig * 4);
            #pragma unroll
            for (int nt = 0; nt < 8; nt++) {
                __half2 h0 = (r0 < 49)
                    ? __floats2half2_rn(accS[nt][0] * inv0, accS[nt][1] * inv0)
                    : __floats2half2_rn(0.f, 0.f);
                __half2 h1 = (r0 + 8 < 49)
                    ? __floats2half2_rn(accS[nt][2] * inv1, accS[nt][3] * inv1)
                    : __floats2half2_rn(0.f, 0.f);
                d0[nt * 4] = h0;
                d1[nt * 4] = h1;
            }
        }
        __syncthreads();  // Shc visible; Qc/Kc free for prefetch

        // ---- Phase B: O = S V, double-buffered; prefetch next QK at cc==0
        const int arow = lane & 15;
        const int ak   = (lane >> 4) * 8;
        const int kk_l = (lane & 7) + ((lane >> 3) & 1) * 8;
        const int nc_l = 32 * w + ((lane >> 4) << 3);

        for (int cc = 0; cc < 8; cc++) {
            if (cc + 1 < 8) {
                issue_v(base, cc + 1);
                if (cc == 0 && wl == 0) issue_qk(win_base(wi0 + 1));
                asm volatile("cp.async.wait_group 1;" ::: "memory");
            } else {
                asm volatile("cp.async.wait_group 0;" ::: "memory");
            }
            __syncthreads();

            const uint32_t vb = vbb + (cc & 1) * V_BUFB;
            float acc[4][4][4];
            #pragma unroll
            for (int i = 0; i < 4; i++)
                #pragma unroll
                for (int j = 0; j < 4; j++)
                    #pragma unroll
                    for (int q = 0; q < 4; q++) acc[i][j][q] = 0.f;

            #pragma unroll
            for (int ks = 0; ks < 4; ks++) {
                uint32_t a[4][4], bq[2][4];
                #pragma unroll
                for (int mt = 0; mt < 4; mt++)
                    LDMATRIX_X4(a[mt][0], a[mt][1], a[mt][2], a[mt][3],
                                shb + (16 * mt + arow) * SH_STRB + (ks * 16 + ak) * 2);
                #pragma unroll
                for (int nb2 = 0; nb2 < 2; nb2++)
                    LDMATRIX_X4_T(bq[nb2][0], bq[nb2][1], bq[nb2][2], bq[nb2][3],
                                  vb + (ks * 16 + kk_l) * VC_STRB + (nc_l + nb2 * 16) * 2);
                #pragma unroll
                for (int mt = 0; mt < 4; mt++)
                    #pragma unroll
                    for (int nt = 0; nt < 4; nt++)
                        MMA16816(acc[mt][nt], a[mt],
                                 bq[nt >> 1][(nt & 1) * 2], bq[nt >> 1][(nt & 1) * 2 + 1]);
            }

            #pragma unroll
            for (int mt = 0; mt < 4; mt++) {
                #pragma unroll
                for (int h = 0; h < 2; h++) {
                    int m = 16 * mt + g + h * 8;
                    if (m < 49) {
                        int r = base + (m / 7) * 56 + (m % 7);
                        __half* dst = ao + (size_t)r * CDIM + cc * 128;
                        #pragma unroll
                        for (int nt = 0; nt < 4; nt++) {
                            int n = 32 * w + nt * 8 + tig * 2;
                            *(__half2*)(dst + n) =
                                __floats2half2_rn(acc[mt][nt][h*2+0], acc[mt][nt][h*2+1]);
                        }
                    }
                }
            }
            __syncthreads();
        }
    }
}

// ============================================================
// Host launcher
// ============================================================
extern "C" void kernel_launch(void* const* d_in, const int* in_sizes, int n_in,
                              void* d_out, int out_size)
{
    const float* x      = (const float*)d_in[0];
    const float* norm_w = (const float*)d_in[1];
    const float* norm_b = (const float*)d_in[2];
    const float* wq     = (const float*)d_in[3];
    const float* bq     = (const float*)d_in[4];
    const float* wk     = (const float*)d_in[5];
    const float* bk     = (const float*)d_in[6];
    const float* wv     = (const float*)d_in[7];
    const float* bv     = (const float*)d_in[8];
    const float* wr     = (const float*)d_in[9];
    const float* br     = (const float*)d_in[10];
    const float* gamma  = (const float*)d_in[11];
    (void)in_sizes; (void)n_in; (void)out_size;

    float* out  = (float*)d_out;
    float* sem  = out;
    float* xout = out + (size_t)M_ROWS * KSEM;

    __half *xnh, *semh, *kfh, *aoh, *wqkh, *wrh, *wvth, *wch;
    float* bvr;
    cudaGetSymbolAddress((void**)&xnh,  g_xnh);
    cudaGetSymbolAddress((void**)&semh, g_semh);
    cudaGetSymbolAddress((void**)&kfh,  g_kfh);
    cudaGetSymbolAddress((void**)&aoh,  g_aoh);
    cudaGetSymbolAddress((void**)&wqkh, g_wqkh);
    cudaGetSymbolAddress((void**)&wrh,  g_wrh);
    cudaGetSymbolAddress((void**)&wvth, g_wvth);
    cudaGetSymbolAddress((void**)&wch,  g_wch);
    cudaGetSymbolAddress((void**)&bvr,  g_bvr);

    const int SMEM256 = 3 * 49152 + 1024;
    const int SMEM160 = 3 * 36864 + 1024;
    const int SMEM128 = 3 * 32768 + 1024;
    cudaFuncSetAttribute(gemm_h<1, 256, 4>, cudaFuncAttributeMaxDynamicSharedMemorySize, SMEM256);
    cudaFuncSetAttribute(gemm_h<2, 160, 2>, cudaFuncAttributeMaxDynamicSharedMemorySize, SMEM160);
    cudaFuncSetAttribute(gemm_h<4, 128, 2>, cudaFuncAttributeMaxDynamicSharedMemorySize, SMEM128);
    cudaFuncSetAttribute(attn_mma, cudaFuncAttributeMaxDynamicSharedMemorySize, ATTN_SMEM);

    // 0+1) merged prep + LayerNorm
    ln_prep_kernel<<<PREP_BLOCKS + M_ROWS, 256>>>(x, norm_w, norm_b, xnh,
                                                  wq, wk, wr, wv, bv, br, gamma,
                                                  wqkh, wrh, wvth, bvr, semh, kfh);

    // Wc = gamma * Wr @ Wv (half)
    gemm_h<4, 128, 2><<<dim3(8, 8), 256, SMEM128>>>(wrh, wvth, nullptr, nullptr,
                                                    nullptr, wch, nullptr, CDIM, CDIM, nullptr, gamma);

    // 2) merged Q/K projection
    gemm_h<2, 160, 2><<<dim3(2, M_ROWS / 128), 256, SMEM160>>>(xnh, wqkh, bq, bk, sem, semh, kfh,
                                                               300, KSEM, nullptr, nullptr);

    // 3) attention: 2 windows per block
    attn_mma<<<NWIN / 2, 128, ATTN_SMEM>>>(semh, kfh, xnh, aoh);

    // 4) xout = aoh @ Wc^T + bvr + xnh
    gemm_h<1, 256, 4><<<dim3(4, M_ROWS / 128), 256, SMEM256>>>(aoh, wch, bvr, nullptr, xout,
                                                               nullptr, nullptr, CDIM, CDIM, xnh, nullptr);
}

// round 12
// speedup vs baseline: 11.1113x; 1.0170x over previous
#include <cuda_runtime.h>
#include <cuda_fp16.h>
#include <cstdint>
#include <cstddef>

// Problem constants (B=16, H=W=56, C=1024, K=150, WS=7)
#define M_ROWS 50176
#define CDIM   1024
#define KSEM   150
#define NWIN   1024
#define BATCH_STRIDE 3136

// -------- scratch (device globals) --------
__device__ __half g_xnh [(size_t)M_ROWS * CDIM];   // LN out half
__device__ __half g_semh[(size_t)M_ROWS * 160];    // seg_map half, padded stride
__device__ __half g_kfh [(size_t)M_ROWS * 160];    // seg_ft half, padded stride
__device__ __half g_aoh [(size_t)M_ROWS * CDIM];   // attention out half
__device__ __half g_wqkh[(size_t)300 * CDIM];      // wq(150) + wk(150) stacked
__device__ __half g_wrh [(size_t)CDIM * CDIM];     // wr half
__device__ __half g_wvth[(size_t)CDIM * CDIM];     // wv^T half
__device__ __half g_wch [(size_t)CDIM * CDIM];     // Wc = gamma * Wr @ Wv, half
__device__ float  g_bvr [CDIM];                    // gamma * (Wr @ bv + br)

__device__ __forceinline__ uint32_t smem_to_u32(const void* p) {
    uint32_t a;
    asm("{ .reg .u64 t; cvta.to.shared.u64 t, %1; cvt.u32.u64 %0, t; }" : "=r"(a) : "l"(p));
    return a;
}
#define CP_ASYNC16(dst, src) \
    asm volatile("cp.async.cg.shared.global [%0], [%1], 16;" :: "r"(dst), "l"(src) : "memory")
#define CP_COMMIT() asm volatile("cp.async.commit_group;" ::: "memory")
#define LDMATRIX_X4(r0, r1, r2, r3, addr) \
    asm volatile("ldmatrix.sync.aligned.m8n8.x4.shared.b16 {%0,%1,%2,%3}, [%4];" \
        : "=r"(r0), "=r"(r1), "=r"(r2), "=r"(r3) : "r"(addr))
#define LDMATRIX_X4_T(r0, r1, r2, r3, addr) \
    asm volatile("ldmatrix.sync.aligned.m8n8.x4.trans.shared.b16 {%0,%1,%2,%3}, [%4];" \
        : "=r"(r0), "=r"(r1), "=r"(r2), "=r"(r3) : "r"(addr))
#define MMA16816(acc, a, b0, b1) \
    asm volatile("mma.sync.aligned.m16n8k16.row.col.f32.f16.f16.f32 " \
        "{%0,%1,%2,%3}, {%4,%5,%6,%7}, {%8,%9}, {%0,%1,%2,%3};" \
        : "+f"((acc)[0]), "+f"((acc)[1]), "+f"((acc)[2]), "+f"((acc)[3]) \
        : "r"((a)[0]), "r"((a)[1]), "r"((a)[2]), "r"((a)[3]), "r"(b0), "r"(b1))

// ============================================================
// Merged LN + prep kernel (unchanged)
// ============================================================
#define PREP_BLOCKS 2548

__global__ __launch_bounds__(256)
void ln_prep_kernel(const float* __restrict__ x, const float* __restrict__ norm_w,
                    const float* __restrict__ norm_b, __half* __restrict__ outh,
                    const float* __restrict__ wq, const float* __restrict__ wk,
                    const float* __restrict__ wr, const float* __restrict__ wv,
                    const float* __restrict__ bv, const float* __restrict__ br,
                    const float* __restrict__ gammap,
                    __half* __restrict__ wqkh, __half* __restrict__ wrh,
                    __half* __restrict__ wvth, float* __restrict__ bvr,
                    __half* __restrict__ semh, __half* __restrict__ kfh)
{
    __shared__ float tile[32][33];
    __shared__ float red[2][8];
    int bid = blockIdx.x;
    int t = threadIdx.x;

    if (bid >= PREP_BLOCKS) {
        int row = bid - PREP_BLOCKS;
        const float4* xr = (const float4*)(x + (size_t)row * CDIM);
        float4 v = xr[t];
        float s  = v.x + v.y + v.z + v.w;
        float sq = v.x*v.x + v.y*v.y + v.z*v.z + v.w*v.w;
        #pragma unroll
        for (int o = 16; o > 0; o >>= 1) {
            s  += __shfl_xor_sync(0xFFFFFFFFu, s,  o);
            sq += __shfl_xor_sync(0xFFFFFFFFu, sq, o);
        }
        int wid = t >> 5, lid = t & 31;
        if (lid == 0) { red[0][wid] = s; red[1][wid] = sq; }
        __syncthreads();
        float st = 0.f, sqt = 0.f;
        #pragma unroll
        for (int i = 0; i < 8; i++) { st += red[0][i]; sqt += red[1][i]; }
        float mu   = st * (1.0f / CDIM);
        float var  = sqt * (1.0f / CDIM) - mu * mu;
        float rstd = rsqrtf(var + 1e-5f);
        float4 wv4 = ((const float4*)norm_w)[t];
        float4 bv4 = ((const float4*)norm_b)[t];
        float4 o;
        o.x = (v.x - mu) * rstd * wv4.x + bv4.x;
        o.y = (v.y - mu) * rstd * wv4.y + bv4.y;
        o.z = (v.z - mu) * rstd * wv4.z + bv4.z;
        o.w = (v.w - mu) * rstd * wv4.w + bv4.w;
        __half2* hp = (__half2*)(outh + (size_t)row * CDIM + t * 4);
        hp[0] = __floats2half2_rn(o.x, o.y);
        hp[1] = __floats2half2_rn(o.z, o.w);
    } else if (bid < 300) {
        const float* in = (bid < 150) ? wq : wk;
        __half* out = wqkh + (bid < 150 ? 0 : (size_t)150 * CDIM);
        int i = (bid % 150) * 1024 + t * 4;
        float4 v = *(const float4*)(in + i);
        *(__half2*)(out + i)     = __floats2half2_rn(v.x, v.y);
        *(__half2*)(out + i + 2) = __floats2half2_rn(v.z, v.w);
    } else if (bid < 1324) {
        int i = (bid - 300) * 1024 + t * 4;
        float4 v = *(const float4*)(wr + i);
        *(__half2*)(wrh + i)     = __floats2half2_rn(v.x, v.y);
        *(__half2*)(wrh + i + 2) = __floats2half2_rn(v.z, v.w);
    } else if (bid < 2348) {
        int idx = bid - 1324;
        int bx = idx & 31, by = idx >> 5;
        int tx = t & 31, ty = t >> 5;
        int xx = bx * 32 + tx;
        int y0 = by * 32 + ty;
        #pragma unroll
        for (int i = 0; i < 32; i += 8)
            tile[ty + i][tx] = wv[(size_t)(y0 + i) * CDIM + xx];
        __syncthreads();
        int x2 = by * 32 + tx;
        int y2 = bx * 32 + ty;
        #pragma unroll
        for (int i = 0; i < 32; i += 8)
            wvth[(size_t)(y2 + i) * CDIM + x2] = __float2half_rn(tile[tx][ty + i]);
    } else if (bid < 2352) {
        int i = (bid - 2348) * 256 + t;
        const float4* w4 = (const float4*)(wr + (size_t)i * CDIM);
        const float4* b4 = (const float4*)bv;
        float s = 0.f;
        #pragma unroll 8
        for (int k = 0; k < 256; k++) {
            float4 a = w4[k], b = b4[k];
            s += a.x * b.x + a.y * b.y + a.z * b.z + a.w * b.w;
        }
        bvr[i] = gammap[0] * (s + br[i]);
    } else {
        int r = (bid - 2352) * 256 + t;
        if (r < M_ROWS) {
            __half2 z = __floats2half2_rn(0.f, 0.f);
            __half2* pa = (__half2*)(semh + (size_t)r * 160 + 150);
            __half2* pb = (__half2*)(kfh  + (size_t)r * 160 + 150);
            #pragma unroll
            for (int i = 0; i < 5; i++) { pa[i] = z; pb[i] = z; }
        }
    }
}

// ============================================================
// fp16 mma.sync GEMM (unchanged)
// ============================================================
template<int MODE, int BN, int WN>
__global__ __launch_bounds__(256, 1)
void gemm_h(const __half* __restrict__ A, const __half* __restrict__ W,
            const float* __restrict__ bias0, const float* __restrict__ bias1,
            float* __restrict__ C0, __half* __restrict__ H0, __half* __restrict__ H1,
            int Nvalid, int ldc,
            const __half* __restrict__ residh, const float* __restrict__ gammap)
{
    constexpr int S = 3;
    constexpr int A_BYTES = 128 * 128;
    constexpr int B_BYTES = BN * 128;
    constexpr int STAGE = A_BYTES + B_BYTES;
    constexpr int NITER = CDIM / 64;
    constexpr int BLD = BN / 32;
    constexpr int WM  = 8 / WN;
    constexpr int MT  = 128 / (WM * 16);
    constexpr int NT  = BN / (WN * 8);
    constexpr int NB2 = (NT + 1) / 2;

    extern __shared__ char smem_raw[];
    char* tiles = (char*)(((uintptr_t)smem_raw + 1023) & ~(uintptr_t)1023);
    const uint32_t base = smem_to_u32(tiles);

    const int tid = threadIdx.x;
    const int m0  = blockIdx.y * 128;
    const int n0  = blockIdx.x * BN;
    const int vrows = (Nvalid - n0 < BN) ? (Nvalid - n0) : BN;

    if (vrows < BN) {
        #pragma unroll
        for (int s = 0; s < S; s++) {
            float4* z = (float4*)(tiles + s * STAGE + A_BYTES + vrows * 128);
            int cnt = (BN - vrows) * 8;
            for (int i = tid; i < cnt; i += 256) z[i] = make_float4(0.f, 0.f, 0.f, 0.f);
        }
        __syncthreads();
    }

    auto load_stage = [&](int c) {
        int st = c % S;
        uint32_t as = base + st * STAGE;
        uint32_t bs = as + A_BYTES;
        const char* Ag = (const char*)A + (size_t)m0 * (CDIM * 2) + c * 128;
        const char* Wg = (const char*)W + (size_t)n0 * (CDIM * 2) + c * 128;
        #pragma unroll
        for (int i = 0; i < 4; i++) {
            int idx = tid + i * 256;
            int r = idx >> 3, u = idx & 7;
            CP_ASYNC16(as + r * 128 + ((u ^ (r & 7)) << 4),
                       Ag + (size_t)r * (CDIM * 2) + u * 16);
        }
        #pragma unroll
        for (int i = 0; i < BLD; i++) {
            int idx = tid + i * 256;
            int r = idx >> 3, u = idx & 7;
            if (r < vrows)
                CP_ASYNC16(bs + r * 128 + ((u ^ (r & 7)) << 4),
                           Wg + (size_t)r * (CDIM * 2) + u * 16);
        }
        CP_COMMIT();
    };

    load_stage(0);
    load_stage(1);

    float acc[MT][NT][4];
    #pragma unroll
    for (int i = 0; i < MT; i++)
        #pragma unroll
        for (int j = 0; j < NT; j++)
            #pragma unroll
            for (int q = 0; q < 4; q++) acc[i][j][q] = 0.f;

    const int lane = tid & 31;
    const int wid  = tid >> 5;
    const int wm = (wid & (WM - 1)) * (128 / WM);
    const int wn = (wid / WM) * (NT * 8);

    const int arow_l = wm + (lane & 15);
    const int au_l   = lane >> 4;
    const int brow_l = wn + (lane & 7) + ((lane >> 4) << 3);
    const int bu_l   = (lane >> 3) & 1;

    for (int it = 0; it < NITER; it++) {
        asm volatile("cp.async.wait_group 1;" ::: "memory");
        __syncthreads();
        if (it + 2 < NITER) load_stage(it + 2);

        uint32_t as = base + (it % S) * STAGE;
        uint32_t bs = as + A_BYTES;
        #pragma unroll
        for (int kk = 0; kk < 4; kk++) {
            uint32_t a[MT][4], b[NB2][4];
            #pragma unroll
            for (int mt = 0; mt < MT; mt++) {
                int row = arow_l + mt * 16;
                int u = kk * 2 + au_l;
                LDMATRIX_X4(a[mt][0], a[mt][1], a[mt][2], a[mt][3],
                            as + row * 128 + ((u ^ (row & 7)) << 4));
            }
            #pragma unroll
            for (int np = 0; np < NB2; np++) {
                int row = brow_l + np * 16;
                int u = kk * 2 + bu_l;
                LDMATRIX_X4(b[np][0], b[np][1], b[np][2], b[np][3],
                            bs + row * 128 + ((u ^ (row & 7)) << 4));
            }
            #pragma unroll
            for (int mt = 0; mt < MT; mt++)
                #pragma unroll
                for (int nt = 0; nt < NT; nt++)
                    MMA16816(acc[mt][nt], a[mt],
                             b[nt >> 1][(nt & 1) * 2], b[nt >> 1][(nt & 1) * 2 + 1]);
        }
    }

    const int g = lane >> 2, tig = lane & 3;
    #pragma unroll
    for (int mt = 0; mt < MT; mt++) {
        #pragma unroll
        for (int nt = 0; nt < NT; nt++) {
            int m = m0 + wm + mt * 16 + g;
            int n = n0 + wn + nt * 8 + tig * 2;
            if (MODE == 2) {
                if (n >= Nvalid) continue;
                #pragma unroll
                for (int h = 0; h < 2; h++) {
                    int mr = m + h * 8;
                    float v0, v1;
                    if (n < 150) {
                        v0 = acc[mt][nt][h*2+0] + bias0[n];
                        v1 = acc[mt][nt][h*2+1] + bias0[n + 1];
                        C0[(size_t)mr * 150 + n]     = v0;
                        C0[(size_t)mr * 150 + n + 1] = v1;
                        *(__half2*)(H0 + (size_t)mr * 160 + n) = __floats2half2_rn(v0, v1);
                    } else {
                        int nn = n - 150;
                        v0 = acc[mt][nt][h*2+0] + bias1[nn];
                        v1 = acc[mt][nt][h*2+1] + bias1[nn + 1];
                        *(__half2*)(H1 + (size_t)mr * 160 + nn) = __floats2half2_rn(v0, v1);
                    }
                }
            } else if (MODE == 4) {
                float gm = gammap[0];
                #pragma unroll
                for (int h = 0; h < 2; h++) {
                    int mr = m + h * 8;
                    *(__half2*)(H0 + (size_t)mr * ldc + n) =
                        __floats2half2_rn(gm * acc[mt][nt][h*2+0], gm * acc[mt][nt][h*2+1]);
                }
            } else { // MODE 1
                float b0 = bias0[n], b1 = bias0[n + 1];
                #pragma unroll
                for (int h = 0; h < 2; h++) {
                    int mr = m + h * 8;
                    __half2 rv = *(const __half2*)(residh + (size_t)mr * CDIM + n);
                    float v0 = acc[mt][nt][h*2+0] + b0 + __low2float(rv);
                    float v1 = acc[mt][nt][h*2+1] + b1 + __high2float(rv);
                    *(float2*)(C0 + (size_t)mr * ldc + n) = make_float2(v0, v1);
                }
            }
        }
    }
}

// ============================================================
// HMMA attention: 2 windows per block, register softmax,
// cross-window QK prefetch, double-buffered V,
// S fragments hoisted to registers across all 8 V chunks.
// ============================================================
#define QK_STRB 336
#define SH_STRB 144
#define VC_STRB 272
#define SH_OFF  43008
#define V_OFF   52224
#define V_BUFB  17408
#define ATTN_SMEM (52224 + 2 * 17408)  // 87040

__global__ __launch_bounds__(128)
void attn_mma(const __half* __restrict__ semh, const __half* __restrict__ kfh,
              const __half* __restrict__ vh, __half* __restrict__ ao)
{
    extern __shared__ char sm[];
    char* Qc  = sm;
    char* Kc  = sm + 21504;
    char* Shc = sm + SH_OFF;
    char* Vb0 = sm + V_OFF;

    const uint32_t qb  = smem_to_u32(Qc);
    const uint32_t kb  = smem_to_u32(Kc);
    const uint32_t shb = smem_to_u32(Shc);
    const uint32_t vbb = smem_to_u32(Vb0);

    int t = threadIdx.x;
    const int lane = t & 31, w = t >> 5;
    const int g = lane >> 2, tig = lane & 3;

    auto win_base = [](int wi) {
        int b  = wi >> 6;
        int wh = (wi >> 3) & 7;
        int ww = wi & 7;
        return b * BATCH_STRIDE + wh * 7 * 56 + ww * 7;
    };
    auto issue_qk = [&](int base) {
        for (int idx = t; idx < 1960; idx += 128) {
            int which = idx >= 980;
            int i2 = idx - which * 980;
            int n = i2 / 20, u = i2 % 20;
            int r = base + (n / 7) * 56 + (n % 7);
            uint32_t dst = (which ? kb : qb) + n * QK_STRB + u * 16;
            const char* src = (const char*)(which ? kfh : semh) + (size_t)r * 320 + u * 16;
            CP_ASYNC16(dst, src);
        }
        CP_COMMIT();
    };
    auto issue_v = [&](int base, int cc) {
        uint32_t nb = vbb + (cc & 1) * V_BUFB;
        for (int idx = t; idx < 49 * 16; idx += 128) {
            int m = idx >> 4, u = idx & 15;
            int r = base + (m / 7) * 56 + (m % 7);
            CP_ASYNC16(nb + m * VC_STRB + u * 16,
                       (const char*)vh + (size_t)r * 2048 + cc * 256 + u * 16);
        }
        CP_COMMIT();
    };

    // ---- one-time pad zeroing (rows 49..63 of Qc/Kc and both V buffers)
    for (int i = t; i < 630; i += 128) {
        char* buf = (i < 315) ? Qc : Kc;
        int idx = (i < 315) ? i : i - 315;
        int row = 49 + idx / 21, u = idx % 21;
        ((float4*)(buf + row * QK_STRB))[u] = make_float4(0.f, 0.f, 0.f, 0.f);
    }
    for (int i = t; i < 510; i += 128) {
        int bsel = i >= 255;
        int idx = i - bsel * 255;
        int row = 49 + idx / 17, u = idx % 17;
        ((float4*)(Vb0 + bsel * V_BUFB + row * VC_STRB))[u] = make_float4(0.f, 0.f, 0.f, 0.f);
    }

    const int wi0 = blockIdx.x * 2;
    issue_qk(win_base(wi0));

    for (int wl = 0; wl < 2; wl++) {
        const int base = win_base(wi0 + wl);
        issue_v(base, 0);
        if (wl == 0) {
            asm volatile("cp.async.wait_group 0;" ::: "memory");
        }
        __syncthreads();

        // ---- Phase A: S = Q K^T
        float accS[8][4];
        #pragma unroll
        for (int j = 0; j < 8; j++)
            #pragma unroll
            for (int q = 0; q < 4; q++) accS[j][q] = 0.f;
        {
            const int arow = 16 * w + (lane & 15);
            const int ak   = (lane >> 4) * 8;
            const int brow = (lane & 7) + ((lane >> 4) << 3);
            const int bk   = ((lane >> 3) & 1) * 8;
            #pragma unroll
            for (int ks = 0; ks < 10; ks++) {
                uint32_t a[4], bfr[4][4];
                LDMATRIX_X4(a[0], a[1], a[2], a[3],
                            qb + arow * QK_STRB + (ks * 16 + ak) * 2);
                #pragma unroll
                for (int np = 0; np < 4; np++)
                    LDMATRIX_X4(bfr[np][0], bfr[np][1], bfr[np][2], bfr[np][3],
                                kb + (brow + np * 16) * QK_STRB + (ks * 16 + bk) * 2);
                #pragma unroll
                for (int nt = 0; nt < 8; nt++)
                    MMA16816(accS[nt], a, bfr[nt >> 1][(nt & 1) * 2], bfr[nt >> 1][(nt & 1) * 2 + 1]);
            }
        }

        // ---- register softmax (quad shfl) + write half S to Shc
        {
            int r0 = 16 * w + g;
            float m0 = -1e30f, m1 = -1e30f;
            #pragma unroll
            for (int nt = 0; nt < 8; nt++)
                #pragma unroll
                for (int e = 0; e < 2; e++) {
                    int c = nt * 8 + tig * 2 + e;
                    if (c < 49) {
                        m0 = fmaxf(m0, accS[nt][e]);
                        m1 = fmaxf(m1, accS[nt][2 + e]);
                    }
                }
            m0 = fmaxf(m0, __shfl_xor_sync(0xFFFFFFFFu, m0, 1));
            m0 = fmaxf(m0, __shfl_xor_sync(0xFFFFFFFFu, m0, 2));
            m1 = fmaxf(m1, __shfl_xor_sync(0xFFFFFFFFu, m1, 1));
            m1 = fmaxf(m1, __shfl_xor_sync(0xFFFFFFFFu, m1, 2));
            float s0 = 0.f, s1 = 0.f;
            #pragma unroll
            for (int nt = 0; nt < 8; nt++)
                #pragma unroll
                for (int e = 0; e < 2; e++) {
                    int c = nt * 8 + tig * 2 + e;
                    float e0 = 0.f, e1 = 0.f;
                    if (c < 49) {
                        e0 = __expf(accS[nt][e]     - m0);
                        e1 = __expf(accS[nt][2 + e] - m1);
                    }
                    accS[nt][e] = e0;     s0 += e0;
                    accS[nt][2 + e] = e1; s1 += e1;
                }
            s0 += __shfl_xor_sync(0xFFFFFFFFu, s0, 1);
            s0 += __shfl_xor_sync(0xFFFFFFFFu, s0, 2);
            s1 += __shfl_xor_sync(0xFFFFFFFFu, s1, 1);
            s1 += __shfl_xor_sync(0xFFFFFFFFu, s1, 2);
            float inv0 = 1.f / s0, inv1 = 1.f / s1;
            __half2* d0 = (__half2*)(Shc + r0 * SH_STRB + tig * 4);
            __half2* d1 = (__half2*)(Shc + (r0 + 8) * SH_STRB + tig * 4);
            #pragma unroll
            for (int nt = 0; nt < 8; nt++) {
                __half2 h0 = (r0 < 49)
                    ? __floats2half2_rn(accS[nt][0] * inv0, accS[nt][1] * inv0)
                    : __floats2half2_rn(0.f, 0.f);
                __half2 h1 = (r0 + 8 < 49)
                    ? __floats2half2_rn(accS[nt][2] * inv1, accS[nt][3] * inv1)
                    : __floats2half2_rn(0.f, 0.f);
                d0[nt * 4] = h0;
                d1[nt * 4] = h1;
            }
        }
        __syncthreads();  // Shc visible; Qc/Kc free for prefetch

        // ---- hoist S fragments into registers (reused by all 8 chunks)
        const int arow = lane & 15;
        const int ak   = (lane >> 4) * 8;
        uint32_t sA[4][4][4];
        #pragma unroll
        for (int ks = 0; ks < 4; ks++)
            #pragma unroll
            for (int mt = 0; mt < 4; mt++)
                LDMATRIX_X4(sA[ks][mt][0], sA[ks][mt][1], sA[ks][mt][2], sA[ks][mt][3],
                            shb + (16 * mt + arow) * SH_STRB + (ks * 16 + ak) * 2);

        // ---- Phase B: O = S V, double-buffered; prefetch next QK at cc==0
        const int kk_l = (lane & 7) + ((lane >> 3) & 1) * 8;
        const int nc_l = 32 * w + ((lane >> 4) << 3);

        for (int cc = 0; cc < 8; cc++) {
            if (cc + 1 < 8) {
                issue_v(base, cc + 1);
                if (cc == 0 && wl == 0) issue_qk(win_base(wi0 + 1));
                asm volatile("cp.async.wait_group 1;" ::: "memory");
            } else {
                asm volatile("cp.async.wait_group 0;" ::: "memory");
            }
            __syncthreads();

            const uint32_t vb = vbb + (cc & 1) * V_BUFB;
            float acc[4][4][4];
            #pragma unroll
            for (int i = 0; i < 4; i++)
                #pragma unroll
                for (int j = 0; j < 4; j++)
                    #pragma unroll
                    for (int q = 0; q < 4; q++) acc[i][j][q] = 0.f;

            #pragma unroll
            for (int ks = 0; ks < 4; ks++) {
                uint32_t bq[2][4];
                #pragma unroll
                for (int nb2 = 0; nb2 < 2; nb2++)
                    LDMATRIX_X4_T(bq[nb2][0], bq[nb2][1], bq[nb2][2], bq[nb2][3],
                                  vb + (ks * 16 + kk_l) * VC_STRB + (nc_l + nb2 * 16) * 2);
                #pragma unroll
                for (int mt = 0; mt < 4; mt++)
                    #pragma unroll
                    for (int nt = 0; nt < 4; nt++)
                        MMA16816(acc[mt][nt], sA[ks][mt],
                                 bq[nt >> 1][(nt & 1) * 2], bq[nt >> 1][(nt & 1) * 2 + 1]);
            }

            #pragma unroll
            for (int mt = 0; mt < 4; mt++) {
                #pragma unroll
                for (int h = 0; h < 2; h++) {
                    int m = 16 * mt + g + h * 8;
                    if (m < 49) {
                        int r = base + (m / 7) * 56 + (m % 7);
                        __half* dst = ao + (size_t)r * CDIM + cc * 128;
                        #pragma unroll
                        for (int nt = 0; nt < 4; nt++) {
                            int n = 32 * w + nt * 8 + tig * 2;
                            *(__half2*)(dst + n) =
                                __floats2half2_rn(acc[mt][nt][h*2+0], acc[mt][nt][h*2+1]);
                        }
                    }
                }
            }
            __syncthreads();
        }
    }
}

// ============================================================
// Host launcher
// ============================================================
extern "C" void kernel_launch(void* const* d_in, const int* in_sizes, int n_in,
                              void* d_out, int out_size)
{
    const float* x      = (const float*)d_in[0];
    const float* norm_w = (const float*)d_in[1];
    const float* norm_b = (const float*)d_in[2];
    const float* wq     = (const float*)d_in[3];
    const float* bq     = (const float*)d_in[4];
    const float* wk     = (const float*)d_in[5];
    const float* bk     = (const float*)d_in[6];
    const float* wv     = (const float*)d_in[7];
    const float* bv     = (const float*)d_in[8];
    const float* wr     = (const float*)d_in[9];
    const float* br     = (const float*)d_in[10];
    const float* gamma  = (const float*)d_in[11];
    (void)in_sizes; (void)n_in; (void)out_size;

    float* out  = (float*)d_out;
    float* sem  = out;
    float* xout = out + (size_t)M_ROWS * KSEM;

    __half *xnh, *semh, *kfh, *aoh, *wqkh, *wrh, *wvth, *wch;
    float* bvr;
    cudaGetSymbolAddress((void**)&xnh,  g_xnh);
    cudaGetSymbolAddress((void**)&semh, g_semh);
    cudaGetSymbolAddress((void**)&kfh,  g_kfh);
    cudaGetSymbolAddress((void**)&aoh,  g_aoh);
    cudaGetSymbolAddress((void**)&wqkh, g_wqkh);
    cudaGetSymbolAddress((void**)&wrh,  g_wrh);
    cudaGetSymbolAddress((void**)&wvth, g_wvth);
    cudaGetSymbolAddress((void**)&wch,  g_wch);
    cudaGetSymbolAddress((void**)&bvr,  g_bvr);

    const int SMEM256 = 3 * 49152 + 1024;
    const int SMEM160 = 3 * 36864 + 1024;
    const int SMEM128 = 3 * 32768 + 1024;
    cudaFuncSetAttribute(gemm_h<1, 256, 4>, cudaFuncAttributeMaxDynamicSharedMemorySize, SMEM256);
    cudaFuncSetAttribute(gemm_h<2, 160, 2>, cudaFuncAttributeMaxDynamicSharedMemorySize, SMEM160);
    cudaFuncSetAttribute(gemm_h<4, 128, 2>, cudaFuncAttributeMaxDynamicSharedMemorySize, SMEM128);
    cudaFuncSetAttribute(attn_mma, cudaFuncAttributeMaxDynamicSharedMemorySize, ATTN_SMEM);

    // 0+1) merged prep + LayerNorm
    ln_prep_kernel<<<PREP_BLOCKS + M_ROWS, 256>>>(x, norm_w, norm_b, xnh,
                                                  wq, wk, wr, wv, bv, br, gamma,
                                                  wqkh, wrh, wvth, bvr, semh, kfh);

    // Wc = gamma * Wr @ Wv (half)
    gemm_h<4, 128, 2><<<dim3(8, 8), 256, SMEM128>>>(wrh, wvth, nullptr, nullptr,
                                                    nullptr, wch, nullptr, CDIM, CDIM, nullptr, gamma);

    // 2) merged Q/K projection
    gemm_h<2, 160, 2><<<dim3(2, M_ROWS / 128), 256, SMEM160>>>(xnh, wqkh, bq, bk, sem, semh, kfh,
                                                               300, KSEM, nullptr, nullptr);

    // 3) attention: 2 windows per block
    attn_mma<<<NWIN / 2, 128, ATTN_SMEM>>>(semh, kfh, xnh, aoh);

    // 4) xout = aoh @ Wc^T + bvr + xnh
    gemm_h<1, 256, 4><<<dim3(4, M_ROWS / 128), 256, SMEM256>>>(aoh, wch, bvr, nullptr, xout,
                                                               nullptr, nullptr, CDIM, CDIM, xnh, nullptr);
}